// round 1
// baseline (speedup 1.0000x reference)
#include <cuda_runtime.h>
#include <cuda_bf16.h>

// ---------------- problem constants ----------------
#define B_ 2
#define T_ 2048
#define DIM_ 1024
#define SEG_ 8
#define SD_ 128
#define NE_ 16
#define KTOP_ 2
#define HSH_ 4096
#define HR_ 512
#define TOK_ (B_ * T_)            // 4096 tokens
#define NS_ (TOK_ * SEG_)         // 32768 token-segments
#define NENT_ (NS_ * KTOP_)       // 65536 routed entries

// ---------------- device scratch (static: no allocations allowed) ----------------
__device__ float g_Hsh[TOK_ * HSH_];        // 64 MB shared-expert hidden
__device__ float g_Yent[NENT_ * SD_];       // 32 MB per-entry routed outputs
__device__ int   g_top_idx[NENT_];
__device__ float g_top_w[NENT_];
__device__ int   g_cnt[NE_];
__device__ float g_wsum[NE_];
__device__ int   g_off[NE_ + 1];
__device__ int   g_cursor[NE_];
__device__ int   g_perm[NENT_];
__device__ float g_aux;

__device__ __forceinline__ float gelu_t(float x) {
    float x3 = x * x * x;
    return 0.5f * x * (1.0f + tanhf(0.7978845608028654f * (x + 0.044715f * x3)));
}

// ---------------- init ----------------
__global__ void init_kernel() {
    int t = threadIdx.x;
    if (t < NE_) { g_cnt[t] = 0; g_wsum[t] = 0.0f; }
}

// ---------------- router: one thread per slot ----------------
__global__ void router_kernel(const float* __restrict__ X, const float* __restrict__ Wr) {
    __shared__ float Wrs[SD_ * NE_];
    __shared__ int   scnt[NE_];
    __shared__ float sws[NE_];
    int tid = threadIdx.x;
    for (int i = tid; i < SD_ * NE_; i += 128) Wrs[i] = Wr[i];
    if (tid < NE_) { scnt[tid] = 0; sws[tid] = 0.0f; }
    __syncthreads();

    int slot = blockIdx.x * 128 + tid;
    const float* x = X + (slot >> 3) * DIM_ + (slot & 7) * SD_;
    float lg[NE_];
#pragma unroll
    for (int e = 0; e < NE_; e++) lg[e] = 0.0f;
    for (int k = 0; k < SD_; k++) {
        float xv = x[k];
        const float* wr = &Wrs[k * NE_];
#pragma unroll
        for (int e = 0; e < NE_; e++) lg[e] += xv * wr[e];
    }
    float mx = lg[0];
#pragma unroll
    for (int e = 1; e < NE_; e++) mx = fmaxf(mx, lg[e]);
    float p[NE_]; float sum = 0.0f;
#pragma unroll
    for (int e = 0; e < NE_; e++) { p[e] = expf(lg[e] - mx); sum += p[e]; }
    float inv = 1.0f / sum;
    int i0 = 0; float m0 = -1.0f;
#pragma unroll
    for (int e = 0; e < NE_; e++) if (p[e] > m0) { m0 = p[e]; i0 = e; }
    int i1 = 0; float m1 = -1.0f;
#pragma unroll
    for (int e = 0; e < NE_; e++) if (e != i0 && p[e] > m1) { m1 = p[e]; i1 = e; }
    float w0 = m0 * inv, w1 = m1 * inv;

    g_top_idx[2 * slot]     = i0;
    g_top_idx[2 * slot + 1] = i1;
    g_top_w[2 * slot]       = w0;
    g_top_w[2 * slot + 1]   = w1;

    atomicAdd(&scnt[i0], 1); atomicAdd(&scnt[i1], 1);
    atomicAdd(&sws[i0], w0); atomicAdd(&sws[i1], w1);
    __syncthreads();
    if (tid < NE_) {
        atomicAdd(&g_cnt[tid], scnt[tid]);
        atomicAdd(&g_wsum[tid], sws[tid]);
    }
}

// ---------------- offsets + aux ----------------
__global__ void offsets_kernel() {
    if (threadIdx.x == 0) {
        int acc = 0; float aux = 0.0f;
        for (int e = 0; e < NE_; e++) {
            g_off[e] = acc; g_cursor[e] = acc;
            acc += g_cnt[e];
            float f = (float)g_cnt[e] / ((float)NS_ * (float)KTOP_);
            float P = g_wsum[e] / (float)NS_;
            aux += f * P;
        }
        g_off[NE_] = acc;
        g_aux = (float)NE_ * aux;
    }
}

// ---------------- scatter entries into expert buckets ----------------
__global__ void scatter_kernel() {
    int slot = blockIdx.x * blockDim.x + threadIdx.x;
    if (slot >= NS_) return;
#pragma unroll
    for (int k = 0; k < KTOP_; k++) {
        int en = 2 * slot + k;
        int e = g_top_idx[en];
        int p = atomicAdd(&g_cursor[e], 1);
        g_perm[p] = en;
    }
}

// ---------------- classic 128x128x8 SGEMM, 8x8 micro-tile, fused bias(+gelu) ----------------
template <bool GELU>
__global__ void __launch_bounds__(256, 2)
sgemm128(const float* __restrict__ A, const float* __restrict__ Bm,
         const float* __restrict__ bias, float* __restrict__ C,
         int M, int N, int K) {
    __shared__ float As[8][128];
    __shared__ float Bs[8][128];
    int tid = threadIdx.x;
    int tx = tid & 15, ty = tid >> 4;
    int bm = blockIdx.y * 128, bn = blockIdx.x * 128;

    float acc[8][8];
#pragma unroll
    for (int i = 0; i < 8; i++)
#pragma unroll
        for (int j = 0; j < 8; j++) acc[i][j] = 0.0f;

    int arow = tid >> 1, acol = (tid & 1) * 4;
    int brow = tid >> 5, bcol = (tid & 31) * 4;
    const float* Aptr = A + (bm + arow) * K + acol;
    const float* Bptr = Bm + brow * N + bn + bcol;

    for (int k0 = 0; k0 < K; k0 += 8) {
        float4 a4 = *(const float4*)Aptr; Aptr += 8;
        float4 b4 = *(const float4*)Bptr; Bptr += 8 * N;
        As[acol + 0][arow] = a4.x;
        As[acol + 1][arow] = a4.y;
        As[acol + 2][arow] = a4.z;
        As[acol + 3][arow] = a4.w;
        *(float4*)&Bs[brow][bcol] = b4;
        __syncthreads();
#pragma unroll
        for (int k = 0; k < 8; k++) {
            float4 ra0 = *(const float4*)&As[k][ty * 8];
            float4 ra1 = *(const float4*)&As[k][ty * 8 + 4];
            float4 rb0 = *(const float4*)&Bs[k][tx * 8];
            float4 rb1 = *(const float4*)&Bs[k][tx * 8 + 4];
            float ra[8] = {ra0.x, ra0.y, ra0.z, ra0.w, ra1.x, ra1.y, ra1.z, ra1.w};
            float rb[8] = {rb0.x, rb0.y, rb0.z, rb0.w, rb1.x, rb1.y, rb1.z, rb1.w};
#pragma unroll
            for (int i = 0; i < 8; i++)
#pragma unroll
                for (int j = 0; j < 8; j++) acc[i][j] += ra[i] * rb[j];
        }
        __syncthreads();
    }

    int cn = bn + tx * 8;
    float bb[8];
#pragma unroll
    for (int j = 0; j < 8; j++) bb[j] = bias[cn + j];
#pragma unroll
    for (int i = 0; i < 8; i++) {
        float* crow = C + (bm + ty * 8 + i) * N + cn;
        float v[8];
#pragma unroll
        for (int j = 0; j < 8; j++) {
            float t = acc[i][j] + bb[j];
            v[j] = GELU ? gelu_t(t) : t;
        }
        *(float4*)crow       = make_float4(v[0], v[1], v[2], v[3]);
        *(float4*)(crow + 4) = make_float4(v[4], v[5], v[6], v[7]);
    }
}

// ---------------- fused routed-expert FFN: 64 entries per block ----------------
// smem: Xs[64][132] + Hs[64][68] + Ws[max(128*68, 64*132)]
#define RT_SMEM ((64 * 132 + 64 * 68 + 128 * 68) * 4)

__global__ void __launch_bounds__(256, 2)
routed_ffn(const float* __restrict__ X,
           const float* __restrict__ We1, const float* __restrict__ be1,
           const float* __restrict__ We2, const float* __restrict__ be2) {
    extern __shared__ float sm[];
    float* Xs = sm;                   // 64 x 132
    float* Hs = Xs + 64 * 132;        // 64 x 68
    float* Ws = Hs + 64 * 68;         // W1 chunk [128][68] / W2 chunk [64][132]
    __shared__ int   s_entry[64];
    __shared__ float s_w[64];

    int tid = threadIdx.x;
    int e = blockIdx.y;
    int base = g_off[e] + blockIdx.x * 64;
    int end  = g_off[e + 1];
    if (base >= end) return;

    for (int i = tid; i < 64; i += 256) {
        int p = base + i;
        if (p < end) {
            int en = g_perm[p];
            s_entry[i] = en;
            s_w[i] = g_top_w[en];
        } else {
            s_entry[i] = -1;
            s_w[i] = 0.0f;
        }
    }
    __syncthreads();

    // gather x rows
    for (int i = tid; i < 64 * 32; i += 256) {
        int row = i >> 5, c4 = (i & 31) << 2;
        float4 v = make_float4(0.f, 0.f, 0.f, 0.f);
        int en = s_entry[row];
        if (en >= 0) {
            int slot = en >> 1;
            v = *(const float4*)(X + (slot >> 3) * DIM_ + (slot & 7) * SD_ + c4);
        }
        *(float4*)&Xs[row * 132 + c4] = v;
    }

    const float* W1 = We1 + e * (SD_ * HR_);
    const float* W2 = We2 + e * (HR_ * SD_);
    const float* b1 = be1 + e * HR_;
    const float* b2 = be2 + e * SD_;

    int rg = tid >> 4;       // 0..15 -> rows rg*4..+3
    int cgrp = tid & 15;
    int r0 = rg * 4;
    int hc0 = cgrp * 4;      // up-phase cols
    int c0 = cgrp * 8;       // down-phase cols

    float yacc[4][8];
#pragma unroll
    for (int i = 0; i < 4; i++)
#pragma unroll
        for (int j = 0; j < 8; j++) yacc[i][j] = 0.0f;

    __syncthreads();

    for (int ch = 0; ch < 8; ch++) {
        int h0 = ch * 64;
        // load W1 chunk [128][64] (stride 68)
        for (int i = tid; i < 128 * 16; i += 256) {
            int k = i >> 4, h4 = (i & 15) << 2;
            *(float4*)&Ws[k * 68 + h4] = *(const float4*)(W1 + k * HR_ + h0 + h4);
        }
        __syncthreads();

        // H chunk: [64 rows][64 hidden], each thread 4x4
        float hacc[4][4];
#pragma unroll
        for (int i = 0; i < 4; i++)
#pragma unroll
            for (int j = 0; j < 4; j++) hacc[i][j] = 0.0f;
        for (int k = 0; k < SD_; k++) {
            float a0 = Xs[(r0 + 0) * 132 + k];
            float a1 = Xs[(r0 + 1) * 132 + k];
            float a2 = Xs[(r0 + 2) * 132 + k];
            float a3 = Xs[(r0 + 3) * 132 + k];
            float4 b = *(const float4*)&Ws[k * 68 + hc0];
            hacc[0][0] += a0 * b.x; hacc[0][1] += a0 * b.y; hacc[0][2] += a0 * b.z; hacc[0][3] += a0 * b.w;
            hacc[1][0] += a1 * b.x; hacc[1][1] += a1 * b.y; hacc[1][2] += a1 * b.z; hacc[1][3] += a1 * b.w;
            hacc[2][0] += a2 * b.x; hacc[2][1] += a2 * b.y; hacc[2][2] += a2 * b.z; hacc[2][3] += a2 * b.w;
            hacc[3][0] += a3 * b.x; hacc[3][1] += a3 * b.y; hacc[3][2] += a3 * b.z; hacc[3][3] += a3 * b.w;
        }
#pragma unroll
        for (int i = 0; i < 4; i++)
#pragma unroll
            for (int j = 0; j < 4; j++) {
                float v = hacc[i][j] + b1[h0 + hc0 + j];
                Hs[(r0 + i) * 68 + hc0 + j] = gelu_t(v);
            }
        __syncthreads();

        // load W2 chunk [64][128] (stride 132)
        for (int i = tid; i < 64 * 32; i += 256) {
            int h = i >> 5, c4 = (i & 31) << 2;
            *(float4*)&Ws[h * 132 + c4] = *(const float4*)(W2 + (h0 + h) * SD_ + c4);
        }
        __syncthreads();

        // down-proj accumulate: each thread 4 rows x 8 cols
        for (int hc = 0; hc < 64; hc++) {
            float a0 = Hs[(r0 + 0) * 68 + hc];
            float a1 = Hs[(r0 + 1) * 68 + hc];
            float a2 = Hs[(r0 + 2) * 68 + hc];
            float a3 = Hs[(r0 + 3) * 68 + hc];
            float4 w0 = *(const float4*)&Ws[hc * 132 + c0];
            float4 w1 = *(const float4*)&Ws[hc * 132 + c0 + 4];
            float wv[8] = {w0.x, w0.y, w0.z, w0.w, w1.x, w1.y, w1.z, w1.w};
#pragma unroll
            for (int j = 0; j < 8; j++) {
                yacc[0][j] += a0 * wv[j];
                yacc[1][j] += a1 * wv[j];
                yacc[2][j] += a2 * wv[j];
                yacc[3][j] += a3 * wv[j];
            }
        }
        __syncthreads();
    }

    // epilogue: Yent[entry] = w * (y + be2)
    float bb[8];
#pragma unroll
    for (int j = 0; j < 8; j++) bb[j] = b2[c0 + j];
#pragma unroll
    for (int i = 0; i < 4; i++) {
        int row = r0 + i;
        int en = s_entry[row];
        if (en >= 0) {
            float w = s_w[row];
            float v[8];
#pragma unroll
            for (int j = 0; j < 8; j++) v[j] = w * (yacc[i][j] + bb[j]);
            float* dst = &g_Yent[en * SD_ + c0];
            *(float4*)dst       = make_float4(v[0], v[1], v[2], v[3]);
            *(float4*)(dst + 4) = make_float4(v[4], v[5], v[6], v[7]);
        }
    }
}

// ---------------- combine: out = shared + sum_k w_k*y_k ; write aux ----------------
__global__ void combine_kernel(float* __restrict__ out, int out_size) {
    int idx = blockIdx.x * 256 + threadIdx.x;  // over NS_*SD_ = 4194304
    int c = idx & (SD_ - 1);
    int slot = idx >> 7;
    int token = slot >> 3, s = slot & 7;
    float add = g_Yent[(2 * slot) * SD_ + c] + g_Yent[(2 * slot + 1) * SD_ + c];
    out[token * DIM_ + s * SD_ + c] += add;
    if (idx == 0 && out_size > TOK_ * DIM_) out[TOK_ * DIM_] = g_aux;
}

// ---------------- launch ----------------
extern "C" void kernel_launch(void* const* d_in, const int* in_sizes, int n_in,
                              void* d_out, int out_size) {
    const float* X   = (const float*)d_in[0];
    const float* Ws1 = (const float*)d_in[1];
    const float* bs1 = (const float*)d_in[2];
    const float* Ws2 = (const float*)d_in[3];
    const float* bs2 = (const float*)d_in[4];
    const float* Wr  = (const float*)d_in[5];
    const float* We1 = (const float*)d_in[6];
    const float* be1 = (const float*)d_in[7];
    const float* We2 = (const float*)d_in[8];
    const float* be2 = (const float*)d_in[9];
    float* out = (float*)d_out;

    cudaFuncSetAttribute(routed_ffn, cudaFuncAttributeMaxDynamicSharedMemorySize, RT_SMEM);

    init_kernel<<<1, 64>>>();
    router_kernel<<<NS_ / 128, 128>>>(X, Wr);
    offsets_kernel<<<1, 32>>>();
    scatter_kernel<<<NS_ / 128, 128>>>();

    // shared expert
    sgemm128<true><<<dim3(HSH_ / 128, TOK_ / 128), 256>>>(X, Ws1, bs1, g_Hsh, TOK_, HSH_, DIM_);
    sgemm128<false><<<dim3(DIM_ / 128, TOK_ / 128), 256>>>(g_Hsh, Ws2, bs2, out, TOK_, DIM_, HSH_);

    // routed experts (worst case one expert gets everything -> 1024 tiles)
    routed_ffn<<<dim3(NENT_ / 64, NE_), 256, RT_SMEM>>>(X, We1, be1, We2, be2);

    combine_kernel<<<(NS_ * SD_) / 256, 256>>>(out, out_size);
}

// round 3
// speedup vs baseline: 3.2121x; 3.2121x over previous
#include <cuda_runtime.h>
#include <cuda_bf16.h>
#include <cstdint>

// ---------------- problem constants ----------------
#define B_ 2
#define T_ 2048
#define DIM_ 1024
#define SEG_ 8
#define SD_ 128
#define NE_ 16
#define KTOP_ 2
#define HSH_ 4096
#define HR_ 512
#define TOK_ (B_ * T_)            // 4096 tokens
#define NS_ (TOK_ * SEG_)         // 32768 token-segments
#define NENT_ (NS_ * KTOP_)       // 65536 routed entries

// ---------------- device scratch (static; no allocations allowed) ----------------
__device__ __nv_bfloat16 g_Xh[TOK_ * DIM_];
__device__ __nv_bfloat16 g_Xl[TOK_ * DIM_];
__device__ __nv_bfloat16 g_W1h[DIM_ * HSH_];
__device__ __nv_bfloat16 g_W1l[DIM_ * HSH_];
__device__ __nv_bfloat16 g_W2h[HSH_ * DIM_];
__device__ __nv_bfloat16 g_W2l[HSH_ * DIM_];
__device__ __nv_bfloat16 g_H1h[TOK_ * HSH_];
__device__ __nv_bfloat16 g_H1l[TOK_ * HSH_];
__device__ float g_Yent[NENT_ * SD_];
__device__ int   g_top_idx[NENT_];
__device__ float g_top_w[NENT_];
__device__ int   g_cnt[NE_];
__device__ float g_wsum[NE_];
__device__ int   g_off[NE_ + 1];
__device__ int   g_cursor[NE_];
__device__ int   g_perm[NENT_];
__device__ float g_aux;

__device__ __forceinline__ float gelu_t(float x) {
    float x3 = x * x * x;
    return 0.5f * x * (1.0f + tanhf(0.7978845608028654f * (x + 0.044715f * x3)));
}

__device__ __forceinline__ uint32_t smem_u32(const void* p) {
    uint32_t a;
    asm("{ .reg .u64 t; cvta.to.shared.u64 t, %1; cvt.u32.u64 %0, t; }" : "=r"(a) : "l"(p));
    return a;
}

__device__ __forceinline__ void ldsm_x4(uint32_t r[4], uint32_t addr) {
    asm volatile("ldmatrix.sync.aligned.m8n8.x4.shared.b16 {%0,%1,%2,%3}, [%4];"
        : "=r"(r[0]), "=r"(r[1]), "=r"(r[2]), "=r"(r[3]) : "r"(addr));
}
__device__ __forceinline__ void ldsm_x4_t(uint32_t r[4], uint32_t addr) {
    asm volatile("ldmatrix.sync.aligned.m8n8.x4.trans.shared.b16 {%0,%1,%2,%3}, [%4];"
        : "=r"(r[0]), "=r"(r[1]), "=r"(r[2]), "=r"(r[3]) : "r"(addr));
}
__device__ __forceinline__ void mma_bf16(float d[4], const uint32_t a[4], const uint32_t b[2]) {
    asm volatile("mma.sync.aligned.m16n8k16.row.col.f32.bf16.bf16.f32 "
        "{%0,%1,%2,%3}, {%4,%5,%6,%7}, {%8,%9}, {%0,%1,%2,%3};"
        : "+f"(d[0]), "+f"(d[1]), "+f"(d[2]), "+f"(d[3])
        : "r"(a[0]), "r"(a[1]), "r"(a[2]), "r"(a[3]), "r"(b[0]), "r"(b[1]));
}

// ---------------- split-precision conversion ----------------
__global__ void split_kernel(const float* __restrict__ src,
                             __nv_bfloat16* __restrict__ h,
                             __nv_bfloat16* __restrict__ l, int n4) {
    int i = blockIdx.x * 256 + threadIdx.x;
    if (i >= n4) return;
    float4 v = ((const float4*)src)[i];
    float vs[4] = {v.x, v.y, v.z, v.w};
    __nv_bfloat16 hh[4], ll[4];
#pragma unroll
    for (int j = 0; j < 4; j++) {
        hh[j] = __float2bfloat16(vs[j]);
        ll[j] = __float2bfloat16(vs[j] - __bfloat162float(hh[j]));
    }
    ((__nv_bfloat162*)h)[2 * i]     = __nv_bfloat162(hh[0], hh[1]);
    ((__nv_bfloat162*)h)[2 * i + 1] = __nv_bfloat162(hh[2], hh[3]);
    ((__nv_bfloat162*)l)[2 * i]     = __nv_bfloat162(ll[0], ll[1]);
    ((__nv_bfloat162*)l)[2 * i + 1] = __nv_bfloat162(ll[2], ll[3]);
}

// ---------------- HMMA split-bf16 GEMM: C[M,N] = A[M,K] @ B[K,N] ----------------
// MODE 0: epilogue gelu(acc+bias) -> (Ch, Cl) bf16 split pair
// MODE 1: epilogue acc+bias -> Cf fp32
#define BM_ 128
#define BN_ 128
#define BK_ 64
#define ASTR_ 72     // bf16 elems per A smem row (pad 8)
#define BSTR_ 136    // bf16 elems per B smem row (pad 8)
#define GSM_BYTES ((BM_ * ASTR_ * 2 + BK_ * BSTR_ * 2) * 2)

template <int MODE>
__global__ void __launch_bounds__(256)
gemm_hmma(const __nv_bfloat16* __restrict__ Ah, const __nv_bfloat16* __restrict__ Al,
          const __nv_bfloat16* __restrict__ Bh, const __nv_bfloat16* __restrict__ Bl,
          const float* __restrict__ bias,
          float* __restrict__ Cf,
          __nv_bfloat16* __restrict__ Ch, __nv_bfloat16* __restrict__ Cl,
          int M, int N, int K) {
    extern __shared__ char smraw[];
    __nv_bfloat16* sAh = (__nv_bfloat16*)smraw;                 // [BM][ASTR]
    __nv_bfloat16* sAl = sAh + BM_ * ASTR_;
    __nv_bfloat16* sBh = sAl + BM_ * ASTR_;                     // [BK][BSTR]
    __nv_bfloat16* sBl = sBh + BK_ * BSTR_;

    int tid = threadIdx.x;
    int wid = tid >> 5, lane = tid & 31;
    int wm = wid & 1, wn = wid >> 1;          // 2 x 4 warp grid
    int bn = blockIdx.x * BN_, bm = blockIdx.y * BM_;

    uint32_t uAh = smem_u32(sAh), uAl = smem_u32(sAl);
    uint32_t uBh = smem_u32(sBh), uBl = smem_u32(sBl);

    float acc[4][4][4];
#pragma unroll
    for (int i = 0; i < 4; i++)
#pragma unroll
        for (int j = 0; j < 4; j++)
#pragma unroll
            for (int q = 0; q < 4; q++) acc[i][j][q] = 0.0f;

    int lo16 = lane & 15, hi16 = lane >> 4;

    for (int kc = 0; kc < K; kc += BK_) {
        // load A tiles: BM x BK (uint4 = 8 bf16)
#pragma unroll 2
        for (int i = tid; i < BM_ * BK_ / 8; i += 256) {
            int r = i >> 3, u = i & 7;
            int g = (bm + r) * K + kc + u * 8;
            int s = r * ASTR_ + u * 8;
            *(uint4*)(sAh + s) = *(const uint4*)(Ah + g);
            *(uint4*)(sAl + s) = *(const uint4*)(Al + g);
        }
        // load B tiles: BK x BN
#pragma unroll 2
        for (int i = tid; i < BK_ * BN_ / 8; i += 256) {
            int r = i >> 4, u = i & 15;
            int g = (kc + r) * N + bn + u * 8;
            int s = r * BSTR_ + u * 8;
            *(uint4*)(sBh + s) = *(const uint4*)(Bh + g);
            *(uint4*)(sBl + s) = *(const uint4*)(Bl + g);
        }
        __syncthreads();

#pragma unroll
        for (int ks = 0; ks < 4; ks++) {
            int k0 = ks * 16;
            // B fragments for this warp's 32-wide n range
            uint32_t Bfh[4][2], Bfl[4][2];
#pragma unroll
            for (int p = 0; p < 2; p++) {
                uint32_t boff = (uint32_t)(((k0 + lo16) * BSTR_ + wn * 32 + p * 16 + 8 * hi16) * 2);
                uint32_t r4[4];
                ldsm_x4_t(r4, uBh + boff);
                Bfh[p * 2][0] = r4[0]; Bfh[p * 2][1] = r4[1];
                Bfh[p * 2 + 1][0] = r4[2]; Bfh[p * 2 + 1][1] = r4[3];
                ldsm_x4_t(r4, uBl + boff);
                Bfl[p * 2][0] = r4[0]; Bfl[p * 2][1] = r4[1];
                Bfl[p * 2 + 1][0] = r4[2]; Bfl[p * 2 + 1][1] = r4[3];
            }
#pragma unroll
            for (int mt = 0; mt < 4; mt++) {
                uint32_t aoff = (uint32_t)(((wm * 64 + mt * 16 + lo16) * ASTR_ + k0 + 8 * hi16) * 2);
                uint32_t Afh[4], Afl[4];
                ldsm_x4(Afh, uAh + aoff);
                ldsm_x4(Afl, uAl + aoff);
#pragma unroll
                for (int nt = 0; nt < 4; nt++) {
                    mma_bf16(acc[mt][nt], Afh, Bfh[nt]);
                    mma_bf16(acc[mt][nt], Afh, Bfl[nt]);
                    mma_bf16(acc[mt][nt], Afl, Bfh[nt]);
                }
            }
        }
        __syncthreads();
    }

    // epilogue
    int row_in = lane >> 2, colq = (lane & 3) * 2;
#pragma unroll
    for (int mt = 0; mt < 4; mt++) {
#pragma unroll
        for (int nt = 0; nt < 4; nt++) {
            int m0 = bm + wm * 64 + mt * 16 + row_in;
            int n0 = bn + wn * 32 + nt * 8 + colq;
            float b0 = bias[n0], b1 = bias[n0 + 1];
            float v00 = acc[mt][nt][0] + b0, v01 = acc[mt][nt][1] + b1;
            float v10 = acc[mt][nt][2] + b0, v11 = acc[mt][nt][3] + b1;
            if (MODE == 0) {
                float g00 = gelu_t(v00), g01 = gelu_t(v01);
                float g10 = gelu_t(v10), g11 = gelu_t(v11);
                __nv_bfloat16 h00 = __float2bfloat16(g00), h01 = __float2bfloat16(g01);
                __nv_bfloat16 h10 = __float2bfloat16(g10), h11 = __float2bfloat16(g11);
                __nv_bfloat16 l00 = __float2bfloat16(g00 - __bfloat162float(h00));
                __nv_bfloat16 l01 = __float2bfloat16(g01 - __bfloat162float(h01));
                __nv_bfloat16 l10 = __float2bfloat16(g10 - __bfloat162float(h10));
                __nv_bfloat16 l11 = __float2bfloat16(g11 - __bfloat162float(h11));
                *(__nv_bfloat162*)(Ch + m0 * N + n0)       = __nv_bfloat162(h00, h01);
                *(__nv_bfloat162*)(Ch + (m0 + 8) * N + n0) = __nv_bfloat162(h10, h11);
                *(__nv_bfloat162*)(Cl + m0 * N + n0)       = __nv_bfloat162(l00, l01);
                *(__nv_bfloat162*)(Cl + (m0 + 8) * N + n0) = __nv_bfloat162(l10, l11);
            } else {
                *(float2*)(Cf + m0 * N + n0)       = make_float2(v00, v01);
                *(float2*)(Cf + (m0 + 8) * N + n0) = make_float2(v10, v11);
            }
        }
    }
}

// ---------------- init ----------------
__global__ void init_kernel() {
    int t = threadIdx.x;
    if (t < NE_) { g_cnt[t] = 0; g_wsum[t] = 0.0f; }
}

// ---------------- router ----------------
__global__ void router_kernel(const float* __restrict__ X, const float* __restrict__ Wr) {
    __shared__ float Wrs[SD_ * NE_];
    __shared__ int   scnt[NE_];
    __shared__ float sws[NE_];
    int tid = threadIdx.x;
    for (int i = tid; i < SD_ * NE_; i += 128) Wrs[i] = Wr[i];
    if (tid < NE_) { scnt[tid] = 0; sws[tid] = 0.0f; }
    __syncthreads();

    int slot = blockIdx.x * 128 + tid;
    const float* x = X + (slot >> 3) * DIM_ + (slot & 7) * SD_;
    float lg[NE_];
#pragma unroll
    for (int e = 0; e < NE_; e++) lg[e] = 0.0f;
    for (int k = 0; k < SD_; k++) {
        float xv = x[k];
        const float* wr = &Wrs[k * NE_];
#pragma unroll
        for (int e = 0; e < NE_; e++) lg[e] += xv * wr[e];
    }
    float mx = lg[0];
#pragma unroll
    for (int e = 1; e < NE_; e++) mx = fmaxf(mx, lg[e]);
    float p[NE_]; float sum = 0.0f;
#pragma unroll
    for (int e = 0; e < NE_; e++) { p[e] = expf(lg[e] - mx); sum += p[e]; }
    float inv = 1.0f / sum;
    int i0 = 0; float m0 = -1.0f;
#pragma unroll
    for (int e = 0; e < NE_; e++) if (p[e] > m0) { m0 = p[e]; i0 = e; }
    int i1 = 0; float m1 = -1.0f;
#pragma unroll
    for (int e = 0; e < NE_; e++) if (e != i0 && p[e] > m1) { m1 = p[e]; i1 = e; }
    float w0 = m0 * inv, w1 = m1 * inv;

    g_top_idx[2 * slot]     = i0;
    g_top_idx[2 * slot + 1] = i1;
    g_top_w[2 * slot]       = w0;
    g_top_w[2 * slot + 1]   = w1;

    atomicAdd(&scnt[i0], 1); atomicAdd(&scnt[i1], 1);
    atomicAdd(&sws[i0], w0); atomicAdd(&sws[i1], w1);
    __syncthreads();
    if (tid < NE_) {
        atomicAdd(&g_cnt[tid], scnt[tid]);
        atomicAdd(&g_wsum[tid], sws[tid]);
    }
}

// ---------------- offsets + aux ----------------
__global__ void offsets_kernel() {
    if (threadIdx.x == 0) {
        int acc = 0; float aux = 0.0f;
        for (int e = 0; e < NE_; e++) {
            g_off[e] = acc; g_cursor[e] = acc;
            acc += g_cnt[e];
            float f = (float)g_cnt[e] / ((float)NS_ * (float)KTOP_);
            float P = g_wsum[e] / (float)NS_;
            aux += f * P;
        }
        g_off[NE_] = acc;
        g_aux = (float)NE_ * aux;
    }
}

// ---------------- scatter ----------------
__global__ void scatter_kernel() {
    int slot = blockIdx.x * blockDim.x + threadIdx.x;
    if (slot >= NS_) return;
#pragma unroll
    for (int k = 0; k < KTOP_; k++) {
        int en = 2 * slot + k;
        int e = g_top_idx[en];
        int p = atomicAdd(&g_cursor[e], 1);
        g_perm[p] = en;
    }
}

// ---------------- routed-expert fused FFN (fp32) ----------------
#define RT_SMEM ((64 * 132 + 64 * 68 + 128 * 68) * 4)

__global__ void __launch_bounds__(256, 2)
routed_ffn(const float* __restrict__ X,
           const float* __restrict__ We1, const float* __restrict__ be1,
           const float* __restrict__ We2, const float* __restrict__ be2) {
    extern __shared__ float sm[];
    float* Xs = sm;
    float* Hs = Xs + 64 * 132;
    float* Ws = Hs + 64 * 68;
    __shared__ int   s_entry[64];
    __shared__ float s_w[64];

    int tid = threadIdx.x;
    int e = blockIdx.y;
    int base = g_off[e] + blockIdx.x * 64;
    int end  = g_off[e + 1];
    if (base >= end) return;

    for (int i = tid; i < 64; i += 256) {
        int p = base + i;
        if (p < end) {
            int en = g_perm[p];
            s_entry[i] = en;
            s_w[i] = g_top_w[en];
        } else {
            s_entry[i] = -1;
            s_w[i] = 0.0f;
        }
    }
    __syncthreads();

    for (int i = tid; i < 64 * 32; i += 256) {
        int row = i >> 5, c4 = (i & 31) << 2;
        float4 v = make_float4(0.f, 0.f, 0.f, 0.f);
        int en = s_entry[row];
        if (en >= 0) {
            int slot = en >> 1;
            v = *(const float4*)(X + (slot >> 3) * DIM_ + (slot & 7) * SD_ + c4);
        }
        *(float4*)&Xs[row * 132 + c4] = v;
    }

    const float* W1 = We1 + e * (SD_ * HR_);
    const float* W2 = We2 + e * (HR_ * SD_);
    const float* b1 = be1 + e * HR_;
    const float* b2 = be2 + e * SD_;

    int rg = tid >> 4;
    int cgrp = tid & 15;
    int r0 = rg * 4;
    int hc0 = cgrp * 4;
    int c0 = cgrp * 8;

    float yacc[4][8];
#pragma unroll
    for (int i = 0; i < 4; i++)
#pragma unroll
        for (int j = 0; j < 8; j++) yacc[i][j] = 0.0f;

    __syncthreads();

    for (int ch = 0; ch < 8; ch++) {
        int h0 = ch * 64;
        for (int i = tid; i < 128 * 16; i += 256) {
            int k = i >> 4, h4 = (i & 15) << 2;
            *(float4*)&Ws[k * 68 + h4] = *(const float4*)(W1 + k * HR_ + h0 + h4);
        }
        __syncthreads();

        float hacc[4][4];
#pragma unroll
        for (int i = 0; i < 4; i++)
#pragma unroll
            for (int j = 0; j < 4; j++) hacc[i][j] = 0.0f;
        for (int k = 0; k < SD_; k++) {
            float a0 = Xs[(r0 + 0) * 132 + k];
            float a1 = Xs[(r0 + 1) * 132 + k];
            float a2 = Xs[(r0 + 2) * 132 + k];
            float a3 = Xs[(r0 + 3) * 132 + k];
            float4 b = *(const float4*)&Ws[k * 68 + hc0];
            hacc[0][0] += a0 * b.x; hacc[0][1] += a0 * b.y; hacc[0][2] += a0 * b.z; hacc[0][3] += a0 * b.w;
            hacc[1][0] += a1 * b.x; hacc[1][1] += a1 * b.y; hacc[1][2] += a1 * b.z; hacc[1][3] += a1 * b.w;
            hacc[2][0] += a2 * b.x; hacc[2][1] += a2 * b.y; hacc[2][2] += a2 * b.z; hacc[2][3] += a2 * b.w;
            hacc[3][0] += a3 * b.x; hacc[3][1] += a3 * b.y; hacc[3][2] += a3 * b.z; hacc[3][3] += a3 * b.w;
        }
#pragma unroll
        for (int i = 0; i < 4; i++)
#pragma unroll
            for (int j = 0; j < 4; j++) {
                float v = hacc[i][j] + b1[h0 + hc0 + j];
                Hs[(r0 + i) * 68 + hc0 + j] = gelu_t(v);
            }
        __syncthreads();

        for (int i = tid; i < 64 * 32; i += 256) {
            int h = i >> 5, c4 = (i & 31) << 2;
            *(float4*)&Ws[h * 132 + c4] = *(const float4*)(W2 + (h0 + h) * SD_ + c4);
        }
        __syncthreads();

        for (int hc = 0; hc < 64; hc++) {
            float a0 = Hs[(r0 + 0) * 68 + hc];
            float a1 = Hs[(r0 + 1) * 68 + hc];
            float a2 = Hs[(r0 + 2) * 68 + hc];
            float a3 = Hs[(r0 + 3) * 68 + hc];
            float4 w0 = *(const float4*)&Ws[hc * 132 + c0];
            float4 w1 = *(const float4*)&Ws[hc * 132 + c0 + 4];
            float wv[8] = {w0.x, w0.y, w0.z, w0.w, w1.x, w1.y, w1.z, w1.w};
#pragma unroll
            for (int j = 0; j < 8; j++) {
                yacc[0][j] += a0 * wv[j];
                yacc[1][j] += a1 * wv[j];
                yacc[2][j] += a2 * wv[j];
                yacc[3][j] += a3 * wv[j];
            }
        }
        __syncthreads();
    }

    float bb[8];
#pragma unroll
    for (int j = 0; j < 8; j++) bb[j] = b2[c0 + j];
#pragma unroll
    for (int i = 0; i < 4; i++) {
        int row = r0 + i;
        int en = s_entry[row];
        if (en >= 0) {
            float w = s_w[row];
            float v[8];
#pragma unroll
            for (int j = 0; j < 8; j++) v[j] = w * (yacc[i][j] + bb[j]);
            float* dst = &g_Yent[en * SD_ + c0];
            *(float4*)dst       = make_float4(v[0], v[1], v[2], v[3]);
            *(float4*)(dst + 4) = make_float4(v[4], v[5], v[6], v[7]);
        }
    }
}

// ---------------- combine ----------------
__global__ void combine_kernel(float* __restrict__ out, int out_size) {
    int idx = blockIdx.x * 256 + threadIdx.x;
    int c = idx & (SD_ - 1);
    int slot = idx >> 7;
    int token = slot >> 3, s = slot & 7;
    float add = g_Yent[(2 * slot) * SD_ + c] + g_Yent[(2 * slot + 1) * SD_ + c];
    out[token * DIM_ + s * SD_ + c] += add;
    if (idx == 0 && out_size > TOK_ * DIM_) out[TOK_ * DIM_] = g_aux;
}

// ---------------- launch ----------------
extern "C" void kernel_launch(void* const* d_in, const int* in_sizes, int n_in,
                              void* d_out, int out_size) {
    const float* X   = (const float*)d_in[0];
    const float* Ws1 = (const float*)d_in[1];
    const float* bs1 = (const float*)d_in[2];
    const float* Ws2 = (const float*)d_in[3];
    const float* bs2 = (const float*)d_in[4];
    const float* Wr  = (const float*)d_in[5];
    const float* We1 = (const float*)d_in[6];
    const float* be1 = (const float*)d_in[7];
    const float* We2 = (const float*)d_in[8];
    const float* be2 = (const float*)d_in[9];
    float* out = (float*)d_out;

    cudaFuncSetAttribute(routed_ffn, cudaFuncAttributeMaxDynamicSharedMemorySize, RT_SMEM);
    cudaFuncSetAttribute(gemm_hmma<0>, cudaFuncAttributeMaxDynamicSharedMemorySize, GSM_BYTES);
    cudaFuncSetAttribute(gemm_hmma<1>, cudaFuncAttributeMaxDynamicSharedMemorySize, GSM_BYTES);

    __nv_bfloat16 *Xh, *Xl, *W1h, *W1l, *W2h, *W2l, *H1h, *H1l;
    cudaGetSymbolAddress((void**)&Xh,  g_Xh);
    cudaGetSymbolAddress((void**)&Xl,  g_Xl);
    cudaGetSymbolAddress((void**)&W1h, g_W1h);
    cudaGetSymbolAddress((void**)&W1l, g_W1l);
    cudaGetSymbolAddress((void**)&W2h, g_W2h);
    cudaGetSymbolAddress((void**)&W2l, g_W2l);
    cudaGetSymbolAddress((void**)&H1h, g_H1h);
    cudaGetSymbolAddress((void**)&H1l, g_H1l);

    init_kernel<<<1, 64>>>();
    router_kernel<<<NS_ / 128, 128>>>(X, Wr);
    offsets_kernel<<<1, 32>>>();
    scatter_kernel<<<NS_ / 128, 128>>>();

    // split conversions
    split_kernel<<<(TOK_ * DIM_ / 4 + 255) / 256, 256>>>(X,   Xh,  Xl,  TOK_ * DIM_ / 4);
    split_kernel<<<(DIM_ * HSH_ / 4 + 255) / 256, 256>>>(Ws1, W1h, W1l, DIM_ * HSH_ / 4);
    split_kernel<<<(HSH_ * DIM_ / 4 + 255) / 256, 256>>>(Ws2, W2h, W2l, HSH_ * DIM_ / 4);

    // shared expert via HMMA split-bf16
    gemm_hmma<0><<<dim3(HSH_ / BN_, TOK_ / BM_), 256, GSM_BYTES>>>(
        Xh, Xl, W1h, W1l, bs1, nullptr, H1h, H1l, TOK_, HSH_, DIM_);
    gemm_hmma<1><<<dim3(DIM_ / BN_, TOK_ / BM_), 256, GSM_BYTES>>>(
        H1h, H1l, W2h, W2l, bs2, out, nullptr, nullptr, TOK_, DIM_, HSH_);

    // routed experts
    routed_ffn<<<dim3(NENT_ / 64, NE_), 256, RT_SMEM>>>(X, We1, be1, We2, be2);

    combine_kernel<<<(NS_ * SD_) / 256, 256>>>(out, out_size);
}

// round 4
// speedup vs baseline: 3.9035x; 1.2152x over previous
#include <cuda_runtime.h>
#include <cuda_bf16.h>
#include <cstdint>

// ---------------- problem constants ----------------
#define B_ 2
#define T_ 2048
#define DIM_ 1024
#define SEG_ 8
#define SD_ 128
#define NE_ 16
#define KTOP_ 2
#define HSH_ 4096
#define HR_ 512
#define TOK_ (B_ * T_)            // 4096 tokens
#define NS_ (TOK_ * SEG_)         // 32768 token-segments
#define NENT_ (NS_ * KTOP_)       // 65536 routed entries

// ---------------- device scratch ----------------
__device__ __nv_bfloat16 g_Xh[TOK_ * DIM_];
__device__ __nv_bfloat16 g_Xl[TOK_ * DIM_];
__device__ __nv_bfloat16 g_W1h[DIM_ * HSH_];
__device__ __nv_bfloat16 g_W1l[DIM_ * HSH_];
__device__ __nv_bfloat16 g_W2h[HSH_ * DIM_];
__device__ __nv_bfloat16 g_W2l[HSH_ * DIM_];
__device__ __nv_bfloat16 g_H1h[TOK_ * HSH_];
__device__ __nv_bfloat16 g_H1l[TOK_ * HSH_];
__device__ __nv_bfloat16 g_E1h[NE_ * SD_ * HR_];
__device__ __nv_bfloat16 g_E1l[NE_ * SD_ * HR_];
__device__ __nv_bfloat16 g_E2h[NE_ * HR_ * SD_];
__device__ __nv_bfloat16 g_E2l[NE_ * HR_ * SD_];
__device__ float g_Yent[NENT_ * SD_];
__device__ int   g_top_idx[NENT_];
__device__ float g_top_w[NENT_];
__device__ int   g_cnt[NE_];
__device__ float g_wsum[NE_];
__device__ int   g_off[NE_ + 1];
__device__ int   g_cursor[NE_];
__device__ int   g_perm[NENT_];
__device__ float g_aux;

__device__ __forceinline__ float gelu_t(float x) {
    float x3 = x * x * x;
    return 0.5f * x * (1.0f + tanhf(0.7978845608028654f * (x + 0.044715f * x3)));
}

__device__ __forceinline__ uint32_t smem_u32(const void* p) {
    uint32_t a;
    asm("{ .reg .u64 t; cvta.to.shared.u64 t, %1; cvt.u32.u64 %0, t; }" : "=r"(a) : "l"(p));
    return a;
}

__device__ __forceinline__ void ldsm_x4(uint32_t r[4], uint32_t addr) {
    asm volatile("ldmatrix.sync.aligned.m8n8.x4.shared.b16 {%0,%1,%2,%3}, [%4];"
        : "=r"(r[0]), "=r"(r[1]), "=r"(r[2]), "=r"(r[3]) : "r"(addr));
}
__device__ __forceinline__ void ldsm_x4_t(uint32_t r[4], uint32_t addr) {
    asm volatile("ldmatrix.sync.aligned.m8n8.x4.trans.shared.b16 {%0,%1,%2,%3}, [%4];"
        : "=r"(r[0]), "=r"(r[1]), "=r"(r[2]), "=r"(r[3]) : "r"(addr));
}
__device__ __forceinline__ void mma_bf16(float d[4], const uint32_t a[4], const uint32_t b[2]) {
    asm volatile("mma.sync.aligned.m16n8k16.row.col.f32.bf16.bf16.f32 "
        "{%0,%1,%2,%3}, {%4,%5,%6,%7}, {%8,%9}, {%0,%1,%2,%3};"
        : "+f"(d[0]), "+f"(d[1]), "+f"(d[2]), "+f"(d[3])
        : "r"(a[0]), "r"(a[1]), "r"(a[2]), "r"(a[3]), "r"(b[0]), "r"(b[1]));
}

// ---------------- split-precision conversion ----------------
__global__ void split_kernel(const float* __restrict__ src,
                             __nv_bfloat16* __restrict__ h,
                             __nv_bfloat16* __restrict__ l, int n4) {
    int i = blockIdx.x * 256 + threadIdx.x;
    if (i >= n4) return;
    float4 v = ((const float4*)src)[i];
    float vs[4] = {v.x, v.y, v.z, v.w};
    __nv_bfloat16 hh[4], ll[4];
#pragma unroll
    for (int j = 0; j < 4; j++) {
        hh[j] = __float2bfloat16(vs[j]);
        ll[j] = __float2bfloat16(vs[j] - __bfloat162float(hh[j]));
    }
    ((__nv_bfloat162*)h)[2 * i]     = __nv_bfloat162(hh[0], hh[1]);
    ((__nv_bfloat162*)h)[2 * i + 1] = __nv_bfloat162(hh[2], hh[3]);
    ((__nv_bfloat162*)l)[2 * i]     = __nv_bfloat162(ll[0], ll[1]);
    ((__nv_bfloat162*)l)[2 * i + 1] = __nv_bfloat162(ll[2], ll[3]);
}

// ---------------- HMMA split-bf16 GEMM: C[M,N] = A[M,K] @ B[K,N] ----------------
#define BM_ 128
#define BN_ 128
#define BK_ 64
#define ASTR_ 72
#define BSTR_ 136
#define GSM_BYTES ((BM_ * ASTR_ * 2 + BK_ * BSTR_ * 2) * 2)

template <int MODE>
__global__ void __launch_bounds__(256)
gemm_hmma(const __nv_bfloat16* __restrict__ Ah, const __nv_bfloat16* __restrict__ Al,
          const __nv_bfloat16* __restrict__ Bh, const __nv_bfloat16* __restrict__ Bl,
          const float* __restrict__ bias,
          float* __restrict__ Cf,
          __nv_bfloat16* __restrict__ Ch, __nv_bfloat16* __restrict__ Cl,
          int M, int N, int K) {
    extern __shared__ char smraw[];
    __nv_bfloat16* sAh = (__nv_bfloat16*)smraw;
    __nv_bfloat16* sAl = sAh + BM_ * ASTR_;
    __nv_bfloat16* sBh = sAl + BM_ * ASTR_;
    __nv_bfloat16* sBl = sBh + BK_ * BSTR_;

    int tid = threadIdx.x;
    int wid = tid >> 5, lane = tid & 31;
    int wm = wid & 1, wn = wid >> 1;
    int bn = blockIdx.x * BN_, bm = blockIdx.y * BM_;

    uint32_t uAh = smem_u32(sAh), uAl = smem_u32(sAl);
    uint32_t uBh = smem_u32(sBh), uBl = smem_u32(sBl);

    float acc[4][4][4];
#pragma unroll
    for (int i = 0; i < 4; i++)
#pragma unroll
        for (int j = 0; j < 4; j++)
#pragma unroll
            for (int q = 0; q < 4; q++) acc[i][j][q] = 0.0f;

    int lo16 = lane & 15, hi16 = lane >> 4;

    for (int kc = 0; kc < K; kc += BK_) {
#pragma unroll 2
        for (int i = tid; i < BM_ * BK_ / 8; i += 256) {
            int r = i >> 3, u = i & 7;
            int g = (bm + r) * K + kc + u * 8;
            int s = r * ASTR_ + u * 8;
            *(uint4*)(sAh + s) = *(const uint4*)(Ah + g);
            *(uint4*)(sAl + s) = *(const uint4*)(Al + g);
        }
#pragma unroll 2
        for (int i = tid; i < BK_ * BN_ / 8; i += 256) {
            int r = i >> 4, u = i & 15;
            int g = (kc + r) * N + bn + u * 8;
            int s = r * BSTR_ + u * 8;
            *(uint4*)(sBh + s) = *(const uint4*)(Bh + g);
            *(uint4*)(sBl + s) = *(const uint4*)(Bl + g);
        }
        __syncthreads();

#pragma unroll
        for (int ks = 0; ks < 4; ks++) {
            int k0 = ks * 16;
            uint32_t Bfh[4][2], Bfl[4][2];
#pragma unroll
            for (int p = 0; p < 2; p++) {
                uint32_t boff = (uint32_t)(((k0 + lo16) * BSTR_ + wn * 32 + p * 16 + 8 * hi16) * 2);
                uint32_t r4[4];
                ldsm_x4_t(r4, uBh + boff);
                Bfh[p * 2][0] = r4[0]; Bfh[p * 2][1] = r4[1];
                Bfh[p * 2 + 1][0] = r4[2]; Bfh[p * 2 + 1][1] = r4[3];
                ldsm_x4_t(r4, uBl + boff);
                Bfl[p * 2][0] = r4[0]; Bfl[p * 2][1] = r4[1];
                Bfl[p * 2 + 1][0] = r4[2]; Bfl[p * 2 + 1][1] = r4[3];
            }
#pragma unroll
            for (int mt = 0; mt < 4; mt++) {
                uint32_t aoff = (uint32_t)(((wm * 64 + mt * 16 + lo16) * ASTR_ + k0 + 8 * hi16) * 2);
                uint32_t Afh[4], Afl[4];
                ldsm_x4(Afh, uAh + aoff);
                ldsm_x4(Afl, uAl + aoff);
#pragma unroll
                for (int nt = 0; nt < 4; nt++) {
                    mma_bf16(acc[mt][nt], Afh, Bfh[nt]);
                    mma_bf16(acc[mt][nt], Afh, Bfl[nt]);
                    mma_bf16(acc[mt][nt], Afl, Bfh[nt]);
                }
            }
        }
        __syncthreads();
    }

    int row_in = lane >> 2, colq = (lane & 3) * 2;
#pragma unroll
    for (int mt = 0; mt < 4; mt++) {
#pragma unroll
        for (int nt = 0; nt < 4; nt++) {
            int m0 = bm + wm * 64 + mt * 16 + row_in;
            int n0 = bn + wn * 32 + nt * 8 + colq;
            float b0 = bias[n0], b1 = bias[n0 + 1];
            float v00 = acc[mt][nt][0] + b0, v01 = acc[mt][nt][1] + b1;
            float v10 = acc[mt][nt][2] + b0, v11 = acc[mt][nt][3] + b1;
            if (MODE == 0) {
                float g00 = gelu_t(v00), g01 = gelu_t(v01);
                float g10 = gelu_t(v10), g11 = gelu_t(v11);
                __nv_bfloat16 h00 = __float2bfloat16(g00), h01 = __float2bfloat16(g01);
                __nv_bfloat16 h10 = __float2bfloat16(g10), h11 = __float2bfloat16(g11);
                __nv_bfloat16 l00 = __float2bfloat16(g00 - __bfloat162float(h00));
                __nv_bfloat16 l01 = __float2bfloat16(g01 - __bfloat162float(h01));
                __nv_bfloat16 l10 = __float2bfloat16(g10 - __bfloat162float(h10));
                __nv_bfloat16 l11 = __float2bfloat16(g11 - __bfloat162float(h11));
                *(__nv_bfloat162*)(Ch + m0 * N + n0)       = __nv_bfloat162(h00, h01);
                *(__nv_bfloat162*)(Ch + (m0 + 8) * N + n0) = __nv_bfloat162(h10, h11);
                *(__nv_bfloat162*)(Cl + m0 * N + n0)       = __nv_bfloat162(l00, l01);
                *(__nv_bfloat162*)(Cl + (m0 + 8) * N + n0) = __nv_bfloat162(l10, l11);
            } else {
                *(float2*)(Cf + m0 * N + n0)       = make_float2(v00, v01);
                *(float2*)(Cf + (m0 + 8) * N + n0) = make_float2(v10, v11);
            }
        }
    }
}

// ---------------- routed experts via HMMA split-bf16 ----------------
// One CTA = 128 entries x 1 expert. 4 hidden chunks of 128.
#define RSTR_ 136
#define RXO_  0
#define RXLO_ (128 * RSTR_)
#define RHO_  (2 * 128 * RSTR_)
#define RHLO_ (3 * 128 * RSTR_)
#define RWO_  (4 * 128 * RSTR_)
#define RWLO_ (5 * 128 * RSTR_)
#define RT2_SMEM (6 * 128 * RSTR_ * 2)

__global__ void __launch_bounds__(256)
routed_hmma(const __nv_bfloat16* __restrict__ Xh, const __nv_bfloat16* __restrict__ Xl,
            const __nv_bfloat16* __restrict__ E1h, const __nv_bfloat16* __restrict__ E1l,
            const float* __restrict__ be1,
            const __nv_bfloat16* __restrict__ E2h, const __nv_bfloat16* __restrict__ E2l,
            const float* __restrict__ be2) {
    extern __shared__ __nv_bfloat16 sm2[];
    __nv_bfloat16* sXh = sm2 + RXO_;
    __nv_bfloat16* sXl = sm2 + RXLO_;
    __nv_bfloat16* sHh = sm2 + RHO_;
    __nv_bfloat16* sHl = sm2 + RHLO_;
    __nv_bfloat16* sWh = sm2 + RWO_;
    __nv_bfloat16* sWl = sm2 + RWLO_;
    __shared__ int   s_entry[128];
    __shared__ float s_w[128];

    int tid = threadIdx.x, wid = tid >> 5, lane = tid & 31;
    int e = blockIdx.y;
    int base = g_off[e] + blockIdx.x * 128;
    int end  = g_off[e + 1];
    if (base >= end) return;

    for (int i = tid; i < 128; i += 256) {
        int p = base + i;
        if (p < end) {
            int en = g_perm[p];
            s_entry[i] = en;
            s_w[i] = g_top_w[en];
        } else {
            s_entry[i] = -1;
            s_w[i] = 0.0f;
        }
    }
    __syncthreads();

    // gather X rows (hi/lo): 128 rows x 16 uint4
    for (int i = tid; i < 128 * 16; i += 256) {
        int row = i >> 4, u = i & 15;
        uint4 vh = make_uint4(0, 0, 0, 0), vl = vh;
        int en = s_entry[row];
        if (en >= 0) {
            int slot = en >> 1;
            int goff = (slot >> 3) * DIM_ + (slot & 7) * SD_ + u * 8;
            vh = *(const uint4*)(Xh + goff);
            vl = *(const uint4*)(Xl + goff);
        }
        int s = row * RSTR_ + u * 8;
        *(uint4*)(sXh + s) = vh;
        *(uint4*)(sXl + s) = vl;
    }

    const __nv_bfloat16* W1h = E1h + e * (SD_ * HR_);
    const __nv_bfloat16* W1l = E1l + e * (SD_ * HR_);
    const __nv_bfloat16* W2h = E2h + e * (HR_ * SD_);
    const __nv_bfloat16* W2l = E2l + e * (HR_ * SD_);
    const float* b1 = be1 + e * HR_;
    const float* b2 = be2 + e * SD_;

    int wm = wid & 1, wn = wid >> 1;
    int lo16 = lane & 15, hi16 = lane >> 4;
    int row_in = lane >> 2, colq = (lane & 3) * 2;

    uint32_t uXh = smem_u32(sXh), uXl = smem_u32(sXl);
    uint32_t uHh = smem_u32(sHh), uHl = smem_u32(sHl);
    uint32_t uWh = smem_u32(sWh), uWl = smem_u32(sWl);

    float yacc[4][4][4];
#pragma unroll
    for (int i = 0; i < 4; i++)
#pragma unroll
        for (int j = 0; j < 4; j++)
#pragma unroll
            for (int q = 0; q < 4; q++) yacc[i][j][q] = 0.0f;

    __syncthreads();

    for (int ch = 0; ch < 4; ch++) {
        int h0 = ch * 128;

        // load W1 chunk [k=128][h=128]
        for (int i = tid; i < 128 * 16; i += 256) {
            int k = i >> 4, u = i & 15;
            int g = k * HR_ + h0 + u * 8;
            int s = k * RSTR_ + u * 8;
            *(uint4*)(sWh + s) = *(const uint4*)(W1h + g);
            *(uint4*)(sWl + s) = *(const uint4*)(W1l + g);
        }
        __syncthreads();

        // GEMM1: H = X @ W1c (3-term split)
        float hacc[4][4][4];
#pragma unroll
        for (int i = 0; i < 4; i++)
#pragma unroll
            for (int j = 0; j < 4; j++)
#pragma unroll
                for (int q = 0; q < 4; q++) hacc[i][j][q] = 0.0f;

#pragma unroll
        for (int ks = 0; ks < 8; ks++) {
            int k0 = ks * 16;
            uint32_t Bfh[4][2], Bfl[4][2];
#pragma unroll
            for (int p = 0; p < 2; p++) {
                uint32_t boff = (uint32_t)(((k0 + lo16) * RSTR_ + wn * 32 + p * 16 + 8 * hi16) * 2);
                uint32_t r4[4];
                ldsm_x4_t(r4, uWh + boff);
                Bfh[p * 2][0] = r4[0]; Bfh[p * 2][1] = r4[1];
                Bfh[p * 2 + 1][0] = r4[2]; Bfh[p * 2 + 1][1] = r4[3];
                ldsm_x4_t(r4, uWl + boff);
                Bfl[p * 2][0] = r4[0]; Bfl[p * 2][1] = r4[1];
                Bfl[p * 2 + 1][0] = r4[2]; Bfl[p * 2 + 1][1] = r4[3];
            }
#pragma unroll
            for (int mt = 0; mt < 4; mt++) {
                uint32_t aoff = (uint32_t)(((wm * 64 + mt * 16 + lo16) * RSTR_ + k0 + 8 * hi16) * 2);
                uint32_t Afh[4], Afl[4];
                ldsm_x4(Afh, uXh + aoff);
                ldsm_x4(Afl, uXl + aoff);
#pragma unroll
                for (int nt = 0; nt < 4; nt++) {
                    mma_bf16(hacc[mt][nt], Afh, Bfh[nt]);
                    mma_bf16(hacc[mt][nt], Afh, Bfl[nt]);
                    mma_bf16(hacc[mt][nt], Afl, Bfh[nt]);
                }
            }
        }

        // H epilogue: gelu(bias+acc) -> split bf16 pair into sH
#pragma unroll
        for (int mt = 0; mt < 4; mt++) {
#pragma unroll
            for (int nt = 0; nt < 4; nt++) {
                int n0 = wn * 32 + nt * 8 + colq;
                float bb0 = b1[h0 + n0], bb1 = b1[h0 + n0 + 1];
                float g00 = gelu_t(hacc[mt][nt][0] + bb0);
                float g01 = gelu_t(hacc[mt][nt][1] + bb1);
                float g10 = gelu_t(hacc[mt][nt][2] + bb0);
                float g11 = gelu_t(hacc[mt][nt][3] + bb1);
                __nv_bfloat16 h00 = __float2bfloat16(g00), h01 = __float2bfloat16(g01);
                __nv_bfloat16 h10 = __float2bfloat16(g10), h11 = __float2bfloat16(g11);
                __nv_bfloat16 l00 = __float2bfloat16(g00 - __bfloat162float(h00));
                __nv_bfloat16 l01 = __float2bfloat16(g01 - __bfloat162float(h01));
                __nv_bfloat16 l10 = __float2bfloat16(g10 - __bfloat162float(h10));
                __nv_bfloat16 l11 = __float2bfloat16(g11 - __bfloat162float(h11));
                int r0 = wm * 64 + mt * 16 + row_in;
                *(__nv_bfloat162*)(sHh + r0 * RSTR_ + n0)       = __nv_bfloat162(h00, h01);
                *(__nv_bfloat162*)(sHh + (r0 + 8) * RSTR_ + n0) = __nv_bfloat162(h10, h11);
                *(__nv_bfloat162*)(sHl + r0 * RSTR_ + n0)       = __nv_bfloat162(l00, l01);
                *(__nv_bfloat162*)(sHl + (r0 + 8) * RSTR_ + n0) = __nv_bfloat162(l10, l11);
            }
        }
        __syncthreads();

        // load W2 chunk [k=128 hidden][d=128]
        for (int i = tid; i < 128 * 16; i += 256) {
            int k = i >> 4, u = i & 15;
            int g = (h0 + k) * SD_ + u * 8;
            int s = k * RSTR_ + u * 8;
            *(uint4*)(sWh + s) = *(const uint4*)(W2h + g);
            *(uint4*)(sWl + s) = *(const uint4*)(W2l + g);
        }
        __syncthreads();

        // GEMM2: Y += H @ W2c (3-term split)
#pragma unroll
        for (int ks = 0; ks < 8; ks++) {
            int k0 = ks * 16;
            uint32_t Bfh[4][2], Bfl[4][2];
#pragma unroll
            for (int p = 0; p < 2; p++) {
                uint32_t boff = (uint32_t)(((k0 + lo16) * RSTR_ + wn * 32 + p * 16 + 8 * hi16) * 2);
                uint32_t r4[4];
                ldsm_x4_t(r4, uWh + boff);
                Bfh[p * 2][0] = r4[0]; Bfh[p * 2][1] = r4[1];
                Bfh[p * 2 + 1][0] = r4[2]; Bfh[p * 2 + 1][1] = r4[3];
                ldsm_x4_t(r4, uWl + boff);
                Bfl[p * 2][0] = r4[0]; Bfl[p * 2][1] = r4[1];
                Bfl[p * 2 + 1][0] = r4[2]; Bfl[p * 2 + 1][1] = r4[3];
            }
#pragma unroll
            for (int mt = 0; mt < 4; mt++) {
                uint32_t aoff = (uint32_t)(((wm * 64 + mt * 16 + lo16) * RSTR_ + k0 + 8 * hi16) * 2);
                uint32_t Afh[4], Afl[4];
                ldsm_x4(Afh, uHh + aoff);
                ldsm_x4(Afl, uHl + aoff);
#pragma unroll
                for (int nt = 0; nt < 4; nt++) {
                    mma_bf16(yacc[mt][nt], Afh, Bfh[nt]);
                    mma_bf16(yacc[mt][nt], Afh, Bfl[nt]);
                    mma_bf16(yacc[mt][nt], Afl, Bfh[nt]);
                }
            }
        }
        __syncthreads();
    }

    // epilogue: g_Yent[entry] = w * (y + b2)
#pragma unroll
    for (int mt = 0; mt < 4; mt++) {
#pragma unroll
        for (int nt = 0; nt < 4; nt++) {
            int n0 = wn * 32 + nt * 8 + colq;
            float bb0 = b2[n0], bb1 = b2[n0 + 1];
            int r0 = wm * 64 + mt * 16 + row_in;
            int en0 = s_entry[r0];
            if (en0 >= 0) {
                float w = s_w[r0];
                *(float2*)(g_Yent + en0 * SD_ + n0) =
                    make_float2(w * (yacc[mt][nt][0] + bb0), w * (yacc[mt][nt][1] + bb1));
            }
            int en1 = s_entry[r0 + 8];
            if (en1 >= 0) {
                float w = s_w[r0 + 8];
                *(float2*)(g_Yent + en1 * SD_ + n0) =
                    make_float2(w * (yacc[mt][nt][2] + bb0), w * (yacc[mt][nt][3] + bb1));
            }
        }
    }
}

// ---------------- init ----------------
__global__ void init_kernel() {
    int t = threadIdx.x;
    if (t < NE_) { g_cnt[t] = 0; g_wsum[t] = 0.0f; }
}

// ---------------- router ----------------
__global__ void router_kernel(const float* __restrict__ X, const float* __restrict__ Wr) {
    __shared__ float Wrs[SD_ * NE_];
    __shared__ int   scnt[NE_];
    __shared__ float sws[NE_];
    int tid = threadIdx.x;
    for (int i = tid; i < SD_ * NE_; i += 128) Wrs[i] = Wr[i];
    if (tid < NE_) { scnt[tid] = 0; sws[tid] = 0.0f; }
    __syncthreads();

    int slot = blockIdx.x * 128 + tid;
    const float* x = X + (slot >> 3) * DIM_ + (slot & 7) * SD_;
    float lg[NE_];
#pragma unroll
    for (int e = 0; e < NE_; e++) lg[e] = 0.0f;
    for (int k = 0; k < SD_; k++) {
        float xv = x[k];
        const float* wr = &Wrs[k * NE_];
#pragma unroll
        for (int e = 0; e < NE_; e++) lg[e] += xv * wr[e];
    }
    float mx = lg[0];
#pragma unroll
    for (int e = 1; e < NE_; e++) mx = fmaxf(mx, lg[e]);
    float p[NE_]; float sum = 0.0f;
#pragma unroll
    for (int e = 0; e < NE_; e++) { p[e] = expf(lg[e] - mx); sum += p[e]; }
    float inv = 1.0f / sum;
    int i0 = 0; float m0 = -1.0f;
#pragma unroll
    for (int e = 0; e < NE_; e++) if (p[e] > m0) { m0 = p[e]; i0 = e; }
    int i1 = 0; float m1 = -1.0f;
#pragma unroll
    for (int e = 0; e < NE_; e++) if (e != i0 && p[e] > m1) { m1 = p[e]; i1 = e; }
    float w0 = m0 * inv, w1 = m1 * inv;

    g_top_idx[2 * slot]     = i0;
    g_top_idx[2 * slot + 1] = i1;
    g_top_w[2 * slot]       = w0;
    g_top_w[2 * slot + 1]   = w1;

    atomicAdd(&scnt[i0], 1); atomicAdd(&scnt[i1], 1);
    atomicAdd(&sws[i0], w0); atomicAdd(&sws[i1], w1);
    __syncthreads();
    if (tid < NE_) {
        atomicAdd(&g_cnt[tid], scnt[tid]);
        atomicAdd(&g_wsum[tid], sws[tid]);
    }
}

// ---------------- offsets + aux ----------------
__global__ void offsets_kernel() {
    if (threadIdx.x == 0) {
        int acc = 0; float aux = 0.0f;
        for (int e = 0; e < NE_; e++) {
            g_off[e] = acc; g_cursor[e] = acc;
            acc += g_cnt[e];
            float f = (float)g_cnt[e] / ((float)NS_ * (float)KTOP_);
            float P = g_wsum[e] / (float)NS_;
            aux += f * P;
        }
        g_off[NE_] = acc;
        g_aux = (float)NE_ * aux;
    }
}

// ---------------- scatter ----------------
__global__ void scatter_kernel() {
    int slot = blockIdx.x * blockDim.x + threadIdx.x;
    if (slot >= NS_) return;
#pragma unroll
    for (int k = 0; k < KTOP_; k++) {
        int en = 2 * slot + k;
        int e = g_top_idx[en];
        int p = atomicAdd(&g_cursor[e], 1);
        g_perm[p] = en;
    }
}

// ---------------- combine ----------------
__global__ void combine_kernel(float* __restrict__ out, int out_size) {
    int idx = blockIdx.x * 256 + threadIdx.x;
    int c = idx & (SD_ - 1);
    int slot = idx >> 7;
    int token = slot >> 3, s = slot & 7;
    float add = g_Yent[(2 * slot) * SD_ + c] + g_Yent[(2 * slot + 1) * SD_ + c];
    out[token * DIM_ + s * SD_ + c] += add;
    if (idx == 0 && out_size > TOK_ * DIM_) out[TOK_ * DIM_] = g_aux;
}

// ---------------- launch ----------------
extern "C" void kernel_launch(void* const* d_in, const int* in_sizes, int n_in,
                              void* d_out, int out_size) {
    const float* X   = (const float*)d_in[0];
    const float* Ws1 = (const float*)d_in[1];
    const float* bs1 = (const float*)d_in[2];
    const float* Ws2 = (const float*)d_in[3];
    const float* bs2 = (const float*)d_in[4];
    const float* Wr  = (const float*)d_in[5];
    const float* We1 = (const float*)d_in[6];
    const float* be1 = (const float*)d_in[7];
    const float* We2 = (const float*)d_in[8];
    const float* be2 = (const float*)d_in[9];
    float* out = (float*)d_out;

    cudaFuncSetAttribute(gemm_hmma<0>, cudaFuncAttributeMaxDynamicSharedMemorySize, GSM_BYTES);
    cudaFuncSetAttribute(gemm_hmma<1>, cudaFuncAttributeMaxDynamicSharedMemorySize, GSM_BYTES);
    cudaFuncSetAttribute(routed_hmma, cudaFuncAttributeMaxDynamicSharedMemorySize, RT2_SMEM);

    __nv_bfloat16 *Xh, *Xl, *W1h, *W1l, *W2h, *W2l, *H1h, *H1l;
    __nv_bfloat16 *E1h, *E1l, *E2h, *E2l;
    cudaGetSymbolAddress((void**)&Xh,  g_Xh);
    cudaGetSymbolAddress((void**)&Xl,  g_Xl);
    cudaGetSymbolAddress((void**)&W1h, g_W1h);
    cudaGetSymbolAddress((void**)&W1l, g_W1l);
    cudaGetSymbolAddress((void**)&W2h, g_W2h);
    cudaGetSymbolAddress((void**)&W2l, g_W2l);
    cudaGetSymbolAddress((void**)&H1h, g_H1h);
    cudaGetSymbolAddress((void**)&H1l, g_H1l);
    cudaGetSymbolAddress((void**)&E1h, g_E1h);
    cudaGetSymbolAddress((void**)&E1l, g_E1l);
    cudaGetSymbolAddress((void**)&E2h, g_E2h);
    cudaGetSymbolAddress((void**)&E2l, g_E2l);

    init_kernel<<<1, 64>>>();
    router_kernel<<<NS_ / 128, 128>>>(X, Wr);
    offsets_kernel<<<1, 32>>>();
    scatter_kernel<<<NS_ / 128, 128>>>();

    // split conversions
    split_kernel<<<(TOK_ * DIM_ / 4 + 255) / 256, 256>>>(X,   Xh,  Xl,  TOK_ * DIM_ / 4);
    split_kernel<<<(DIM_ * HSH_ / 4 + 255) / 256, 256>>>(Ws1, W1h, W1l, DIM_ * HSH_ / 4);
    split_kernel<<<(HSH_ * DIM_ / 4 + 255) / 256, 256>>>(Ws2, W2h, W2l, HSH_ * DIM_ / 4);
    split_kernel<<<(NE_ * SD_ * HR_ / 4 + 255) / 256, 256>>>(We1, E1h, E1l, NE_ * SD_ * HR_ / 4);
    split_kernel<<<(NE_ * HR_ * SD_ / 4 + 255) / 256, 256>>>(We2, E2h, E2l, NE_ * HR_ * SD_ / 4);

    // shared expert via HMMA split-bf16
    gemm_hmma<0><<<dim3(HSH_ / BN_, TOK_ / BM_), 256, GSM_BYTES>>>(
        Xh, Xl, W1h, W1l, bs1, nullptr, H1h, H1l, TOK_, HSH_, DIM_);
    gemm_hmma<1><<<dim3(DIM_ / BN_, TOK_ / BM_), 256, GSM_BYTES>>>(
        H1h, H1l, W2h, W2l, bs2, out, nullptr, nullptr, TOK_, DIM_, HSH_);

    // routed experts via HMMA split-bf16
    routed_hmma<<<dim3(NENT_ / 128, NE_), 256, RT2_SMEM>>>(
        Xh, Xl, E1h, E1l, be1, E2h, E2l, be2);

    combine_kernel<<<(NS_ * SD_) / 256, 256>>>(out, out_size);
}

// round 6
// speedup vs baseline: 4.2121x; 1.0790x over previous
#include <cuda_runtime.h>
#include <cuda_bf16.h>
#include <cstdint>

// ---------------- problem constants ----------------
#define B_ 2
#define T_ 2048
#define DIM_ 1024
#define SEG_ 8
#define SD_ 128
#define NE_ 16
#define KTOP_ 2
#define HSH_ 4096
#define HR_ 512
#define TOK_ (B_ * T_)            // 4096 tokens
#define NS_ (TOK_ * SEG_)         // 32768 token-segments
#define NENT_ (NS_ * KTOP_)       // 65536 routed entries

// ---------------- device scratch ----------------
__device__ __nv_bfloat16 g_Xh[TOK_ * DIM_];
__device__ __nv_bfloat16 g_Xl[TOK_ * DIM_];
__device__ __nv_bfloat16 g_W1h[DIM_ * HSH_];
__device__ __nv_bfloat16 g_W1l[DIM_ * HSH_];
__device__ __nv_bfloat16 g_W2h[HSH_ * DIM_];
__device__ __nv_bfloat16 g_W2l[HSH_ * DIM_];
__device__ __nv_bfloat16 g_H1h[TOK_ * HSH_];
__device__ __nv_bfloat16 g_H1l[TOK_ * HSH_];
__device__ __nv_bfloat16 g_E1h[NE_ * SD_ * HR_];
__device__ __nv_bfloat16 g_E1l[NE_ * SD_ * HR_];
__device__ __nv_bfloat16 g_E2h[NE_ * HR_ * SD_];
__device__ __nv_bfloat16 g_E2l[NE_ * HR_ * SD_];
__device__ float g_Yent[NENT_ * SD_];
__device__ int   g_top_idx[NENT_];
__device__ float g_top_w[NENT_];
__device__ int   g_cnt[NE_];
__device__ float g_wsum[NE_];
__device__ int   g_off[NE_ + 1];
__device__ int   g_cursor[NE_];
__device__ int   g_perm[NENT_];
__device__ float g_aux;

__device__ __forceinline__ float gelu_t(float x) {
    float x3 = x * x * x;
    return 0.5f * x * (1.0f + tanhf(0.7978845608028654f * (x + 0.044715f * x3)));
}

__device__ __forceinline__ uint32_t smem_u32(const void* p) {
    uint32_t a;
    asm("{ .reg .u64 t; cvta.to.shared.u64 t, %1; cvt.u32.u64 %0, t; }" : "=r"(a) : "l"(p));
    return a;
}

__device__ __forceinline__ void ldsm_x4(uint32_t r[4], uint32_t addr) {
    asm volatile("ldmatrix.sync.aligned.m8n8.x4.shared.b16 {%0,%1,%2,%3}, [%4];"
        : "=r"(r[0]), "=r"(r[1]), "=r"(r[2]), "=r"(r[3]) : "r"(addr));
}
__device__ __forceinline__ void ldsm_x4_t(uint32_t r[4], uint32_t addr) {
    asm volatile("ldmatrix.sync.aligned.m8n8.x4.trans.shared.b16 {%0,%1,%2,%3}, [%4];"
        : "=r"(r[0]), "=r"(r[1]), "=r"(r[2]), "=r"(r[3]) : "r"(addr));
}
__device__ __forceinline__ void mma_bf16(float d[4], const uint32_t a[4], const uint32_t b[2]) {
    asm volatile("mma.sync.aligned.m16n8k16.row.col.f32.bf16.bf16.f32 "
        "{%0,%1,%2,%3}, {%4,%5,%6,%7}, {%8,%9}, {%0,%1,%2,%3};"
        : "+f"(d[0]), "+f"(d[1]), "+f"(d[2]), "+f"(d[3])
        : "r"(a[0]), "r"(a[1]), "r"(a[2]), "r"(a[3]), "r"(b[0]), "r"(b[1]));
}
__device__ __forceinline__ void cp16(uint32_t s, const void* g, int szbytes) {
    asm volatile("cp.async.cg.shared.global [%0], [%1], 16, %2;"
        :: "r"(s), "l"(g), "r"(szbytes));
}
__device__ __forceinline__ void cp_commit() { asm volatile("cp.async.commit_group;" ::: "memory"); }
__device__ __forceinline__ void cp_wait0()  { asm volatile("cp.async.wait_group 0;" ::: "memory"); }

// ---------------- split-precision conversion ----------------
__global__ void split_kernel(const float* __restrict__ src,
                             __nv_bfloat16* __restrict__ h,
                             __nv_bfloat16* __restrict__ l, int n4) {
    int i = blockIdx.x * 256 + threadIdx.x;
    if (i >= n4) return;
    float4 v = ((const float4*)src)[i];
    float vs[4] = {v.x, v.y, v.z, v.w};
    __nv_bfloat16 hh[4], ll[4];
#pragma unroll
    for (int j = 0; j < 4; j++) {
        hh[j] = __float2bfloat16(vs[j]);
        ll[j] = __float2bfloat16(vs[j] - __bfloat162float(hh[j]));
    }
    ((__nv_bfloat162*)h)[2 * i]     = __nv_bfloat162(hh[0], hh[1]);
    ((__nv_bfloat162*)h)[2 * i + 1] = __nv_bfloat162(hh[2], hh[3]);
    ((__nv_bfloat162*)l)[2 * i]     = __nv_bfloat162(ll[0], ll[1]);
    ((__nv_bfloat162*)l)[2 * i + 1] = __nv_bfloat162(ll[2], ll[3]);
}

// ---------------- HMMA split-bf16 GEMM: C[M,N] = A[M,K] @ B[K,N] ----------------
#define BM_ 128
#define BN_ 128
#define BK_ 64
#define ASTR_ 72
#define BSTR_ 136
#define GSM_BYTES ((BM_ * ASTR_ * 2 + BK_ * BSTR_ * 2) * 2)

template <int MODE>
__global__ void __launch_bounds__(256)
gemm_hmma(const __nv_bfloat16* __restrict__ Ah, const __nv_bfloat16* __restrict__ Al,
          const __nv_bfloat16* __restrict__ Bh, const __nv_bfloat16* __restrict__ Bl,
          const float* __restrict__ bias,
          float* __restrict__ Cf,
          __nv_bfloat16* __restrict__ Ch, __nv_bfloat16* __restrict__ Cl,
          int M, int N, int K) {
    extern __shared__ char smraw[];
    __nv_bfloat16* sAh = (__nv_bfloat16*)smraw;
    __nv_bfloat16* sAl = sAh + BM_ * ASTR_;
    __nv_bfloat16* sBh = sAl + BM_ * ASTR_;
    __nv_bfloat16* sBl = sBh + BK_ * BSTR_;

    int tid = threadIdx.x;
    int wid = tid >> 5, lane = tid & 31;
    int wm = wid & 1, wn = wid >> 1;
    int bn = blockIdx.x * BN_, bm = blockIdx.y * BM_;

    uint32_t uAh = smem_u32(sAh), uAl = smem_u32(sAl);
    uint32_t uBh = smem_u32(sBh), uBl = smem_u32(sBl);

    float acc[4][4][4];
#pragma unroll
    for (int i = 0; i < 4; i++)
#pragma unroll
        for (int j = 0; j < 4; j++)
#pragma unroll
            for (int q = 0; q < 4; q++) acc[i][j][q] = 0.0f;

    int lo16 = lane & 15, hi16 = lane >> 4;

    for (int kc = 0; kc < K; kc += BK_) {
#pragma unroll 2
        for (int i = tid; i < BM_ * BK_ / 8; i += 256) {
            int r = i >> 3, u = i & 7;
            int g = (bm + r) * K + kc + u * 8;
            int s = r * ASTR_ + u * 8;
            *(uint4*)(sAh + s) = *(const uint4*)(Ah + g);
            *(uint4*)(sAl + s) = *(const uint4*)(Al + g);
        }
#pragma unroll 2
        for (int i = tid; i < BK_ * BN_ / 8; i += 256) {
            int r = i >> 4, u = i & 15;
            int g = (kc + r) * N + bn + u * 8;
            int s = r * BSTR_ + u * 8;
            *(uint4*)(sBh + s) = *(const uint4*)(Bh + g);
            *(uint4*)(sBl + s) = *(const uint4*)(Bl + g);
        }
        __syncthreads();

#pragma unroll
        for (int ks = 0; ks < 4; ks++) {
            int k0 = ks * 16;
            uint32_t Bfh[4][2], Bfl[4][2];
#pragma unroll
            for (int p = 0; p < 2; p++) {
                uint32_t boff = (uint32_t)(((k0 + lo16) * BSTR_ + wn * 32 + p * 16 + 8 * hi16) * 2);
                uint32_t r4[4];
                ldsm_x4_t(r4, uBh + boff);
                Bfh[p * 2][0] = r4[0]; Bfh[p * 2][1] = r4[1];
                Bfh[p * 2 + 1][0] = r4[2]; Bfh[p * 2 + 1][1] = r4[3];
                ldsm_x4_t(r4, uBl + boff);
                Bfl[p * 2][0] = r4[0]; Bfl[p * 2][1] = r4[1];
                Bfl[p * 2 + 1][0] = r4[2]; Bfl[p * 2 + 1][1] = r4[3];
            }
#pragma unroll
            for (int mt = 0; mt < 4; mt++) {
                uint32_t aoff = (uint32_t)(((wm * 64 + mt * 16 + lo16) * ASTR_ + k0 + 8 * hi16) * 2);
                uint32_t Afh[4], Afl[4];
                ldsm_x4(Afh, uAh + aoff);
                ldsm_x4(Afl, uAl + aoff);
#pragma unroll
                for (int nt = 0; nt < 4; nt++) {
                    mma_bf16(acc[mt][nt], Afh, Bfh[nt]);
                    mma_bf16(acc[mt][nt], Afh, Bfl[nt]);
                    mma_bf16(acc[mt][nt], Afl, Bfh[nt]);
                }
            }
        }
        __syncthreads();
    }

    int row_in = lane >> 2, colq = (lane & 3) * 2;
#pragma unroll
    for (int mt = 0; mt < 4; mt++) {
#pragma unroll
        for (int nt = 0; nt < 4; nt++) {
            int m0 = bm + wm * 64 + mt * 16 + row_in;
            int n0 = bn + wn * 32 + nt * 8 + colq;
            float b0 = bias[n0], b1 = bias[n0 + 1];
            float v00 = acc[mt][nt][0] + b0, v01 = acc[mt][nt][1] + b1;
            float v10 = acc[mt][nt][2] + b0, v11 = acc[mt][nt][3] + b1;
            if (MODE == 0) {
                float g00 = gelu_t(v00), g01 = gelu_t(v01);
                float g10 = gelu_t(v10), g11 = gelu_t(v11);
                __nv_bfloat16 h00 = __float2bfloat16(g00), h01 = __float2bfloat16(g01);
                __nv_bfloat16 h10 = __float2bfloat16(g10), h11 = __float2bfloat16(g11);
                __nv_bfloat16 l00 = __float2bfloat16(g00 - __bfloat162float(h00));
                __nv_bfloat16 l01 = __float2bfloat16(g01 - __bfloat162float(h01));
                __nv_bfloat16 l10 = __float2bfloat16(g10 - __bfloat162float(h10));
                __nv_bfloat16 l11 = __float2bfloat16(g11 - __bfloat162float(h11));
                *(__nv_bfloat162*)(Ch + m0 * N + n0)       = __nv_bfloat162(h00, h01);
                *(__nv_bfloat162*)(Ch + (m0 + 8) * N + n0) = __nv_bfloat162(h10, h11);
                *(__nv_bfloat162*)(Cl + m0 * N + n0)       = __nv_bfloat162(l00, l01);
                *(__nv_bfloat162*)(Cl + (m0 + 8) * N + n0) = __nv_bfloat162(l10, l11);
            } else {
                *(float2*)(Cf + m0 * N + n0)       = make_float2(v00, v01);
                *(float2*)(Cf + (m0 + 8) * N + n0) = make_float2(v10, v11);
            }
        }
    }
}

// ---------------- routed experts: 512 threads, cp.async pipelined ----------------
// smem layout (bf16 elems):
//  sXh [128][136] @ 0       sXl @ 17408
//  sHh [128][72]  @ 34816   sHl @ 44032
//  W1 buf: h @ 53248, l @ 62464   (used as [128][72], data cols 0..63)
//  W2 buf: h @ 71680, l @ 80896   (used as [64][136], data cols 0..127)
#define RT2_SMEM (90112 * 2)

__global__ void __launch_bounds__(512)
routed_hmma(const __nv_bfloat16* __restrict__ Xh, const __nv_bfloat16* __restrict__ Xl,
            const __nv_bfloat16* __restrict__ E1h, const __nv_bfloat16* __restrict__ E1l,
            const float* __restrict__ be1,
            const __nv_bfloat16* __restrict__ E2h, const __nv_bfloat16* __restrict__ E2l,
            const float* __restrict__ be2) {
    extern __shared__ __nv_bfloat16 sm2[];
    __shared__ int   s_entry[128];
    __shared__ float s_w[128];

    int tid = threadIdx.x, wid = tid >> 5, lane = tid & 31;
    int e = blockIdx.y;
    int base = g_off[e] + blockIdx.x * 128;
    int end  = g_off[e + 1];
    if (base >= end) return;

    __nv_bfloat16* sHh = sm2 + 34816;
    __nv_bfloat16* sHl = sm2 + 44032;

    uint32_t uS  = smem_u32(sm2);
    uint32_t uXh = uS, uXl = uS + 17408 * 2;
    uint32_t uHh = uS + 34816 * 2, uHl = uS + 44032 * 2;
    uint32_t uW1h = uS + 53248 * 2, uW1l = uS + 62464 * 2;
    uint32_t uW2h = uS + 71680 * 2, uW2l = uS + 80896 * 2;

    for (int i = tid; i < 128; i += 512) {
        int p = base + i;
        if (p < end) {
            int en = g_perm[p];
            s_entry[i] = en;
            s_w[i] = g_top_w[en];
        } else {
            s_entry[i] = -1;
            s_w[i] = 0.0f;
        }
    }
    __syncthreads();

    const __nv_bfloat16* W1h = E1h + e * (SD_ * HR_);
    const __nv_bfloat16* W1l = E1l + e * (SD_ * HR_);
    const __nv_bfloat16* W2h = E2h + e * (HR_ * SD_);
    const __nv_bfloat16* W2l = E2l + e * (HR_ * SD_);
    const float* b1 = be1 + e * HR_;
    const float* b2 = be2 + e * SD_;

    // X gather via cp.async (zero-fill masked rows): 128 rows x 16 chunks, hi+lo
    for (int i = tid; i < 2048; i += 512) {
        int row = i >> 4, u = i & 15;
        int en = s_entry[row];
        int sz = (en >= 0) ? 16 : 0;
        int slot = en >> 1;
        long goff = (en >= 0) ? ((long)(slot >> 3) * DIM_ + (slot & 7) * SD_ + u * 8) : 0;
        uint32_t so = (uint32_t)(row * 136 + u * 8) * 2;
        cp16(uXh + so, Xh + goff, sz);
        cp16(uXl + so, Xl + goff, sz);
    }
    // W1 chunk 0: [k=128][h=64] = 128 rows x 8 chunks per buffer, hi+lo = 2048
    for (int i = tid; i < 2048; i += 512) {
        int hl = i >> 10, j = i & 1023;
        int k = j >> 3, u = j & 7;
        const __nv_bfloat16* src = (hl ? W1l : W1h) + k * HR_ + u * 8;
        uint32_t so = (hl ? uW1l : uW1h) + (uint32_t)(k * 72 + u * 8) * 2;
        cp16(so, src, 16);
    }
    cp_commit();
    cp_wait0();
    __syncthreads();

    int wm = wid & 3, wn = wid >> 2;
    int lo16 = lane & 15, hi16 = lane >> 4;
    int row_in = lane >> 2, colq = (lane & 3) * 2;

    float yacc[2][4][4];
#pragma unroll
    for (int i = 0; i < 2; i++)
#pragma unroll
        for (int j = 0; j < 4; j++)
#pragma unroll
            for (int q = 0; q < 4; q++) yacc[i][j][q] = 0.0f;

    for (int ch = 0; ch < 8; ch++) {
        int h0 = ch * 64;

        // prefetch W2[ch] during GEMM1: [k=64][d=128] = 64 rows x 16 chunks, hi+lo = 2048
        for (int i = tid; i < 2048; i += 512) {
            int hl = i >> 10, j = i & 1023;
            int k = j >> 4, u = j & 15;
            const __nv_bfloat16* src = (hl ? W2l : W2h) + (h0 + k) * SD_ + u * 8;
            uint32_t so = (hl ? uW2l : uW2h) + (uint32_t)(k * 136 + u * 8) * 2;
            cp16(so, src, 16);
        }
        cp_commit();

        // GEMM1: H = X @ W1[ch]  (M=128, N=64, K=128)
        float hacc[2][2][4];
#pragma unroll
        for (int i = 0; i < 2; i++)
#pragma unroll
            for (int j = 0; j < 2; j++)
#pragma unroll
                for (int q = 0; q < 4; q++) hacc[i][j][q] = 0.0f;

#pragma unroll
        for (int ks = 0; ks < 8; ks++) {
            int k0 = ks * 16;
            uint32_t boff = (uint32_t)(((k0 + lo16) * 72 + wn * 16 + 8 * hi16) * 2);
            uint32_t Bfh[2][2], Bfl[2][2], r4[4];
            ldsm_x4_t(r4, uW1h + boff);
            Bfh[0][0] = r4[0]; Bfh[0][1] = r4[1]; Bfh[1][0] = r4[2]; Bfh[1][1] = r4[3];
            ldsm_x4_t(r4, uW1l + boff);
            Bfl[0][0] = r4[0]; Bfl[0][1] = r4[1]; Bfl[1][0] = r4[2]; Bfl[1][1] = r4[3];
#pragma unroll
            for (int mt = 0; mt < 2; mt++) {
                uint32_t aoff = (uint32_t)(((wm * 32 + mt * 16 + lo16) * 136 + k0 + 8 * hi16) * 2);
                uint32_t Afh[4], Afl[4];
                ldsm_x4(Afh, uXh + aoff);
                ldsm_x4(Afl, uXl + aoff);
#pragma unroll
                for (int nt = 0; nt < 2; nt++) {
                    mma_bf16(hacc[mt][nt], Afh, Bfh[nt]);
                    mma_bf16(hacc[mt][nt], Afh, Bfl[nt]);
                    mma_bf16(hacc[mt][nt], Afl, Bfh[nt]);
                }
            }
        }

        // H epilogue: gelu(bias+acc) -> split pair into sH
#pragma unroll
        for (int mt = 0; mt < 2; mt++) {
#pragma unroll
            for (int nt = 0; nt < 2; nt++) {
                int n0 = wn * 16 + nt * 8 + colq;
                float bb0 = b1[h0 + n0], bb1 = b1[h0 + n0 + 1];
                float g00 = gelu_t(hacc[mt][nt][0] + bb0);
                float g01 = gelu_t(hacc[mt][nt][1] + bb1);
                float g10 = gelu_t(hacc[mt][nt][2] + bb0);
                float g11 = gelu_t(hacc[mt][nt][3] + bb1);
                __nv_bfloat16 h00 = __float2bfloat16(g00), h01 = __float2bfloat16(g01);
                __nv_bfloat16 h10 = __float2bfloat16(g10), h11 = __float2bfloat16(g11);
                __nv_bfloat16 l00 = __float2bfloat16(g00 - __bfloat162float(h00));
                __nv_bfloat16 l01 = __float2bfloat16(g01 - __bfloat162float(h01));
                __nv_bfloat16 l10 = __float2bfloat16(g10 - __bfloat162float(h10));
                __nv_bfloat16 l11 = __float2bfloat16(g11 - __bfloat162float(h11));
                int r0 = wm * 32 + mt * 16 + row_in;
                *(__nv_bfloat162*)(sHh + r0 * 72 + n0)       = __nv_bfloat162(h00, h01);
                *(__nv_bfloat162*)(sHh + (r0 + 8) * 72 + n0) = __nv_bfloat162(h10, h11);
                *(__nv_bfloat162*)(sHl + r0 * 72 + n0)       = __nv_bfloat162(l00, l01);
                *(__nv_bfloat162*)(sHl + (r0 + 8) * 72 + n0) = __nv_bfloat162(l10, l11);
            }
        }
        cp_wait0();
        __syncthreads();

        // prefetch W1[ch+1] during GEMM2
        if (ch < 7) {
            int h1 = h0 + 64;
            for (int i = tid; i < 2048; i += 512) {
                int hl = i >> 10, j = i & 1023;
                int k = j >> 3, u = j & 7;
                const __nv_bfloat16* src = (hl ? W1l : W1h) + k * HR_ + h1 + u * 8;
                uint32_t so = (hl ? uW1l : uW1h) + (uint32_t)(k * 72 + u * 8) * 2;
                cp16(so, src, 16);
            }
        }
        cp_commit();

        // GEMM2: Y += H @ W2[ch]  (M=128, N=128, K=64)
#pragma unroll
        for (int ks = 0; ks < 4; ks++) {
            int k0 = ks * 16;
            uint32_t Bfh[4][2], Bfl[4][2];
#pragma unroll
            for (int p = 0; p < 2; p++) {
                uint32_t boff = (uint32_t)(((k0 + lo16) * 136 + wn * 32 + p * 16 + 8 * hi16) * 2);
                uint32_t r4[4];
                ldsm_x4_t(r4, uW2h + boff);
                Bfh[p * 2][0] = r4[0]; Bfh[p * 2][1] = r4[1];
                Bfh[p * 2 + 1][0] = r4[2]; Bfh[p * 2 + 1][1] = r4[3];
                ldsm_x4_t(r4, uW2l + boff);
                Bfl[p * 2][0] = r4[0]; Bfl[p * 2][1] = r4[1];
                Bfl[p * 2 + 1][0] = r4[2]; Bfl[p * 2 + 1][1] = r4[3];
            }
#pragma unroll
            for (int mt = 0; mt < 2; mt++) {
                uint32_t aoff = (uint32_t)(((wm * 32 + mt * 16 + lo16) * 72 + k0 + 8 * hi16) * 2);
                uint32_t Afh[4], Afl[4];
                ldsm_x4(Afh, uHh + aoff);
                ldsm_x4(Afl, uHl + aoff);
#pragma unroll
                for (int nt = 0; nt < 4; nt++) {
                    mma_bf16(yacc[mt][nt], Afh, Bfh[nt]);
                    mma_bf16(yacc[mt][nt], Afh, Bfl[nt]);
                    mma_bf16(yacc[mt][nt], Afl, Bfh[nt]);
                }
            }
        }
        cp_wait0();
        __syncthreads();
    }

    // epilogue: g_Yent[entry] = w * (y + b2)
#pragma unroll
    for (int mt = 0; mt < 2; mt++) {
#pragma unroll
        for (int nt = 0; nt < 4; nt++) {
            int n0 = wn * 32 + nt * 8 + colq;
            float bb0 = b2[n0], bb1 = b2[n0 + 1];
            int r0 = wm * 32 + mt * 16 + row_in;
            int en0 = s_entry[r0];
            if (en0 >= 0) {
                float w = s_w[r0];
                *(float2*)(g_Yent + en0 * SD_ + n0) =
                    make_float2(w * (yacc[mt][nt][0] + bb0), w * (yacc[mt][nt][1] + bb1));
            }
            int en1 = s_entry[r0 + 8];
            if (en1 >= 0) {
                float w = s_w[r0 + 8];
                *(float2*)(g_Yent + en1 * SD_ + n0) =
                    make_float2(w * (yacc[mt][nt][2] + bb0), w * (yacc[mt][nt][3] + bb1));
            }
        }
    }
}

// ---------------- init ----------------
__global__ void init_kernel() {
    int t = threadIdx.x;
    if (t < NE_) { g_cnt[t] = 0; g_wsum[t] = 0.0f; }
}

// ---------------- router ----------------
__global__ void router_kernel(const float* __restrict__ X, const float* __restrict__ Wr) {
    __shared__ float Wrs[SD_ * NE_];
    __shared__ int   scnt[NE_];
    __shared__ float sws[NE_];
    int tid = threadIdx.x;
    for (int i = tid; i < SD_ * NE_; i += 128) Wrs[i] = Wr[i];
    if (tid < NE_) { scnt[tid] = 0; sws[tid] = 0.0f; }
    __syncthreads();

    int slot = blockIdx.x * 128 + tid;
    const float* x = X + (slot >> 3) * DIM_ + (slot & 7) * SD_;
    float lg[NE_];
#pragma unroll
    for (int e = 0; e < NE_; e++) lg[e] = 0.0f;
    for (int k = 0; k < SD_; k++) {
        float xv = x[k];
        const float* wr = &Wrs[k * NE_];
#pragma unroll
        for (int e = 0; e < NE_; e++) lg[e] += xv * wr[e];
    }
    float mx = lg[0];
#pragma unroll
    for (int e = 1; e < NE_; e++) mx = fmaxf(mx, lg[e]);
    float p[NE_]; float sum = 0.0f;
#pragma unroll
    for (int e = 0; e < NE_; e++) { p[e] = expf(lg[e] - mx); sum += p[e]; }
    float inv = 1.0f / sum;
    int i0 = 0; float m0 = -1.0f;
#pragma unroll
    for (int e = 0; e < NE_; e++) if (p[e] > m0) { m0 = p[e]; i0 = e; }
    int i1 = 0; float m1 = -1.0f;
#pragma unroll
    for (int e = 0; e < NE_; e++) if (e != i0 && p[e] > m1) { m1 = p[e]; i1 = e; }
    float w0 = m0 * inv, w1 = m1 * inv;

    g_top_idx[2 * slot]     = i0;
    g_top_idx[2 * slot + 1] = i1;
    g_top_w[2 * slot]       = w0;
    g_top_w[2 * slot + 1]   = w1;

    atomicAdd(&scnt[i0], 1); atomicAdd(&scnt[i1], 1);
    atomicAdd(&sws[i0], w0); atomicAdd(&sws[i1], w1);
    __syncthreads();
    if (tid < NE_) {
        atomicAdd(&g_cnt[tid], scnt[tid]);
        atomicAdd(&g_wsum[tid], sws[tid]);
    }
}

// ---------------- offsets + aux ----------------
__global__ void offsets_kernel() {
    if (threadIdx.x == 0) {
        int acc = 0; float aux = 0.0f;
        for (int e = 0; e < NE_; e++) {
            g_off[e] = acc; g_cursor[e] = acc;
            acc += g_cnt[e];
            float f = (float)g_cnt[e] / ((float)NS_ * (float)KTOP_);
            float P = g_wsum[e] / (float)NS_;
            aux += f * P;
        }
        g_off[NE_] = acc;
        g_aux = (float)NE_ * aux;
    }
}

// ---------------- scatter ----------------
__global__ void scatter_kernel() {
    int slot = blockIdx.x * blockDim.x + threadIdx.x;
    if (slot >= NS_) return;
#pragma unroll
    for (int k = 0; k < KTOP_; k++) {
        int en = 2 * slot + k;
        int e = g_top_idx[en];
        int p = atomicAdd(&g_cursor[e], 1);
        g_perm[p] = en;
    }
}

// ---------------- combine ----------------
__global__ void combine_kernel(float* __restrict__ out, int out_size) {
    int idx = blockIdx.x * 256 + threadIdx.x;
    int c = idx & (SD_ - 1);
    int slot = idx >> 7;
    int token = slot >> 3, s = slot & 7;
    float add = g_Yent[(2 * slot) * SD_ + c] + g_Yent[(2 * slot + 1) * SD_ + c];
    out[token * DIM_ + s * SD_ + c] += add;
    if (idx == 0 && out_size > TOK_ * DIM_) out[TOK_ * DIM_] = g_aux;
}

// ---------------- launch ----------------
extern "C" void kernel_launch(void* const* d_in, const int* in_sizes, int n_in,
                              void* d_out, int out_size) {
    const float* X   = (const float*)d_in[0];
    const float* Ws1 = (const float*)d_in[1];
    const float* bs1 = (const float*)d_in[2];
    const float* Ws2 = (const float*)d_in[3];
    const float* bs2 = (const float*)d_in[4];
    const float* Wr  = (const float*)d_in[5];
    const float* We1 = (const float*)d_in[6];
    const float* be1 = (const float*)d_in[7];
    const float* We2 = (const float*)d_in[8];
    const float* be2 = (const float*)d_in[9];
    float* out = (float*)d_out;

    static cudaStream_t s2 = nullptr;
    static cudaEvent_t evFork = nullptr, evJoin = nullptr;
    if (s2 == nullptr) {
        cudaStreamCreateWithFlags(&s2, cudaStreamNonBlocking);
        cudaEventCreateWithFlags(&evFork, cudaEventDisableTiming);
        cudaEventCreateWithFlags(&evJoin, cudaEventDisableTiming);
    }

    cudaFuncSetAttribute(gemm_hmma<0>, cudaFuncAttributeMaxDynamicSharedMemorySize, GSM_BYTES);
    cudaFuncSetAttribute(gemm_hmma<1>, cudaFuncAttributeMaxDynamicSharedMemorySize, GSM_BYTES);
    cudaFuncSetAttribute(routed_hmma, cudaFuncAttributeMaxDynamicSharedMemorySize, RT2_SMEM);

    __nv_bfloat16 *Xh, *Xl, *W1h, *W1l, *W2h, *W2l, *H1h, *H1l;
    __nv_bfloat16 *E1h, *E1l, *E2h, *E2l;
    cudaGetSymbolAddress((void**)&Xh,  g_Xh);
    cudaGetSymbolAddress((void**)&Xl,  g_Xl);
    cudaGetSymbolAddress((void**)&W1h, g_W1h);
    cudaGetSymbolAddress((void**)&W1l, g_W1l);
    cudaGetSymbolAddress((void**)&W2h, g_W2h);
    cudaGetSymbolAddress((void**)&W2l, g_W2l);
    cudaGetSymbolAddress((void**)&H1h, g_H1h);
    cudaGetSymbolAddress((void**)&H1l, g_H1l);
    cudaGetSymbolAddress((void**)&E1h, g_E1h);
    cudaGetSymbolAddress((void**)&E1l, g_E1l);
    cudaGetSymbolAddress((void**)&E2h, g_E2h);
    cudaGetSymbolAddress((void**)&E2l, g_E2l);

    // ---- main stream: router chain + routed prerequisites ----
    init_kernel<<<1, 64>>>();
    router_kernel<<<NS_ / 128, 128>>>(X, Wr);
    offsets_kernel<<<1, 32>>>();
    scatter_kernel<<<NS_ / 128, 128>>>();
    split_kernel<<<(TOK_ * DIM_ / 4 + 255) / 256, 256>>>(X, Xh, Xl, TOK_ * DIM_ / 4);
    split_kernel<<<(NE_ * SD_ * HR_ / 4 + 255) / 256, 256>>>(We1, E1h, E1l, NE_ * SD_ * HR_ / 4);
    split_kernel<<<(NE_ * HR_ * SD_ / 4 + 255) / 256, 256>>>(We2, E2h, E2l, NE_ * HR_ * SD_ / 4);

    // ---- fork: routed experts on s2, overlapping the shared-expert GEMMs ----
    cudaEventRecord(evFork, 0);
    cudaStreamWaitEvent(s2, evFork, 0);
    routed_hmma<<<dim3(NENT_ / 128, NE_), 512, RT2_SMEM, s2>>>(
        Xh, Xl, E1h, E1l, be1, E2h, E2l, be2);
    cudaEventRecord(evJoin, s2);

    // ---- main stream: shared expert ----
    split_kernel<<<(DIM_ * HSH_ / 4 + 255) / 256, 256>>>(Ws1, W1h, W1l, DIM_ * HSH_ / 4);
    split_kernel<<<(HSH_ * DIM_ / 4 + 255) / 256, 256>>>(Ws2, W2h, W2l, HSH_ * DIM_ / 4);
    gemm_hmma<0><<<dim3(HSH_ / BN_, TOK_ / BM_), 256, GSM_BYTES>>>(
        Xh, Xl, W1h, W1l, bs1, nullptr, H1h, H1l, TOK_, HSH_, DIM_);
    gemm_hmma<1><<<dim3(DIM_ / BN_, TOK_ / BM_), 256, GSM_BYTES>>>(
        H1h, H1l, W2h, W2l, bs2, out, nullptr, nullptr, TOK_, DIM_, HSH_);

    // ---- join + combine ----
    cudaStreamWaitEvent(0, evJoin, 0);
    combine_kernel<<<(NS_ * SD_) / 256, 256>>>(out, out_size);
}

// round 7
// speedup vs baseline: 5.5673x; 1.3217x over previous
#include <cuda_runtime.h>
#include <cuda_bf16.h>
#include <cstdint>

// ---------------- problem constants ----------------
#define B_ 2
#define T_ 2048
#define DIM_ 1024
#define SEG_ 8
#define SD_ 128
#define NE_ 16
#define KTOP_ 2
#define HSH_ 4096
#define HR_ 512
#define TOK_ (B_ * T_)            // 4096 tokens
#define NS_ (TOK_ * SEG_)         // 32768 token-segments
#define NENT_ (NS_ * KTOP_)       // 65536 routed entries

// ---------------- device scratch ----------------
__device__ __nv_bfloat16 g_Xh[TOK_ * DIM_];
__device__ __nv_bfloat16 g_Xl[TOK_ * DIM_];
__device__ __nv_bfloat16 g_W1h[DIM_ * HSH_];
__device__ __nv_bfloat16 g_W1l[DIM_ * HSH_];
__device__ __nv_bfloat16 g_W2h[HSH_ * DIM_];
__device__ __nv_bfloat16 g_W2l[HSH_ * DIM_];
__device__ __nv_bfloat16 g_H1h[TOK_ * HSH_];
__device__ __nv_bfloat16 g_H1l[TOK_ * HSH_];
__device__ __nv_bfloat16 g_E1h[NE_ * SD_ * HR_];
__device__ __nv_bfloat16 g_E1l[NE_ * SD_ * HR_];
__device__ __nv_bfloat16 g_E2h[NE_ * HR_ * SD_];
__device__ __nv_bfloat16 g_E2l[NE_ * HR_ * SD_];
__device__ float g_Yent[NENT_ * SD_];
__device__ int   g_top_idx[NENT_];
__device__ float g_top_w[NENT_];
__device__ int   g_cnt[NE_];
__device__ float g_wsum[NE_];
__device__ int   g_off[NE_ + 1];
__device__ int   g_cursor[NE_];
__device__ int   g_perm[NENT_];
__device__ float g_aux;

__device__ __forceinline__ float gelu_t(float x) {
    float x3 = x * x * x;
    return 0.5f * x * (1.0f + tanhf(0.7978845608028654f * (x + 0.044715f * x3)));
}

__device__ __forceinline__ uint32_t smem_u32(const void* p) {
    uint32_t a;
    asm("{ .reg .u64 t; cvta.to.shared.u64 t, %1; cvt.u32.u64 %0, t; }" : "=r"(a) : "l"(p));
    return a;
}

__device__ __forceinline__ void ldsm_x4(uint32_t r[4], uint32_t addr) {
    asm volatile("ldmatrix.sync.aligned.m8n8.x4.shared.b16 {%0,%1,%2,%3}, [%4];"
        : "=r"(r[0]), "=r"(r[1]), "=r"(r[2]), "=r"(r[3]) : "r"(addr));
}
__device__ __forceinline__ void ldsm_x4_t(uint32_t r[4], uint32_t addr) {
    asm volatile("ldmatrix.sync.aligned.m8n8.x4.trans.shared.b16 {%0,%1,%2,%3}, [%4];"
        : "=r"(r[0]), "=r"(r[1]), "=r"(r[2]), "=r"(r[3]) : "r"(addr));
}
__device__ __forceinline__ void mma_bf16(float d[4], const uint32_t a[4], const uint32_t b[2]) {
    asm volatile("mma.sync.aligned.m16n8k16.row.col.f32.bf16.bf16.f32 "
        "{%0,%1,%2,%3}, {%4,%5,%6,%7}, {%8,%9}, {%0,%1,%2,%3};"
        : "+f"(d[0]), "+f"(d[1]), "+f"(d[2]), "+f"(d[3])
        : "r"(a[0]), "r"(a[1]), "r"(a[2]), "r"(a[3]), "r"(b[0]), "r"(b[1]));
}
__device__ __forceinline__ void cp16(uint32_t s, const void* g, int szbytes) {
    asm volatile("cp.async.cg.shared.global [%0], [%1], 16, %2;"
        :: "r"(s), "l"(g), "r"(szbytes));
}
__device__ __forceinline__ void cp_commit() { asm volatile("cp.async.commit_group;" ::: "memory"); }
__device__ __forceinline__ void cp_wait0()  { asm volatile("cp.async.wait_group 0;" ::: "memory"); }
__device__ __forceinline__ void cp_wait1()  { asm volatile("cp.async.wait_group 1;" ::: "memory"); }

// ---------------- split-precision conversion ----------------
__global__ void split_kernel(const float* __restrict__ src,
                             __nv_bfloat16* __restrict__ h,
                             __nv_bfloat16* __restrict__ l, int n4) {
    int i = blockIdx.x * 256 + threadIdx.x;
    if (i >= n4) return;
    float4 v = ((const float4*)src)[i];
    float vs[4] = {v.x, v.y, v.z, v.w};
    __nv_bfloat16 hh[4], ll[4];
#pragma unroll
    for (int j = 0; j < 4; j++) {
        hh[j] = __float2bfloat16(vs[j]);
        ll[j] = __float2bfloat16(vs[j] - __bfloat162float(hh[j]));
    }
    ((__nv_bfloat162*)h)[2 * i]     = __nv_bfloat162(hh[0], hh[1]);
    ((__nv_bfloat162*)h)[2 * i + 1] = __nv_bfloat162(hh[2], hh[3]);
    ((__nv_bfloat162*)l)[2 * i]     = __nv_bfloat162(ll[0], ll[1]);
    ((__nv_bfloat162*)l)[2 * i + 1] = __nv_bfloat162(ll[2], ll[3]);
}

// ---------------- HMMA split-bf16 GEMM, 2-stage cp.async pipeline ----------------
// C[M,N] = A[M,K] @ B[K,N]
// MODE 0: epilogue gelu(acc+bias) -> (Ch, Cl) bf16 split pair
// MODE 1: epilogue acc+bias -> Cf fp32
#define BM_ 128
#define BN_ 128
#define BK_ 64
#define ASTR_ 72
#define BSTR_ 136
// per-stage byte offsets (bf16 elems *2):
//  sAh @ 0 (128x72=9216 el), sAl @ 18432 B, sBh @ 36864 B (64x136=8704 el), sBl @ 54272 B
#define STG_BYTES 71680
#define GSM_BYTES (2 * STG_BYTES)

template <int MODE>
__global__ void __launch_bounds__(256)
gemm_hmma(const __nv_bfloat16* __restrict__ Ah, const __nv_bfloat16* __restrict__ Al,
          const __nv_bfloat16* __restrict__ Bh, const __nv_bfloat16* __restrict__ Bl,
          const float* __restrict__ bias,
          float* __restrict__ Cf,
          __nv_bfloat16* __restrict__ Ch, __nv_bfloat16* __restrict__ Cl,
          int M, int N, int K) {
    extern __shared__ char smraw[];

    int tid = threadIdx.x;
    int wid = tid >> 5, lane = tid & 31;
    int wm = wid & 1, wn = wid >> 1;
    int bn = blockIdx.x * BN_, bm = blockIdx.y * BM_;

    uint32_t uS = smem_u32(smraw);

    float acc[4][4][4];
#pragma unroll
    for (int i = 0; i < 4; i++)
#pragma unroll
        for (int j = 0; j < 4; j++)
#pragma unroll
            for (int q = 0; q < 4; q++) acc[i][j][q] = 0.0f;

    int lo16 = lane & 15, hi16 = lane >> 4;

    // chunk loader: A 128x8 uint4 chunks, B 64x16 uint4 chunks, hi+lo
    auto load_chunk = [&](int kc, int st) {
        uint32_t bAh = uS + st * STG_BYTES;
        uint32_t bAl = bAh + 18432;
        uint32_t bBh = bAh + 36864;
        uint32_t bBl = bAh + 54272;
#pragma unroll 2
        for (int i = tid; i < 1024; i += 256) {
            int r = i >> 3, u = i & 7;
            int g = (bm + r) * K + kc + u * 8;
            uint32_t so = (uint32_t)(r * ASTR_ + u * 8) * 2;
            cp16(bAh + so, Ah + g, 16);
            cp16(bAl + so, Al + g, 16);
        }
#pragma unroll 2
        for (int i = tid; i < 1024; i += 256) {
            int r = i >> 4, u = i & 15;
            int g = (kc + r) * N + bn + u * 8;
            uint32_t so = (uint32_t)(r * BSTR_ + u * 8) * 2;
            cp16(bBh + so, Bh + g, 16);
            cp16(bBl + so, Bl + g, 16);
        }
    };

    int nch = K / BK_;
    load_chunk(0, 0);
    cp_commit();

    for (int c = 0; c < nch; c++) {
        int st = c & 1;
        if (c + 1 < nch) {
            load_chunk((c + 1) * BK_, st ^ 1);
            cp_commit();
            cp_wait1();
        } else {
            cp_wait0();
        }
        __syncthreads();

        uint32_t uAh = uS + st * STG_BYTES;
        uint32_t uAl = uAh + 18432;
        uint32_t uBh = uAh + 36864;
        uint32_t uBl = uAh + 54272;

#pragma unroll
        for (int ks = 0; ks < 4; ks++) {
            int k0 = ks * 16;
            uint32_t Bfh[4][2], Bfl[4][2];
#pragma unroll
            for (int p = 0; p < 2; p++) {
                uint32_t boff = (uint32_t)(((k0 + lo16) * BSTR_ + wn * 32 + p * 16 + 8 * hi16) * 2);
                uint32_t r4[4];
                ldsm_x4_t(r4, uBh + boff);
                Bfh[p * 2][0] = r4[0]; Bfh[p * 2][1] = r4[1];
                Bfh[p * 2 + 1][0] = r4[2]; Bfh[p * 2 + 1][1] = r4[3];
                ldsm_x4_t(r4, uBl + boff);
                Bfl[p * 2][0] = r4[0]; Bfl[p * 2][1] = r4[1];
                Bfl[p * 2 + 1][0] = r4[2]; Bfl[p * 2 + 1][1] = r4[3];
            }
#pragma unroll
            for (int mt = 0; mt < 4; mt++) {
                uint32_t aoff = (uint32_t)(((wm * 64 + mt * 16 + lo16) * ASTR_ + k0 + 8 * hi16) * 2);
                uint32_t Afh[4], Afl[4];
                ldsm_x4(Afh, uAh + aoff);
                ldsm_x4(Afl, uAl + aoff);
#pragma unroll
                for (int nt = 0; nt < 4; nt++) {
                    mma_bf16(acc[mt][nt], Afh, Bfh[nt]);
                    mma_bf16(acc[mt][nt], Afh, Bfl[nt]);
                    mma_bf16(acc[mt][nt], Afl, Bfh[nt]);
                }
            }
        }
        __syncthreads();
    }

    int row_in = lane >> 2, colq = (lane & 3) * 2;
#pragma unroll
    for (int mt = 0; mt < 4; mt++) {
#pragma unroll
        for (int nt = 0; nt < 4; nt++) {
            int m0 = bm + wm * 64 + mt * 16 + row_in;
            int n0 = bn + wn * 32 + nt * 8 + colq;
            float b0 = bias[n0], b1 = bias[n0 + 1];
            float v00 = acc[mt][nt][0] + b0, v01 = acc[mt][nt][1] + b1;
            float v10 = acc[mt][nt][2] + b0, v11 = acc[mt][nt][3] + b1;
            if (MODE == 0) {
                float g00 = gelu_t(v00), g01 = gelu_t(v01);
                float g10 = gelu_t(v10), g11 = gelu_t(v11);
                __nv_bfloat16 h00 = __float2bfloat16(g00), h01 = __float2bfloat16(g01);
                __nv_bfloat16 h10 = __float2bfloat16(g10), h11 = __float2bfloat16(g11);
                __nv_bfloat16 l00 = __float2bfloat16(g00 - __bfloat162float(h00));
                __nv_bfloat16 l01 = __float2bfloat16(g01 - __bfloat162float(h01));
                __nv_bfloat16 l10 = __float2bfloat16(g10 - __bfloat162float(h10));
                __nv_bfloat16 l11 = __float2bfloat16(g11 - __bfloat162float(h11));
                *(__nv_bfloat162*)(Ch + m0 * N + n0)       = __nv_bfloat162(h00, h01);
                *(__nv_bfloat162*)(Ch + (m0 + 8) * N + n0) = __nv_bfloat162(h10, h11);
                *(__nv_bfloat162*)(Cl + m0 * N + n0)       = __nv_bfloat162(l00, l01);
                *(__nv_bfloat162*)(Cl + (m0 + 8) * N + n0) = __nv_bfloat162(l10, l11);
            } else {
                *(float2*)(Cf + m0 * N + n0)       = make_float2(v00, v01);
                *(float2*)(Cf + (m0 + 8) * N + n0) = make_float2(v10, v11);
            }
        }
    }
}

// ---------------- routed experts: 512 threads, cp.async pipelined ----------------
// smem layout (bf16 elems):
//  sXh [128][136] @ 0       sXl @ 17408
//  sHh [128][72]  @ 34816   sHl @ 44032
//  W1 buf: h @ 53248, l @ 62464   (used as [128][72], data cols 0..63)
//  W2 buf: h @ 71680, l @ 80896   (used as [64][136], data cols 0..127)
#define RT2_SMEM (90112 * 2)

__global__ void __launch_bounds__(512)
routed_hmma(const __nv_bfloat16* __restrict__ Xh, const __nv_bfloat16* __restrict__ Xl,
            const __nv_bfloat16* __restrict__ E1h, const __nv_bfloat16* __restrict__ E1l,
            const float* __restrict__ be1,
            const __nv_bfloat16* __restrict__ E2h, const __nv_bfloat16* __restrict__ E2l,
            const float* __restrict__ be2) {
    extern __shared__ __nv_bfloat16 sm2[];
    __shared__ int   s_entry[128];
    __shared__ float s_w[128];

    int tid = threadIdx.x, wid = tid >> 5, lane = tid & 31;
    int e = blockIdx.y;
    int base = g_off[e] + blockIdx.x * 128;
    int end  = g_off[e + 1];
    if (base >= end) return;

    __nv_bfloat16* sHh = sm2 + 34816;
    __nv_bfloat16* sHl = sm2 + 44032;

    uint32_t uS  = smem_u32(sm2);
    uint32_t uXh = uS, uXl = uS + 17408 * 2;
    uint32_t uHh = uS + 34816 * 2, uHl = uS + 44032 * 2;
    uint32_t uW1h = uS + 53248 * 2, uW1l = uS + 62464 * 2;
    uint32_t uW2h = uS + 71680 * 2, uW2l = uS + 80896 * 2;

    for (int i = tid; i < 128; i += 512) {
        int p = base + i;
        if (p < end) {
            int en = g_perm[p];
            s_entry[i] = en;
            s_w[i] = g_top_w[en];
        } else {
            s_entry[i] = -1;
            s_w[i] = 0.0f;
        }
    }
    __syncthreads();

    const __nv_bfloat16* W1h = E1h + e * (SD_ * HR_);
    const __nv_bfloat16* W1l = E1l + e * (SD_ * HR_);
    const __nv_bfloat16* W2h = E2h + e * (HR_ * SD_);
    const __nv_bfloat16* W2l = E2l + e * (HR_ * SD_);
    const float* b1 = be1 + e * HR_;
    const float* b2 = be2 + e * SD_;

    // X gather via cp.async (zero-fill masked rows): 128 rows x 16 chunks, hi+lo
    for (int i = tid; i < 2048; i += 512) {
        int row = i >> 4, u = i & 15;
        int en = s_entry[row];
        int sz = (en >= 0) ? 16 : 0;
        int slot = en >> 1;
        long goff = (en >= 0) ? ((long)(slot >> 3) * DIM_ + (slot & 7) * SD_ + u * 8) : 0;
        uint32_t so = (uint32_t)(row * 136 + u * 8) * 2;
        cp16(uXh + so, Xh + goff, sz);
        cp16(uXl + so, Xl + goff, sz);
    }
    // W1 chunk 0: [k=128][h=64] = 128 rows x 8 chunks per buffer, hi+lo = 2048
    for (int i = tid; i < 2048; i += 512) {
        int hl = i >> 10, j = i & 1023;
        int k = j >> 3, u = j & 7;
        const __nv_bfloat16* src = (hl ? W1l : W1h) + k * HR_ + u * 8;
        uint32_t so = (hl ? uW1l : uW1h) + (uint32_t)(k * 72 + u * 8) * 2;
        cp16(so, src, 16);
    }
    cp_commit();
    cp_wait0();
    __syncthreads();

    int wm = wid & 3, wn = wid >> 2;
    int lo16 = lane & 15, hi16 = lane >> 4;
    int row_in = lane >> 2, colq = (lane & 3) * 2;

    float yacc[2][4][4];
#pragma unroll
    for (int i = 0; i < 2; i++)
#pragma unroll
        for (int j = 0; j < 4; j++)
#pragma unroll
            for (int q = 0; q < 4; q++) yacc[i][j][q] = 0.0f;

    for (int ch = 0; ch < 8; ch++) {
        int h0 = ch * 64;

        // prefetch W2[ch] during GEMM1: [k=64][d=128] = 64 rows x 16 chunks, hi+lo = 2048
        for (int i = tid; i < 2048; i += 512) {
            int hl = i >> 10, j = i & 1023;
            int k = j >> 4, u = j & 15;
            const __nv_bfloat16* src = (hl ? W2l : W2h) + (h0 + k) * SD_ + u * 8;
            uint32_t so = (hl ? uW2l : uW2h) + (uint32_t)(k * 136 + u * 8) * 2;
            cp16(so, src, 16);
        }
        cp_commit();

        // GEMM1: H = X @ W1[ch]  (M=128, N=64, K=128)
        float hacc[2][2][4];
#pragma unroll
        for (int i = 0; i < 2; i++)
#pragma unroll
            for (int j = 0; j < 2; j++)
#pragma unroll
                for (int q = 0; q < 4; q++) hacc[i][j][q] = 0.0f;

#pragma unroll
        for (int ks = 0; ks < 8; ks++) {
            int k0 = ks * 16;
            uint32_t boff = (uint32_t)(((k0 + lo16) * 72 + wn * 16 + 8 * hi16) * 2);
            uint32_t Bfh[2][2], Bfl[2][2], r4[4];
            ldsm_x4_t(r4, uW1h + boff);
            Bfh[0][0] = r4[0]; Bfh[0][1] = r4[1]; Bfh[1][0] = r4[2]; Bfh[1][1] = r4[3];
            ldsm_x4_t(r4, uW1l + boff);
            Bfl[0][0] = r4[0]; Bfl[0][1] = r4[1]; Bfl[1][0] = r4[2]; Bfl[1][1] = r4[3];
#pragma unroll
            for (int mt = 0; mt < 2; mt++) {
                uint32_t aoff = (uint32_t)(((wm * 32 + mt * 16 + lo16) * 136 + k0 + 8 * hi16) * 2);
                uint32_t Afh[4], Afl[4];
                ldsm_x4(Afh, uXh + aoff);
                ldsm_x4(Afl, uXl + aoff);
#pragma unroll
                for (int nt = 0; nt < 2; nt++) {
                    mma_bf16(hacc[mt][nt], Afh, Bfh[nt]);
                    mma_bf16(hacc[mt][nt], Afh, Bfl[nt]);
                    mma_bf16(hacc[mt][nt], Afl, Bfh[nt]);
                }
            }
        }

        // H epilogue: gelu(bias+acc) -> split pair into sH
#pragma unroll
        for (int mt = 0; mt < 2; mt++) {
#pragma unroll
            for (int nt = 0; nt < 2; nt++) {
                int n0 = wn * 16 + nt * 8 + colq;
                float bb0 = b1[h0 + n0], bb1 = b1[h0 + n0 + 1];
                float g00 = gelu_t(hacc[mt][nt][0] + bb0);
                float g01 = gelu_t(hacc[mt][nt][1] + bb1);
                float g10 = gelu_t(hacc[mt][nt][2] + bb0);
                float g11 = gelu_t(hacc[mt][nt][3] + bb1);
                __nv_bfloat16 h00 = __float2bfloat16(g00), h01 = __float2bfloat16(g01);
                __nv_bfloat16 h10 = __float2bfloat16(g10), h11 = __float2bfloat16(g11);
                __nv_bfloat16 l00 = __float2bfloat16(g00 - __bfloat162float(h00));
                __nv_bfloat16 l01 = __float2bfloat16(g01 - __bfloat162float(h01));
                __nv_bfloat16 l10 = __float2bfloat16(g10 - __bfloat162float(h10));
                __nv_bfloat16 l11 = __float2bfloat16(g11 - __bfloat162float(h11));
                int r0 = wm * 32 + mt * 16 + row_in;
                *(__nv_bfloat162*)(sHh + r0 * 72 + n0)       = __nv_bfloat162(h00, h01);
                *(__nv_bfloat162*)(sHh + (r0 + 8) * 72 + n0) = __nv_bfloat162(h10, h11);
                *(__nv_bfloat162*)(sHl + r0 * 72 + n0)       = __nv_bfloat162(l00, l01);
                *(__nv_bfloat162*)(sHl + (r0 + 8) * 72 + n0) = __nv_bfloat162(l10, l11);
            }
        }
        cp_wait0();
        __syncthreads();

        // prefetch W1[ch+1] during GEMM2
        if (ch < 7) {
            int h1 = h0 + 64;
            for (int i = tid; i < 2048; i += 512) {
                int hl = i >> 10, j = i & 1023;
                int k = j >> 3, u = j & 7;
                const __nv_bfloat16* src = (hl ? W1l : W1h) + k * HR_ + h1 + u * 8;
                uint32_t so = (hl ? uW1l : uW1h) + (uint32_t)(k * 72 + u * 8) * 2;
                cp16(so, src, 16);
            }
        }
        cp_commit();

        // GEMM2: Y += H @ W2[ch]  (M=128, N=128, K=64)
#pragma unroll
        for (int ks = 0; ks < 4; ks++) {
            int k0 = ks * 16;
            uint32_t Bfh[4][2], Bfl[4][2];
#pragma unroll
            for (int p = 0; p < 2; p++) {
                uint32_t boff = (uint32_t)(((k0 + lo16) * 136 + wn * 32 + p * 16 + 8 * hi16) * 2);
                uint32_t r4[4];
                ldsm_x4_t(r4, uW2h + boff);
                Bfh[p * 2][0] = r4[0]; Bfh[p * 2][1] = r4[1];
                Bfh[p * 2 + 1][0] = r4[2]; Bfh[p * 2 + 1][1] = r4[3];
                ldsm_x4_t(r4, uW2l + boff);
                Bfl[p * 2][0] = r4[0]; Bfl[p * 2][1] = r4[1];
                Bfl[p * 2 + 1][0] = r4[2]; Bfl[p * 2 + 1][1] = r4[3];
            }
#pragma unroll
            for (int mt = 0; mt < 2; mt++) {
                uint32_t aoff = (uint32_t)(((wm * 32 + mt * 16 + lo16) * 72 + k0 + 8 * hi16) * 2);
                uint32_t Afh[4], Afl[4];
                ldsm_x4(Afh, uHh + aoff);
                ldsm_x4(Afl, uHl + aoff);
#pragma unroll
                for (int nt = 0; nt < 4; nt++) {
                    mma_bf16(yacc[mt][nt], Afh, Bfh[nt]);
                    mma_bf16(yacc[mt][nt], Afh, Bfl[nt]);
                    mma_bf16(yacc[mt][nt], Afl, Bfh[nt]);
                }
            }
        }
        cp_wait0();
        __syncthreads();
    }

    // epilogue: g_Yent[entry] = w * (y + b2)
#pragma unroll
    for (int mt = 0; mt < 2; mt++) {
#pragma unroll
        for (int nt = 0; nt < 4; nt++) {
            int n0 = wn * 32 + nt * 8 + colq;
            float bb0 = b2[n0], bb1 = b2[n0 + 1];
            int r0 = wm * 32 + mt * 16 + row_in;
            int en0 = s_entry[r0];
            if (en0 >= 0) {
                float w = s_w[r0];
                *(float2*)(g_Yent + en0 * SD_ + n0) =
                    make_float2(w * (yacc[mt][nt][0] + bb0), w * (yacc[mt][nt][1] + bb1));
            }
            int en1 = s_entry[r0 + 8];
            if (en1 >= 0) {
                float w = s_w[r0 + 8];
                *(float2*)(g_Yent + en1 * SD_ + n0) =
                    make_float2(w * (yacc[mt][nt][2] + bb0), w * (yacc[mt][nt][3] + bb1));
            }
        }
    }
}

// ---------------- init ----------------
__global__ void init_kernel() {
    int t = threadIdx.x;
    if (t < NE_) { g_cnt[t] = 0; g_wsum[t] = 0.0f; }
}

// ---------------- router ----------------
__global__ void router_kernel(const float* __restrict__ X, const float* __restrict__ Wr) {
    __shared__ float Wrs[SD_ * NE_];
    __shared__ int   scnt[NE_];
    __shared__ float sws[NE_];
    int tid = threadIdx.x;
    for (int i = tid; i < SD_ * NE_; i += 128) Wrs[i] = Wr[i];
    if (tid < NE_) { scnt[tid] = 0; sws[tid] = 0.0f; }
    __syncthreads();

    int slot = blockIdx.x * 128 + tid;
    const float* x = X + (slot >> 3) * DIM_ + (slot & 7) * SD_;
    float lg[NE_];
#pragma unroll
    for (int e = 0; e < NE_; e++) lg[e] = 0.0f;
    for (int k = 0; k < SD_; k++) {
        float xv = x[k];
        const float* wr = &Wrs[k * NE_];
#pragma unroll
        for (int e = 0; e < NE_; e++) lg[e] += xv * wr[e];
    }
    float mx = lg[0];
#pragma unroll
    for (int e = 1; e < NE_; e++) mx = fmaxf(mx, lg[e]);
    float p[NE_]; float sum = 0.0f;
#pragma unroll
    for (int e = 0; e < NE_; e++) { p[e] = expf(lg[e] - mx); sum += p[e]; }
    float inv = 1.0f / sum;
    int i0 = 0; float m0 = -1.0f;
#pragma unroll
    for (int e = 0; e < NE_; e++) if (p[e] > m0) { m0 = p[e]; i0 = e; }
    int i1 = 0; float m1 = -1.0f;
#pragma unroll
    for (int e = 0; e < NE_; e++) if (e != i0 && p[e] > m1) { m1 = p[e]; i1 = e; }
    float w0 = m0 * inv, w1 = m1 * inv;

    g_top_idx[2 * slot]     = i0;
    g_top_idx[2 * slot + 1] = i1;
    g_top_w[2 * slot]       = w0;
    g_top_w[2 * slot + 1]   = w1;

    atomicAdd(&scnt[i0], 1); atomicAdd(&scnt[i1], 1);
    atomicAdd(&sws[i0], w0); atomicAdd(&sws[i1], w1);
    __syncthreads();
    if (tid < NE_) {
        atomicAdd(&g_cnt[tid], scnt[tid]);
        atomicAdd(&g_wsum[tid], sws[tid]);
    }
}

// ---------------- offsets + aux ----------------
__global__ void offsets_kernel() {
    if (threadIdx.x == 0) {
        int acc = 0; float aux = 0.0f;
        for (int e = 0; e < NE_; e++) {
            g_off[e] = acc; g_cursor[e] = acc;
            acc += g_cnt[e];
            float f = (float)g_cnt[e] / ((float)NS_ * (float)KTOP_);
            float P = g_wsum[e] / (float)NS_;
            aux += f * P;
        }
        g_off[NE_] = acc;
        g_aux = (float)NE_ * aux;
    }
}

// ---------------- scatter ----------------
__global__ void scatter_kernel() {
    int slot = blockIdx.x * blockDim.x + threadIdx.x;
    if (slot >= NS_) return;
#pragma unroll
    for (int k = 0; k < KTOP_; k++) {
        int en = 2 * slot + k;
        int e = g_top_idx[en];
        int p = atomicAdd(&g_cursor[e], 1);
        g_perm[p] = en;
    }
}

// ---------------- combine ----------------
__global__ void combine_kernel(float* __restrict__ out, int out_size) {
    int idx = blockIdx.x * 256 + threadIdx.x;
    int c = idx & (SD_ - 1);
    int slot = idx >> 7;
    int token = slot >> 3, s = slot & 7;
    float add = g_Yent[(2 * slot) * SD_ + c] + g_Yent[(2 * slot + 1) * SD_ + c];
    out[token * DIM_ + s * SD_ + c] += add;
    if (idx == 0 && out_size > TOK_ * DIM_) out[TOK_ * DIM_] = g_aux;
}

// ---------------- launch ----------------
extern "C" void kernel_launch(void* const* d_in, const int* in_sizes, int n_in,
                              void* d_out, int out_size) {
    const float* X   = (const float*)d_in[0];
    const float* Ws1 = (const float*)d_in[1];
    const float* bs1 = (const float*)d_in[2];
    const float* Ws2 = (const float*)d_in[3];
    const float* bs2 = (const float*)d_in[4];
    const float* Wr  = (const float*)d_in[5];
    const float* We1 = (const float*)d_in[6];
    const float* be1 = (const float*)d_in[7];
    const float* We2 = (const float*)d_in[8];
    const float* be2 = (const float*)d_in[9];
    float* out = (float*)d_out;

    static cudaStream_t s2 = nullptr;
    static cudaEvent_t evFork = nullptr, evJoin = nullptr;
    if (s2 == nullptr) {
        cudaStreamCreateWithFlags(&s2, cudaStreamNonBlocking);
        cudaEventCreateWithFlags(&evFork, cudaEventDisableTiming);
        cudaEventCreateWithFlags(&evJoin, cudaEventDisableTiming);
    }

    cudaFuncSetAttribute(gemm_hmma<0>, cudaFuncAttributeMaxDynamicSharedMemorySize, GSM_BYTES);
    cudaFuncSetAttribute(gemm_hmma<1>, cudaFuncAttributeMaxDynamicSharedMemorySize, GSM_BYTES);
    cudaFuncSetAttribute(routed_hmma, cudaFuncAttributeMaxDynamicSharedMemorySize, RT2_SMEM);

    __nv_bfloat16 *Xh, *Xl, *W1h, *W1l, *W2h, *W2l, *H1h, *H1l;
    __nv_bfloat16 *E1h, *E1l, *E2h, *E2l;
    cudaGetSymbolAddress((void**)&Xh,  g_Xh);
    cudaGetSymbolAddress((void**)&Xl,  g_Xl);
    cudaGetSymbolAddress((void**)&W1h, g_W1h);
    cudaGetSymbolAddress((void**)&W1l, g_W1l);
    cudaGetSymbolAddress((void**)&W2h, g_W2h);
    cudaGetSymbolAddress((void**)&W2l, g_W2l);
    cudaGetSymbolAddress((void**)&H1h, g_H1h);
    cudaGetSymbolAddress((void**)&H1l, g_H1l);
    cudaGetSymbolAddress((void**)&E1h, g_E1h);
    cudaGetSymbolAddress((void**)&E1l, g_E1l);
    cudaGetSymbolAddress((void**)&E2h, g_E2h);
    cudaGetSymbolAddress((void**)&E2l, g_E2l);

    // ---- main stream: router chain + routed prerequisites ----
    init_kernel<<<1, 64>>>();
    router_kernel<<<NS_ / 128, 128>>>(X, Wr);
    offsets_kernel<<<1, 32>>>();
    scatter_kernel<<<NS_ / 128, 128>>>();
    split_kernel<<<(TOK_ * DIM_ / 4 + 255) / 256, 256>>>(X, Xh, Xl, TOK_ * DIM_ / 4);
    split_kernel<<<(NE_ * SD_ * HR_ / 4 + 255) / 256, 256>>>(We1, E1h, E1l, NE_ * SD_ * HR_ / 4);
    split_kernel<<<(NE_ * HR_ * SD_ / 4 + 255) / 256, 256>>>(We2, E2h, E2l, NE_ * HR_ * SD_ / 4);

    // ---- fork: routed experts on s2 ----
    cudaEventRecord(evFork, 0);
    cudaStreamWaitEvent(s2, evFork, 0);
    routed_hmma<<<dim3(NENT_ / 128, NE_), 512, RT2_SMEM, s2>>>(
        Xh, Xl, E1h, E1l, be1, E2h, E2l, be2);
    cudaEventRecord(evJoin, s2);

    // ---- main stream: shared expert ----
    split_kernel<<<(DIM_ * HSH_ / 4 + 255) / 256, 256>>>(Ws1, W1h, W1l, DIM_ * HSH_ / 4);
    split_kernel<<<(HSH_ * DIM_ / 4 + 255) / 256, 256>>>(Ws2, W2h, W2l, HSH_ * DIM_ / 4);
    gemm_hmma<0><<<dim3(HSH_ / BN_, TOK_ / BM_), 256, GSM_BYTES>>>(
        Xh, Xl, W1h, W1l, bs1, nullptr, H1h, H1l, TOK_, HSH_, DIM_);
    gemm_hmma<1><<<dim3(DIM_ / BN_, TOK_ / BM_), 256, GSM_BYTES>>>(
        H1h, H1l, W2h, W2l, bs2, out, nullptr, nullptr, TOK_, DIM_, HSH_);

    // ---- join + combine ----
    cudaStreamWaitEvent(0, evJoin, 0);
    combine_kernel<<<(NS_ * SD_) / 256, 256>>>(out, out_size);
}

// round 8
// speedup vs baseline: 5.5890x; 1.0039x over previous
#include <cuda_runtime.h>
#include <cuda_bf16.h>
#include <cstdint>

// ---------------- problem constants ----------------
#define B_ 2
#define T_ 2048
#define DIM_ 1024
#define SEG_ 8
#define SD_ 128
#define NE_ 16
#define KTOP_ 2
#define HSH_ 4096
#define HR_ 512
#define TOK_ (B_ * T_)            // 4096 tokens
#define NS_ (TOK_ * SEG_)         // 32768 token-segments
#define NENT_ (NS_ * KTOP_)       // 65536 routed entries

// ---------------- device scratch ----------------
__device__ __nv_bfloat16 g_Xh[TOK_ * DIM_];
__device__ __nv_bfloat16 g_Xl[TOK_ * DIM_];
__device__ __nv_bfloat16 g_W1h[DIM_ * HSH_];
__device__ __nv_bfloat16 g_W1l[DIM_ * HSH_];
__device__ __nv_bfloat16 g_W2h[HSH_ * DIM_];
__device__ __nv_bfloat16 g_W2l[HSH_ * DIM_];
__device__ __nv_bfloat16 g_H1h[TOK_ * HSH_];
__device__ __nv_bfloat16 g_H1l[TOK_ * HSH_];
__device__ __nv_bfloat16 g_E1h[NE_ * SD_ * HR_];
__device__ __nv_bfloat16 g_E1l[NE_ * SD_ * HR_];
__device__ __nv_bfloat16 g_E2h[NE_ * HR_ * SD_];
__device__ __nv_bfloat16 g_E2l[NE_ * HR_ * SD_];
__device__ float g_Yent[NENT_ * SD_];
__device__ int   g_top_idx[NENT_];
__device__ float g_top_w[NENT_];
__device__ int   g_cnt[NE_];
__device__ float g_wsum[NE_];
__device__ int   g_off[NE_ + 1];
__device__ int   g_cursor[NE_];
__device__ int   g_perm[NENT_];
__device__ float g_aux;

__device__ __forceinline__ float gelu_t(float x) {
    float x3 = x * x * x;
    return 0.5f * x * (1.0f + tanhf(0.7978845608028654f * (x + 0.044715f * x3)));
}

__device__ __forceinline__ uint32_t smem_u32(const void* p) {
    uint32_t a;
    asm("{ .reg .u64 t; cvta.to.shared.u64 t, %1; cvt.u32.u64 %0, t; }" : "=r"(a) : "l"(p));
    return a;
}

__device__ __forceinline__ void ldsm_x4(uint32_t r[4], uint32_t addr) {
    asm volatile("ldmatrix.sync.aligned.m8n8.x4.shared.b16 {%0,%1,%2,%3}, [%4];"
        : "=r"(r[0]), "=r"(r[1]), "=r"(r[2]), "=r"(r[3]) : "r"(addr));
}
__device__ __forceinline__ void ldsm_x4_t(uint32_t r[4], uint32_t addr) {
    asm volatile("ldmatrix.sync.aligned.m8n8.x4.trans.shared.b16 {%0,%1,%2,%3}, [%4];"
        : "=r"(r[0]), "=r"(r[1]), "=r"(r[2]), "=r"(r[3]) : "r"(addr));
}
__device__ __forceinline__ void mma_bf16(float d[4], const uint32_t a[4], const uint32_t b[2]) {
    asm volatile("mma.sync.aligned.m16n8k16.row.col.f32.bf16.bf16.f32 "
        "{%0,%1,%2,%3}, {%4,%5,%6,%7}, {%8,%9}, {%0,%1,%2,%3};"
        : "+f"(d[0]), "+f"(d[1]), "+f"(d[2]), "+f"(d[3])
        : "r"(a[0]), "r"(a[1]), "r"(a[2]), "r"(a[3]), "r"(b[0]), "r"(b[1]));
}
__device__ __forceinline__ void cp16(uint32_t s, const void* g, int szbytes) {
    asm volatile("cp.async.cg.shared.global [%0], [%1], 16, %2;"
        :: "r"(s), "l"(g), "r"(szbytes));
}
__device__ __forceinline__ void cp_commit() { asm volatile("cp.async.commit_group;" ::: "memory"); }
__device__ __forceinline__ void cp_wait0()  { asm volatile("cp.async.wait_group 0;" ::: "memory"); }
__device__ __forceinline__ void cp_wait2()  { asm volatile("cp.async.wait_group 2;" ::: "memory"); }

// ---------------- split-precision conversion ----------------
__global__ void split_kernel(const float* __restrict__ src,
                             __nv_bfloat16* __restrict__ h,
                             __nv_bfloat16* __restrict__ l, int n4) {
    int i = blockIdx.x * 256 + threadIdx.x;
    if (i >= n4) return;
    float4 v = ((const float4*)src)[i];
    float vs[4] = {v.x, v.y, v.z, v.w};
    __nv_bfloat16 hh[4], ll[4];
#pragma unroll
    for (int j = 0; j < 4; j++) {
        hh[j] = __float2bfloat16(vs[j]);
        ll[j] = __float2bfloat16(vs[j] - __bfloat162float(hh[j]));
    }
    ((__nv_bfloat162*)h)[2 * i]     = __nv_bfloat162(hh[0], hh[1]);
    ((__nv_bfloat162*)h)[2 * i + 1] = __nv_bfloat162(hh[2], hh[3]);
    ((__nv_bfloat162*)l)[2 * i]     = __nv_bfloat162(ll[0], ll[1]);
    ((__nv_bfloat162*)l)[2 * i + 1] = __nv_bfloat162(ll[2], ll[3]);
}

// ---------------- HMMA split-bf16 GEMM, 3-stage cp.async pipeline ----------------
// C[M,N] = A[M,K] @ B[K,N]
// MODE 0: epilogue gelu(acc+bias) -> (Ch, Cl) bf16 split pair
// MODE 1: epilogue acc+bias -> Cf fp32
#define BM_ 128
#define BN_ 128
#define BK_ 64
#define ASTR_ 72
#define BSTR_ 136
// per-stage: sAh @0 (128x72 el), sAl @18432B, sBh @36864B (64x136 el), sBl @54272B
#define STG_BYTES 71680
#define GSM_BYTES (3 * STG_BYTES)

template <int MODE>
__global__ void __launch_bounds__(256)
gemm_hmma(const __nv_bfloat16* __restrict__ Ah, const __nv_bfloat16* __restrict__ Al,
          const __nv_bfloat16* __restrict__ Bh, const __nv_bfloat16* __restrict__ Bl,
          const float* __restrict__ bias,
          float* __restrict__ Cf,
          __nv_bfloat16* __restrict__ Ch, __nv_bfloat16* __restrict__ Cl,
          int M, int N, int K) {
    extern __shared__ char smraw[];

    int tid = threadIdx.x;
    int wid = tid >> 5, lane = tid & 31;
    int wm = wid & 1, wn = wid >> 1;
    int bn = blockIdx.x * BN_, bm = blockIdx.y * BM_;

    uint32_t uS = smem_u32(smraw);

    float acc[4][4][4];
#pragma unroll
    for (int i = 0; i < 4; i++)
#pragma unroll
        for (int j = 0; j < 4; j++)
#pragma unroll
            for (int q = 0; q < 4; q++) acc[i][j][q] = 0.0f;

    int lo16 = lane & 15, hi16 = lane >> 4;

    auto load_chunk = [&](int kc, int st) {
        uint32_t bAh = uS + st * STG_BYTES;
        uint32_t bAl = bAh + 18432;
        uint32_t bBh = bAh + 36864;
        uint32_t bBl = bAh + 54272;
#pragma unroll 2
        for (int i = tid; i < 1024; i += 256) {
            int r = i >> 3, u = i & 7;
            int g = (bm + r) * K + kc + u * 8;
            uint32_t so = (uint32_t)(r * ASTR_ + u * 8) * 2;
            cp16(bAh + so, Ah + g, 16);
            cp16(bAl + so, Al + g, 16);
        }
#pragma unroll 2
        for (int i = tid; i < 1024; i += 256) {
            int r = i >> 4, u = i & 15;
            int g = (kc + r) * N + bn + u * 8;
            uint32_t so = (uint32_t)(r * BSTR_ + u * 8) * 2;
            cp16(bBh + so, Bh + g, 16);
            cp16(bBl + so, Bl + g, 16);
        }
    };

    int nch = K / BK_;
    load_chunk(0, 0);
    cp_commit();
    load_chunk(BK_, 1);
    cp_commit();

    for (int c = 0; c < nch; c++) {
        int st = c % 3;
        if (c + 2 < nch) load_chunk((c + 2) * BK_, (c + 2) % 3);
        cp_commit();
        cp_wait2();
        __syncthreads();

        uint32_t uAh = uS + st * STG_BYTES;
        uint32_t uAl = uAh + 18432;
        uint32_t uBh = uAh + 36864;
        uint32_t uBl = uAh + 54272;

#pragma unroll
        for (int ks = 0; ks < 4; ks++) {
            int k0 = ks * 16;
            uint32_t Bfh[4][2], Bfl[4][2];
#pragma unroll
            for (int p = 0; p < 2; p++) {
                uint32_t boff = (uint32_t)(((k0 + lo16) * BSTR_ + wn * 32 + p * 16 + 8 * hi16) * 2);
                uint32_t r4[4];
                ldsm_x4_t(r4, uBh + boff);
                Bfh[p * 2][0] = r4[0]; Bfh[p * 2][1] = r4[1];
                Bfh[p * 2 + 1][0] = r4[2]; Bfh[p * 2 + 1][1] = r4[3];
                ldsm_x4_t(r4, uBl + boff);
                Bfl[p * 2][0] = r4[0]; Bfl[p * 2][1] = r4[1];
                Bfl[p * 2 + 1][0] = r4[2]; Bfl[p * 2 + 1][1] = r4[3];
            }
            uint32_t Afh[4][4], Afl[4][4];
#pragma unroll
            for (int mt = 0; mt < 4; mt++) {
                uint32_t aoff = (uint32_t)(((wm * 64 + mt * 16 + lo16) * ASTR_ + k0 + 8 * hi16) * 2);
                ldsm_x4(Afh[mt], uAh + aoff);
                ldsm_x4(Afl[mt], uAl + aoff);
            }
            // term-outer: 16 independent MMAs between accumulator reuses
#pragma unroll
            for (int mt = 0; mt < 4; mt++)
#pragma unroll
                for (int nt = 0; nt < 4; nt++) mma_bf16(acc[mt][nt], Afh[mt], Bfh[nt]);
#pragma unroll
            for (int mt = 0; mt < 4; mt++)
#pragma unroll
                for (int nt = 0; nt < 4; nt++) mma_bf16(acc[mt][nt], Afh[mt], Bfl[nt]);
#pragma unroll
            for (int mt = 0; mt < 4; mt++)
#pragma unroll
                for (int nt = 0; nt < 4; nt++) mma_bf16(acc[mt][nt], Afl[mt], Bfh[nt]);
        }
        __syncthreads();
    }

    int row_in = lane >> 2, colq = (lane & 3) * 2;
#pragma unroll
    for (int mt = 0; mt < 4; mt++) {
#pragma unroll
        for (int nt = 0; nt < 4; nt++) {
            int m0 = bm + wm * 64 + mt * 16 + row_in;
            int n0 = bn + wn * 32 + nt * 8 + colq;
            float b0 = bias[n0], b1 = bias[n0 + 1];
            float v00 = acc[mt][nt][0] + b0, v01 = acc[mt][nt][1] + b1;
            float v10 = acc[mt][nt][2] + b0, v11 = acc[mt][nt][3] + b1;
            if (MODE == 0) {
                float g00 = gelu_t(v00), g01 = gelu_t(v01);
                float g10 = gelu_t(v10), g11 = gelu_t(v11);
                __nv_bfloat16 h00 = __float2bfloat16(g00), h01 = __float2bfloat16(g01);
                __nv_bfloat16 h10 = __float2bfloat16(g10), h11 = __float2bfloat16(g11);
                __nv_bfloat16 l00 = __float2bfloat16(g00 - __bfloat162float(h00));
                __nv_bfloat16 l01 = __float2bfloat16(g01 - __bfloat162float(h01));
                __nv_bfloat16 l10 = __float2bfloat16(g10 - __bfloat162float(h10));
                __nv_bfloat16 l11 = __float2bfloat16(g11 - __bfloat162float(h11));
                *(__nv_bfloat162*)(Ch + m0 * N + n0)       = __nv_bfloat162(h00, h01);
                *(__nv_bfloat162*)(Ch + (m0 + 8) * N + n0) = __nv_bfloat162(h10, h11);
                *(__nv_bfloat162*)(Cl + m0 * N + n0)       = __nv_bfloat162(l00, l01);
                *(__nv_bfloat162*)(Cl + (m0 + 8) * N + n0) = __nv_bfloat162(l10, l11);
            } else {
                *(float2*)(Cf + m0 * N + n0)       = make_float2(v00, v01);
                *(float2*)(Cf + (m0 + 8) * N + n0) = make_float2(v10, v11);
            }
        }
    }
}

// ---------------- routed experts: 512 threads, cp.async pipelined ----------------
#define RT2_SMEM (90112 * 2)

__global__ void __launch_bounds__(512)
routed_hmma(const __nv_bfloat16* __restrict__ Xh, const __nv_bfloat16* __restrict__ Xl,
            const __nv_bfloat16* __restrict__ E1h, const __nv_bfloat16* __restrict__ E1l,
            const float* __restrict__ be1,
            const __nv_bfloat16* __restrict__ E2h, const __nv_bfloat16* __restrict__ E2l,
            const float* __restrict__ be2) {
    extern __shared__ __nv_bfloat16 sm2[];
    __shared__ int   s_entry[128];
    __shared__ float s_w[128];

    int tid = threadIdx.x, wid = tid >> 5, lane = tid & 31;
    int e = blockIdx.y;
    int base = g_off[e] + blockIdx.x * 128;
    int end  = g_off[e + 1];
    if (base >= end) return;

    __nv_bfloat16* sHh = sm2 + 34816;
    __nv_bfloat16* sHl = sm2 + 44032;

    uint32_t uS  = smem_u32(sm2);
    uint32_t uXh = uS, uXl = uS + 17408 * 2;
    uint32_t uHh = uS + 34816 * 2, uHl = uS + 44032 * 2;
    uint32_t uW1h = uS + 53248 * 2, uW1l = uS + 62464 * 2;
    uint32_t uW2h = uS + 71680 * 2, uW2l = uS + 80896 * 2;

    for (int i = tid; i < 128; i += 512) {
        int p = base + i;
        if (p < end) {
            int en = g_perm[p];
            s_entry[i] = en;
            s_w[i] = g_top_w[en];
        } else {
            s_entry[i] = -1;
            s_w[i] = 0.0f;
        }
    }
    __syncthreads();

    const __nv_bfloat16* W1h = E1h + e * (SD_ * HR_);
    const __nv_bfloat16* W1l = E1l + e * (SD_ * HR_);
    const __nv_bfloat16* W2h = E2h + e * (HR_ * SD_);
    const __nv_bfloat16* W2l = E2l + e * (HR_ * SD_);
    const float* b1 = be1 + e * HR_;
    const float* b2 = be2 + e * SD_;

    // X gather via cp.async (zero-fill masked rows)
    for (int i = tid; i < 2048; i += 512) {
        int row = i >> 4, u = i & 15;
        int en = s_entry[row];
        int sz = (en >= 0) ? 16 : 0;
        int slot = en >> 1;
        long goff = (en >= 0) ? ((long)(slot >> 3) * DIM_ + (slot & 7) * SD_ + u * 8) : 0;
        uint32_t so = (uint32_t)(row * 136 + u * 8) * 2;
        cp16(uXh + so, Xh + goff, sz);
        cp16(uXl + so, Xl + goff, sz);
    }
    // W1 chunk 0
    for (int i = tid; i < 2048; i += 512) {
        int hl = i >> 10, j = i & 1023;
        int k = j >> 3, u = j & 7;
        const __nv_bfloat16* src = (hl ? W1l : W1h) + k * HR_ + u * 8;
        uint32_t so = (hl ? uW1l : uW1h) + (uint32_t)(k * 72 + u * 8) * 2;
        cp16(so, src, 16);
    }
    cp_commit();
    cp_wait0();
    __syncthreads();

    int wm = wid & 3, wn = wid >> 2;
    int lo16 = lane & 15, hi16 = lane >> 4;
    int row_in = lane >> 2, colq = (lane & 3) * 2;

    float yacc[2][4][4];
#pragma unroll
    for (int i = 0; i < 2; i++)
#pragma unroll
        for (int j = 0; j < 4; j++)
#pragma unroll
            for (int q = 0; q < 4; q++) yacc[i][j][q] = 0.0f;

    for (int ch = 0; ch < 8; ch++) {
        int h0 = ch * 64;

        // prefetch W2[ch] during GEMM1
        for (int i = tid; i < 2048; i += 512) {
            int hl = i >> 10, j = i & 1023;
            int k = j >> 4, u = j & 15;
            const __nv_bfloat16* src = (hl ? W2l : W2h) + (h0 + k) * SD_ + u * 8;
            uint32_t so = (hl ? uW2l : uW2h) + (uint32_t)(k * 136 + u * 8) * 2;
            cp16(so, src, 16);
        }
        cp_commit();

        // GEMM1: H = X @ W1[ch]  (M=128, N=64, K=128)
        float hacc[2][2][4];
#pragma unroll
        for (int i = 0; i < 2; i++)
#pragma unroll
            for (int j = 0; j < 2; j++)
#pragma unroll
                for (int q = 0; q < 4; q++) hacc[i][j][q] = 0.0f;

#pragma unroll
        for (int ks = 0; ks < 8; ks++) {
            int k0 = ks * 16;
            uint32_t boff = (uint32_t)(((k0 + lo16) * 72 + wn * 16 + 8 * hi16) * 2);
            uint32_t Bfh[2][2], Bfl[2][2], r4[4];
            ldsm_x4_t(r4, uW1h + boff);
            Bfh[0][0] = r4[0]; Bfh[0][1] = r4[1]; Bfh[1][0] = r4[2]; Bfh[1][1] = r4[3];
            ldsm_x4_t(r4, uW1l + boff);
            Bfl[0][0] = r4[0]; Bfl[0][1] = r4[1]; Bfl[1][0] = r4[2]; Bfl[1][1] = r4[3];
            uint32_t Afh[2][4], Afl[2][4];
#pragma unroll
            for (int mt = 0; mt < 2; mt++) {
                uint32_t aoff = (uint32_t)(((wm * 32 + mt * 16 + lo16) * 136 + k0 + 8 * hi16) * 2);
                ldsm_x4(Afh[mt], uXh + aoff);
                ldsm_x4(Afl[mt], uXl + aoff);
            }
#pragma unroll
            for (int mt = 0; mt < 2; mt++)
#pragma unroll
                for (int nt = 0; nt < 2; nt++) mma_bf16(hacc[mt][nt], Afh[mt], Bfh[nt]);
#pragma unroll
            for (int mt = 0; mt < 2; mt++)
#pragma unroll
                for (int nt = 0; nt < 2; nt++) mma_bf16(hacc[mt][nt], Afh[mt], Bfl[nt]);
#pragma unroll
            for (int mt = 0; mt < 2; mt++)
#pragma unroll
                for (int nt = 0; nt < 2; nt++) mma_bf16(hacc[mt][nt], Afl[mt], Bfh[nt]);
        }

        // H epilogue: gelu(bias+acc) -> split pair into sH
#pragma unroll
        for (int mt = 0; mt < 2; mt++) {
#pragma unroll
            for (int nt = 0; nt < 2; nt++) {
                int n0 = wn * 16 + nt * 8 + colq;
                float bb0 = b1[h0 + n0], bb1 = b1[h0 + n0 + 1];
                float g00 = gelu_t(hacc[mt][nt][0] + bb0);
                float g01 = gelu_t(hacc[mt][nt][1] + bb1);
                float g10 = gelu_t(hacc[mt][nt][2] + bb0);
                float g11 = gelu_t(hacc[mt][nt][3] + bb1);
                __nv_bfloat16 h00 = __float2bfloat16(g00), h01 = __float2bfloat16(g01);
                __nv_bfloat16 h10 = __float2bfloat16(g10), h11 = __float2bfloat16(g11);
                __nv_bfloat16 l00 = __float2bfloat16(g00 - __bfloat162float(h00));
                __nv_bfloat16 l01 = __float2bfloat16(g01 - __bfloat162float(h01));
                __nv_bfloat16 l10 = __float2bfloat16(g10 - __bfloat162float(h10));
                __nv_bfloat16 l11 = __float2bfloat16(g11 - __bfloat162float(h11));
                int r0 = wm * 32 + mt * 16 + row_in;
                *(__nv_bfloat162*)(sHh + r0 * 72 + n0)       = __nv_bfloat162(h00, h01);
                *(__nv_bfloat162*)(sHh + (r0 + 8) * 72 + n0) = __nv_bfloat162(h10, h11);
                *(__nv_bfloat162*)(sHl + r0 * 72 + n0)       = __nv_bfloat162(l00, l01);
                *(__nv_bfloat162*)(sHl + (r0 + 8) * 72 + n0) = __nv_bfloat162(l10, l11);
            }
        }
        cp_wait0();
        __syncthreads();

        // prefetch W1[ch+1] during GEMM2
        if (ch < 7) {
            int h1 = h0 + 64;
            for (int i = tid; i < 2048; i += 512) {
                int hl = i >> 10, j = i & 1023;
                int k = j >> 3, u = j & 7;
                const __nv_bfloat16* src = (hl ? W1l : W1h) + k * HR_ + h1 + u * 8;
                uint32_t so = (hl ? uW1l : uW1h) + (uint32_t)(k * 72 + u * 8) * 2;
                cp16(so, src, 16);
            }
        }
        cp_commit();

        // GEMM2: Y += H @ W2[ch]  (M=128, N=128, K=64)
#pragma unroll
        for (int ks = 0; ks < 4; ks++) {
            int k0 = ks * 16;
            uint32_t Bfh[4][2], Bfl[4][2];
#pragma unroll
            for (int p = 0; p < 2; p++) {
                uint32_t boff = (uint32_t)(((k0 + lo16) * 136 + wn * 32 + p * 16 + 8 * hi16) * 2);
                uint32_t r4[4];
                ldsm_x4_t(r4, uW2h + boff);
                Bfh[p * 2][0] = r4[0]; Bfh[p * 2][1] = r4[1];
                Bfh[p * 2 + 1][0] = r4[2]; Bfh[p * 2 + 1][1] = r4[3];
                ldsm_x4_t(r4, uW2l + boff);
                Bfl[p * 2][0] = r4[0]; Bfl[p * 2][1] = r4[1];
                Bfl[p * 2 + 1][0] = r4[2]; Bfl[p * 2 + 1][1] = r4[3];
            }
            uint32_t Afh[2][4], Afl[2][4];
#pragma unroll
            for (int mt = 0; mt < 2; mt++) {
                uint32_t aoff = (uint32_t)(((wm * 32 + mt * 16 + lo16) * 72 + k0 + 8 * hi16) * 2);
                ldsm_x4(Afh[mt], uHh + aoff);
                ldsm_x4(Afl[mt], uHl + aoff);
            }
#pragma unroll
            for (int mt = 0; mt < 2; mt++)
#pragma unroll
                for (int nt = 0; nt < 4; nt++) mma_bf16(yacc[mt][nt], Afh[mt], Bfh[nt]);
#pragma unroll
            for (int mt = 0; mt < 2; mt++)
#pragma unroll
                for (int nt = 0; nt < 4; nt++) mma_bf16(yacc[mt][nt], Afh[mt], Bfl[nt]);
#pragma unroll
            for (int mt = 0; mt < 2; mt++)
#pragma unroll
                for (int nt = 0; nt < 4; nt++) mma_bf16(yacc[mt][nt], Afl[mt], Bfh[nt]);
        }
        cp_wait0();
        __syncthreads();
    }

    // epilogue: g_Yent[entry] = w * (y + b2)
#pragma unroll
    for (int mt = 0; mt < 2; mt++) {
#pragma unroll
        for (int nt = 0; nt < 4; nt++) {
            int n0 = wn * 32 + nt * 8 + colq;
            float bb0 = b2[n0], bb1 = b2[n0 + 1];
            int r0 = wm * 32 + mt * 16 + row_in;
            int en0 = s_entry[r0];
            if (en0 >= 0) {
                float w = s_w[r0];
                *(float2*)(g_Yent + en0 * SD_ + n0) =
                    make_float2(w * (yacc[mt][nt][0] + bb0), w * (yacc[mt][nt][1] + bb1));
            }
            int en1 = s_entry[r0 + 8];
            if (en1 >= 0) {
                float w = s_w[r0 + 8];
                *(float2*)(g_Yent + en1 * SD_ + n0) =
                    make_float2(w * (yacc[mt][nt][2] + bb0), w * (yacc[mt][nt][3] + bb1));
            }
        }
    }
}

// ---------------- init ----------------
__global__ void init_kernel() {
    int t = threadIdx.x;
    if (t < NE_) { g_cnt[t] = 0; g_wsum[t] = 0.0f; }
}

// ---------------- router ----------------
__global__ void router_kernel(const float* __restrict__ X, const float* __restrict__ Wr) {
    __shared__ float Wrs[SD_ * NE_];
    __shared__ int   scnt[NE_];
    __shared__ float sws[NE_];
    int tid = threadIdx.x;
    for (int i = tid; i < SD_ * NE_; i += 128) Wrs[i] = Wr[i];
    if (tid < NE_) { scnt[tid] = 0; sws[tid] = 0.0f; }
    __syncthreads();

    int slot = blockIdx.x * 128 + tid;
    const float* x = X + (slot >> 3) * DIM_ + (slot & 7) * SD_;
    float lg[NE_];
#pragma unroll
    for (int e = 0; e < NE_; e++) lg[e] = 0.0f;
    for (int k = 0; k < SD_; k++) {
        float xv = x[k];
        const float* wr = &Wrs[k * NE_];
#pragma unroll
        for (int e = 0; e < NE_; e++) lg[e] += xv * wr[e];
    }
    float mx = lg[0];
#pragma unroll
    for (int e = 1; e < NE_; e++) mx = fmaxf(mx, lg[e]);
    float p[NE_]; float sum = 0.0f;
#pragma unroll
    for (int e = 0; e < NE_; e++) { p[e] = expf(lg[e] - mx); sum += p[e]; }
    float inv = 1.0f / sum;
    int i0 = 0; float m0 = -1.0f;
#pragma unroll
    for (int e = 0; e < NE_; e++) if (p[e] > m0) { m0 = p[e]; i0 = e; }
    int i1 = 0; float m1 = -1.0f;
#pragma unroll
    for (int e = 0; e < NE_; e++) if (e != i0 && p[e] > m1) { m1 = p[e]; i1 = e; }
    float w0 = m0 * inv, w1 = m1 * inv;

    g_top_idx[2 * slot]     = i0;
    g_top_idx[2 * slot + 1] = i1;
    g_top_w[2 * slot]       = w0;
    g_top_w[2 * slot + 1]   = w1;

    atomicAdd(&scnt[i0], 1); atomicAdd(&scnt[i1], 1);
    atomicAdd(&sws[i0], w0); atomicAdd(&sws[i1], w1);
    __syncthreads();
    if (tid < NE_) {
        atomicAdd(&g_cnt[tid], scnt[tid]);
        atomicAdd(&g_wsum[tid], sws[tid]);
    }
}

// ---------------- offsets + aux ----------------
__global__ void offsets_kernel() {
    if (threadIdx.x == 0) {
        int acc = 0; float aux = 0.0f;
        for (int e = 0; e < NE_; e++) {
            g_off[e] = acc; g_cursor[e] = acc;
            acc += g_cnt[e];
            float f = (float)g_cnt[e] / ((float)NS_ * (float)KTOP_);
            float P = g_wsum[e] / (float)NS_;
            aux += f * P;
        }
        g_off[NE_] = acc;
        g_aux = (float)NE_ * aux;
    }
}

// ---------------- scatter ----------------
__global__ void scatter_kernel() {
    int slot = blockIdx.x * blockDim.x + threadIdx.x;
    if (slot >= NS_) return;
#pragma unroll
    for (int k = 0; k < KTOP_; k++) {
        int en = 2 * slot + k;
        int e = g_top_idx[en];
        int p = atomicAdd(&g_cursor[e], 1);
        g_perm[p] = en;
    }
}

// ---------------- combine ----------------
__global__ void combine_kernel(float* __restrict__ out, int out_size) {
    int idx = blockIdx.x * 256 + threadIdx.x;
    int c = idx & (SD_ - 1);
    int slot = idx >> 7;
    int token = slot >> 3, s = slot & 7;
    float add = g_Yent[(2 * slot) * SD_ + c] + g_Yent[(2 * slot + 1) * SD_ + c];
    out[token * DIM_ + s * SD_ + c] += add;
    if (idx == 0 && out_size > TOK_ * DIM_) out[TOK_ * DIM_] = g_aux;
}

// ---------------- launch ----------------
extern "C" void kernel_launch(void* const* d_in, const int* in_sizes, int n_in,
                              void* d_out, int out_size) {
    const float* X   = (const float*)d_in[0];
    const float* Ws1 = (const float*)d_in[1];
    const float* bs1 = (const float*)d_in[2];
    const float* Ws2 = (const float*)d_in[3];
    const float* bs2 = (const float*)d_in[4];
    const float* Wr  = (const float*)d_in[5];
    const float* We1 = (const float*)d_in[6];
    const float* be1 = (const float*)d_in[7];
    const float* We2 = (const float*)d_in[8];
    const float* be2 = (const float*)d_in[9];
    float* out = (float*)d_out;

    static cudaStream_t s2 = nullptr;
    static cudaEvent_t evStart = nullptr, evScatter = nullptr, evX = nullptr, evJoin = nullptr;
    if (s2 == nullptr) {
        cudaStreamCreateWithFlags(&s2, cudaStreamNonBlocking);
        cudaEventCreateWithFlags(&evStart,   cudaEventDisableTiming);
        cudaEventCreateWithFlags(&evScatter, cudaEventDisableTiming);
        cudaEventCreateWithFlags(&evX,       cudaEventDisableTiming);
        cudaEventCreateWithFlags(&evJoin,    cudaEventDisableTiming);
    }

    cudaFuncSetAttribute(gemm_hmma<0>, cudaFuncAttributeMaxDynamicSharedMemorySize, GSM_BYTES);
    cudaFuncSetAttribute(gemm_hmma<1>, cudaFuncAttributeMaxDynamicSharedMemorySize, GSM_BYTES);
    cudaFuncSetAttribute(routed_hmma, cudaFuncAttributeMaxDynamicSharedMemorySize, RT2_SMEM);

    __nv_bfloat16 *Xh, *Xl, *W1h, *W1l, *W2h, *W2l, *H1h, *H1l;
    __nv_bfloat16 *E1h, *E1l, *E2h, *E2l;
    cudaGetSymbolAddress((void**)&Xh,  g_Xh);
    cudaGetSymbolAddress((void**)&Xl,  g_Xl);
    cudaGetSymbolAddress((void**)&W1h, g_W1h);
    cudaGetSymbolAddress((void**)&W1l, g_W1l);
    cudaGetSymbolAddress((void**)&W2h, g_W2h);
    cudaGetSymbolAddress((void**)&W2l, g_W2l);
    cudaGetSymbolAddress((void**)&H1h, g_H1h);
    cudaGetSymbolAddress((void**)&H1l, g_H1l);
    cudaGetSymbolAddress((void**)&E1h, g_E1h);
    cudaGetSymbolAddress((void**)&E1l, g_E1l);
    cudaGetSymbolAddress((void**)&E2h, g_E2h);
    cudaGetSymbolAddress((void**)&E2l, g_E2l);

    // ---- fork immediately: splits on s2 concurrent with router chain on main ----
    cudaEventRecord(evStart, 0);
    cudaStreamWaitEvent(s2, evStart, 0);

    // s2: routed prerequisites (independent of router chain)
    split_kernel<<<(TOK_ * DIM_ / 4 + 255) / 256, 256, 0, s2>>>(X, Xh, Xl, TOK_ * DIM_ / 4);
    cudaEventRecord(evX, s2);
    split_kernel<<<(NE_ * SD_ * HR_ / 4 + 255) / 256, 256, 0, s2>>>(We1, E1h, E1l, NE_ * SD_ * HR_ / 4);
    split_kernel<<<(NE_ * HR_ * SD_ / 4 + 255) / 256, 256, 0, s2>>>(We2, E2h, E2l, NE_ * HR_ * SD_ / 4);

    // main: router chain
    init_kernel<<<1, 64>>>();
    router_kernel<<<NS_ / 128, 128>>>(X, Wr);
    offsets_kernel<<<1, 32>>>();
    scatter_kernel<<<NS_ / 128, 128>>>();
    cudaEventRecord(evScatter, 0);

    // s2: routed experts (needs its splits + scatter)
    cudaStreamWaitEvent(s2, evScatter, 0);
    routed_hmma<<<dim3(NENT_ / 128, NE_), 512, RT2_SMEM, s2>>>(
        Xh, Xl, E1h, E1l, be1, E2h, E2l, be2);
    cudaEventRecord(evJoin, s2);

    // main: shared expert (needs W splits + X split from s2)
    split_kernel<<<(DIM_ * HSH_ / 4 + 255) / 256, 256>>>(Ws1, W1h, W1l, DIM_ * HSH_ / 4);
    split_kernel<<<(HSH_ * DIM_ / 4 + 255) / 256, 256>>>(Ws2, W2h, W2l, HSH_ * DIM_ / 4);
    cudaStreamWaitEvent(0, evX, 0);
    gemm_hmma<0><<<dim3(HSH_ / BN_, TOK_ / BM_), 256, GSM_BYTES>>>(
        Xh, Xl, W1h, W1l, bs1, nullptr, H1h, H1l, TOK_, HSH_, DIM_);
    gemm_hmma<1><<<dim3(DIM_ / BN_, TOK_ / BM_), 256, GSM_BYTES>>>(
        H1h, H1l, W2h, W2l, bs2, out, nullptr, nullptr, TOK_, DIM_, HSH_);

    // ---- join + combine ----
    cudaStreamWaitEvent(0, evJoin, 0);
    combine_kernel<<<(NS_ * SD_) / 256, 256>>>(out, out_size);
}

// round 9
// speedup vs baseline: 12.3998x; 2.2186x over previous
#include <cuda_runtime.h>
#include <cuda_fp16.h>
#include <cstdint>

// ---------------- problem constants ----------------
#define B_ 2
#define T_ 2048
#define DIM_ 1024
#define SEG_ 8
#define SD_ 128
#define NE_ 16
#define KTOP_ 2
#define HSH_ 4096
#define HR_ 512
#define TOK_ (B_ * T_)            // 4096 tokens
#define NS_ (TOK_ * SEG_)         // 32768 token-segments
#define NENT_ (NS_ * KTOP_)       // 65536 routed entries

// ---------------- device scratch ----------------
__device__ __half g_Xc[TOK_ * DIM_];
__device__ __half g_W1c[DIM_ * HSH_];
__device__ __half g_W2c[HSH_ * DIM_];
__device__ __half g_H1c[TOK_ * HSH_];
__device__ __half g_E1c[NE_ * SD_ * HR_];
__device__ __half g_E2c[NE_ * HR_ * SD_];
__device__ float g_Yent[NENT_ * SD_];
__device__ int   g_top_idx[NENT_];
__device__ float g_top_w[NENT_];
__device__ int   g_cnt[NE_];
__device__ float g_wsum[NE_];
__device__ int   g_off[NE_ + 1];
__device__ int   g_cursor[NE_];
__device__ int   g_perm[NENT_];
__device__ float g_aux;

__device__ __forceinline__ float gelu_t(float x) {
    float x3 = x * x * x;
    return 0.5f * x * (1.0f + tanhf(0.7978845608028654f * (x + 0.044715f * x3)));
}

__device__ __forceinline__ uint32_t smem_u32(const void* p) {
    uint32_t a;
    asm("{ .reg .u64 t; cvta.to.shared.u64 t, %1; cvt.u32.u64 %0, t; }" : "=r"(a) : "l"(p));
    return a;
}

__device__ __forceinline__ void ldsm_x4(uint32_t r[4], uint32_t addr) {
    asm volatile("ldmatrix.sync.aligned.m8n8.x4.shared.b16 {%0,%1,%2,%3}, [%4];"
        : "=r"(r[0]), "=r"(r[1]), "=r"(r[2]), "=r"(r[3]) : "r"(addr));
}
__device__ __forceinline__ void ldsm_x4_t(uint32_t r[4], uint32_t addr) {
    asm volatile("ldmatrix.sync.aligned.m8n8.x4.trans.shared.b16 {%0,%1,%2,%3}, [%4];"
        : "=r"(r[0]), "=r"(r[1]), "=r"(r[2]), "=r"(r[3]) : "r"(addr));
}
__device__ __forceinline__ void mma_f16(float d[4], const uint32_t a[4], const uint32_t b[2]) {
    asm volatile("mma.sync.aligned.m16n8k16.row.col.f32.f16.f16.f32 "
        "{%0,%1,%2,%3}, {%4,%5,%6,%7}, {%8,%9}, {%0,%1,%2,%3};"
        : "+f"(d[0]), "+f"(d[1]), "+f"(d[2]), "+f"(d[3])
        : "r"(a[0]), "r"(a[1]), "r"(a[2]), "r"(a[3]), "r"(b[0]), "r"(b[1]));
}
__device__ __forceinline__ void cp16(uint32_t s, const void* g, int szbytes) {
    asm volatile("cp.async.cg.shared.global [%0], [%1], 16, %2;"
        :: "r"(s), "l"(g), "r"(szbytes));
}
__device__ __forceinline__ void cp_commit() { asm volatile("cp.async.commit_group;" ::: "memory"); }
__device__ __forceinline__ void cp_wait0()  { asm volatile("cp.async.wait_group 0;" ::: "memory"); }
__device__ __forceinline__ void cp_wait2()  { asm volatile("cp.async.wait_group 2;" ::: "memory"); }

// ---------------- fp32 -> fp16 conversion ----------------
__global__ void cvt_kernel(const float* __restrict__ src, __half* __restrict__ dst, int n4) {
    int i = blockIdx.x * 256 + threadIdx.x;
    if (i >= n4) return;
    float4 v = ((const float4*)src)[i];
    ((__half2*)dst)[2 * i]     = __floats2half2_rn(v.x, v.y);
    ((__half2*)dst)[2 * i + 1] = __floats2half2_rn(v.z, v.w);
}

// ---------------- HMMA fp16 GEMM, 3-stage cp.async pipeline, occ=2 ----------------
// C[M,N] = A[M,K] @ B[K,N]
// MODE 0: epilogue gelu(acc+bias) -> Ch fp16
// MODE 1: epilogue acc+bias -> Cf fp32
#define BM_ 128
#define BN_ 128
#define BK_ 64
#define ASTR_ 72
#define BSTR_ 136
// per-stage: sA @0 (128x72 el = 18432B), sB @18432B (64x136 el = 17408B)
#define STG_BYTES 35840
#define GSM_BYTES (3 * STG_BYTES)

template <int MODE>
__global__ void __launch_bounds__(256, 2)
gemm_hmma(const __half* __restrict__ A, const __half* __restrict__ Bm,
          const float* __restrict__ bias,
          float* __restrict__ Cf, __half* __restrict__ Ch,
          int M, int N, int K) {
    extern __shared__ char smraw[];

    int tid = threadIdx.x;
    int wid = tid >> 5, lane = tid & 31;
    int wm = wid & 1, wn = wid >> 1;
    int bn = blockIdx.x * BN_, bm = blockIdx.y * BM_;

    uint32_t uS = smem_u32(smraw);

    float acc[4][4][4];
#pragma unroll
    for (int i = 0; i < 4; i++)
#pragma unroll
        for (int j = 0; j < 4; j++)
#pragma unroll
            for (int q = 0; q < 4; q++) acc[i][j][q] = 0.0f;

    int lo16 = lane & 15, hi16 = lane >> 4;

    auto load_chunk = [&](int kc, int st) {
        uint32_t bA = uS + st * STG_BYTES;
        uint32_t bB = bA + 18432;
#pragma unroll 2
        for (int i = tid; i < 1024; i += 256) {
            int r = i >> 3, u = i & 7;
            int g = (bm + r) * K + kc + u * 8;
            cp16(bA + (uint32_t)(r * ASTR_ + u * 8) * 2, A + g, 16);
        }
#pragma unroll 2
        for (int i = tid; i < 1024; i += 256) {
            int r = i >> 4, u = i & 15;
            int g = (kc + r) * N + bn + u * 8;
            cp16(bB + (uint32_t)(r * BSTR_ + u * 8) * 2, Bm + g, 16);
        }
    };

    int nch = K / BK_;
    load_chunk(0, 0);
    cp_commit();
    load_chunk(BK_, 1);
    cp_commit();

    for (int c = 0; c < nch; c++) {
        int st = c % 3;
        if (c + 2 < nch) load_chunk((c + 2) * BK_, (c + 2) % 3);
        cp_commit();
        cp_wait2();
        __syncthreads();

        uint32_t uA = uS + st * STG_BYTES;
        uint32_t uB = uA + 18432;

#pragma unroll
        for (int ks = 0; ks < 4; ks++) {
            int k0 = ks * 16;
            uint32_t Bf[4][2];
#pragma unroll
            for (int p = 0; p < 2; p++) {
                uint32_t boff = (uint32_t)(((k0 + lo16) * BSTR_ + wn * 32 + p * 16 + 8 * hi16) * 2);
                uint32_t r4[4];
                ldsm_x4_t(r4, uB + boff);
                Bf[p * 2][0] = r4[0]; Bf[p * 2][1] = r4[1];
                Bf[p * 2 + 1][0] = r4[2]; Bf[p * 2 + 1][1] = r4[3];
            }
            uint32_t Af[4][4];
#pragma unroll
            for (int mt = 0; mt < 4; mt++) {
                uint32_t aoff = (uint32_t)(((wm * 64 + mt * 16 + lo16) * ASTR_ + k0 + 8 * hi16) * 2);
                ldsm_x4(Af[mt], uA + aoff);
            }
#pragma unroll
            for (int mt = 0; mt < 4; mt++)
#pragma unroll
                for (int nt = 0; nt < 4; nt++) mma_f16(acc[mt][nt], Af[mt], Bf[nt]);
        }
        __syncthreads();
    }

    int row_in = lane >> 2, colq = (lane & 3) * 2;
#pragma unroll
    for (int mt = 0; mt < 4; mt++) {
#pragma unroll
        for (int nt = 0; nt < 4; nt++) {
            int m0 = bm + wm * 64 + mt * 16 + row_in;
            int n0 = bn + wn * 32 + nt * 8 + colq;
            float b0 = bias[n0], b1 = bias[n0 + 1];
            float v00 = acc[mt][nt][0] + b0, v01 = acc[mt][nt][1] + b1;
            float v10 = acc[mt][nt][2] + b0, v11 = acc[mt][nt][3] + b1;
            if (MODE == 0) {
                *(__half2*)(Ch + m0 * N + n0)       = __floats2half2_rn(gelu_t(v00), gelu_t(v01));
                *(__half2*)(Ch + (m0 + 8) * N + n0) = __floats2half2_rn(gelu_t(v10), gelu_t(v11));
            } else {
                *(float2*)(Cf + m0 * N + n0)       = make_float2(v00, v01);
                *(float2*)(Cf + (m0 + 8) * N + n0) = make_float2(v10, v11);
            }
        }
    }
}

// ---------------- routed experts: fp16 single-pass, 512 threads, cp.async pipelined ----------------
// smem layout (half elems):
//  sX [128][136] @ 0      (17408)
//  sH [128][72]  @ 17408  (9216)
//  W1 buf [128][72]  @ 26624 (9216, data cols 0..63)
//  W2 buf [64][136]  @ 35840 (8704, data cols 0..127)
#define RT2_SMEM (44544 * 2)

__global__ void __launch_bounds__(512, 2)
routed_hmma(const __half* __restrict__ Xc,
            const __half* __restrict__ E1c, const float* __restrict__ be1,
            const __half* __restrict__ E2c, const float* __restrict__ be2) {
    extern __shared__ __half sm2[];
    __shared__ int   s_entry[128];
    __shared__ float s_w[128];

    int tid = threadIdx.x, wid = tid >> 5, lane = tid & 31;
    int e = blockIdx.y;
    int base = g_off[e] + blockIdx.x * 128;
    int end  = g_off[e + 1];
    if (base >= end) return;

    __half* sH = sm2 + 17408;

    uint32_t uS  = smem_u32(sm2);
    uint32_t uX  = uS;
    uint32_t uH  = uS + 17408 * 2;
    uint32_t uW1 = uS + 26624 * 2;
    uint32_t uW2 = uS + 35840 * 2;

    for (int i = tid; i < 128; i += 512) {
        int p = base + i;
        if (p < end) {
            int en = g_perm[p];
            s_entry[i] = en;
            s_w[i] = g_top_w[en];
        } else {
            s_entry[i] = -1;
            s_w[i] = 0.0f;
        }
    }
    __syncthreads();

    const __half* W1 = E1c + e * (SD_ * HR_);
    const __half* W2 = E2c + e * (HR_ * SD_);
    const float* b1 = be1 + e * HR_;
    const float* b2 = be2 + e * SD_;

    // X gather via cp.async (zero-fill masked rows): 128 rows x 16 chunks
    for (int i = tid; i < 2048; i += 512) {
        int row = i >> 4, u = i & 15;
        int en = s_entry[row];
        int sz = (en >= 0) ? 16 : 0;
        int slot = en >> 1;
        long goff = (en >= 0) ? ((long)(slot >> 3) * DIM_ + (slot & 7) * SD_ + u * 8) : 0;
        cp16(uX + (uint32_t)(row * 136 + u * 8) * 2, Xc + goff, sz);
    }
    // W1 chunk 0: [k=128][h=64] = 128 rows x 8 chunks
    for (int i = tid; i < 1024; i += 512) {
        int k = i >> 3, u = i & 7;
        cp16(uW1 + (uint32_t)(k * 72 + u * 8) * 2, W1 + k * HR_ + u * 8, 16);
    }
    cp_commit();
    cp_wait0();
    __syncthreads();

    int wm = wid & 3, wn = wid >> 2;
    int lo16 = lane & 15, hi16 = lane >> 4;
    int row_in = lane >> 2, colq = (lane & 3) * 2;

    float yacc[2][4][4];
#pragma unroll
    for (int i = 0; i < 2; i++)
#pragma unroll
        for (int j = 0; j < 4; j++)
#pragma unroll
            for (int q = 0; q < 4; q++) yacc[i][j][q] = 0.0f;

    for (int ch = 0; ch < 8; ch++) {
        int h0 = ch * 64;

        // prefetch W2[ch] during GEMM1: [k=64][d=128] = 64 rows x 16 chunks
        for (int i = tid; i < 1024; i += 512) {
            int k = i >> 4, u = i & 15;
            cp16(uW2 + (uint32_t)(k * 136 + u * 8) * 2, W2 + (h0 + k) * SD_ + u * 8, 16);
        }
        cp_commit();

        // GEMM1: H = X @ W1[ch]  (M=128, N=64, K=128)
        float hacc[2][2][4];
#pragma unroll
        for (int i = 0; i < 2; i++)
#pragma unroll
            for (int j = 0; j < 2; j++)
#pragma unroll
                for (int q = 0; q < 4; q++) hacc[i][j][q] = 0.0f;

#pragma unroll
        for (int ks = 0; ks < 8; ks++) {
            int k0 = ks * 16;
            uint32_t boff = (uint32_t)(((k0 + lo16) * 72 + wn * 16 + 8 * hi16) * 2);
            uint32_t Bf[2][2], r4[4];
            ldsm_x4_t(r4, uW1 + boff);
            Bf[0][0] = r4[0]; Bf[0][1] = r4[1]; Bf[1][0] = r4[2]; Bf[1][1] = r4[3];
            uint32_t Af[2][4];
#pragma unroll
            for (int mt = 0; mt < 2; mt++) {
                uint32_t aoff = (uint32_t)(((wm * 32 + mt * 16 + lo16) * 136 + k0 + 8 * hi16) * 2);
                ldsm_x4(Af[mt], uX + aoff);
            }
#pragma unroll
            for (int mt = 0; mt < 2; mt++)
#pragma unroll
                for (int nt = 0; nt < 2; nt++) mma_f16(hacc[mt][nt], Af[mt], Bf[nt]);
        }

        // H epilogue: gelu(bias+acc) -> fp16 into sH
#pragma unroll
        for (int mt = 0; mt < 2; mt++) {
#pragma unroll
            for (int nt = 0; nt < 2; nt++) {
                int n0 = wn * 16 + nt * 8 + colq;
                float bb0 = b1[h0 + n0], bb1 = b1[h0 + n0 + 1];
                int r0 = wm * 32 + mt * 16 + row_in;
                *(__half2*)(sH + r0 * 72 + n0) =
                    __floats2half2_rn(gelu_t(hacc[mt][nt][0] + bb0), gelu_t(hacc[mt][nt][1] + bb1));
                *(__half2*)(sH + (r0 + 8) * 72 + n0) =
                    __floats2half2_rn(gelu_t(hacc[mt][nt][2] + bb0), gelu_t(hacc[mt][nt][3] + bb1));
            }
        }
        cp_wait0();
        __syncthreads();

        // prefetch W1[ch+1] during GEMM2
        if (ch < 7) {
            int h1 = h0 + 64;
            for (int i = tid; i < 1024; i += 512) {
                int k = i >> 3, u = i & 7;
                cp16(uW1 + (uint32_t)(k * 72 + u * 8) * 2, W1 + k * HR_ + h1 + u * 8, 16);
            }
        }
        cp_commit();

        // GEMM2: Y += H @ W2[ch]  (M=128, N=128, K=64)
#pragma unroll
        for (int ks = 0; ks < 4; ks++) {
            int k0 = ks * 16;
            uint32_t Bf[4][2];
#pragma unroll
            for (int p = 0; p < 2; p++) {
                uint32_t boff = (uint32_t)(((k0 + lo16) * 136 + wn * 32 + p * 16 + 8 * hi16) * 2);
                uint32_t r4[4];
                ldsm_x4_t(r4, uW2 + boff);
                Bf[p * 2][0] = r4[0]; Bf[p * 2][1] = r4[1];
                Bf[p * 2 + 1][0] = r4[2]; Bf[p * 2 + 1][1] = r4[3];
            }
            uint32_t Af[2][4];
#pragma unroll
            for (int mt = 0; mt < 2; mt++) {
                uint32_t aoff = (uint32_t)(((wm * 32 + mt * 16 + lo16) * 72 + k0 + 8 * hi16) * 2);
                ldsm_x4(Af[mt], uH + aoff);
            }
#pragma unroll
            for (int mt = 0; mt < 2; mt++)
#pragma unroll
                for (int nt = 0; nt < 4; nt++) mma_f16(yacc[mt][nt], Af[mt], Bf[nt]);
        }
        cp_wait0();
        __syncthreads();
    }

    // epilogue: g_Yent[entry] = w * (y + b2)
#pragma unroll
    for (int mt = 0; mt < 2; mt++) {
#pragma unroll
        for (int nt = 0; nt < 4; nt++) {
            int n0 = wn * 32 + nt * 8 + colq;
            float bb0 = b2[n0], bb1 = b2[n0 + 1];
            int r0 = wm * 32 + mt * 16 + row_in;
            int en0 = s_entry[r0];
            if (en0 >= 0) {
                float w = s_w[r0];
                *(float2*)(g_Yent + en0 * SD_ + n0) =
                    make_float2(w * (yacc[mt][nt][0] + bb0), w * (yacc[mt][nt][1] + bb1));
            }
            int en1 = s_entry[r0 + 8];
            if (en1 >= 0) {
                float w = s_w[r0 + 8];
                *(float2*)(g_Yent + en1 * SD_ + n0) =
                    make_float2(w * (yacc[mt][nt][2] + bb0), w * (yacc[mt][nt][3] + bb1));
            }
        }
    }
}

// ---------------- init ----------------
__global__ void init_kernel() {
    int t = threadIdx.x;
    if (t < NE_) { g_cnt[t] = 0; g_wsum[t] = 0.0f; }
}

// ---------------- router ----------------
__global__ void router_kernel(const float* __restrict__ X, const float* __restrict__ Wr) {
    __shared__ float Wrs[SD_ * NE_];
    __shared__ int   scnt[NE_];
    __shared__ float sws[NE_];
    int tid = threadIdx.x;
    for (int i = tid; i < SD_ * NE_; i += 128) Wrs[i] = Wr[i];
    if (tid < NE_) { scnt[tid] = 0; sws[tid] = 0.0f; }
    __syncthreads();

    int slot = blockIdx.x * 128 + tid;
    const float* x = X + (slot >> 3) * DIM_ + (slot & 7) * SD_;
    float lg[NE_];
#pragma unroll
    for (int e = 0; e < NE_; e++) lg[e] = 0.0f;
    for (int k = 0; k < SD_; k++) {
        float xv = x[k];
        const float* wr = &Wrs[k * NE_];
#pragma unroll
        for (int e = 0; e < NE_; e++) lg[e] += xv * wr[e];
    }
    float mx = lg[0];
#pragma unroll
    for (int e = 1; e < NE_; e++) mx = fmaxf(mx, lg[e]);
    float p[NE_]; float sum = 0.0f;
#pragma unroll
    for (int e = 0; e < NE_; e++) { p[e] = expf(lg[e] - mx); sum += p[e]; }
    float inv = 1.0f / sum;
    int i0 = 0; float m0 = -1.0f;
#pragma unroll
    for (int e = 0; e < NE_; e++) if (p[e] > m0) { m0 = p[e]; i0 = e; }
    int i1 = 0; float m1 = -1.0f;
#pragma unroll
    for (int e = 0; e < NE_; e++) if (e != i0 && p[e] > m1) { m1 = p[e]; i1 = e; }
    float w0 = m0 * inv, w1 = m1 * inv;

    g_top_idx[2 * slot]     = i0;
    g_top_idx[2 * slot + 1] = i1;
    g_top_w[2 * slot]       = w0;
    g_top_w[2 * slot + 1]   = w1;

    atomicAdd(&scnt[i0], 1); atomicAdd(&scnt[i1], 1);
    atomicAdd(&sws[i0], w0); atomicAdd(&sws[i1], w1);
    __syncthreads();
    if (tid < NE_) {
        atomicAdd(&g_cnt[tid], scnt[tid]);
        atomicAdd(&g_wsum[tid], sws[tid]);
    }
}

// ---------------- offsets + aux ----------------
__global__ void offsets_kernel() {
    if (threadIdx.x == 0) {
        int acc = 0; float aux = 0.0f;
        for (int e = 0; e < NE_; e++) {
            g_off[e] = acc; g_cursor[e] = acc;
            acc += g_cnt[e];
            float f = (float)g_cnt[e] / ((float)NS_ * (float)KTOP_);
            float P = g_wsum[e] / (float)NS_;
            aux += f * P;
        }
        g_off[NE_] = acc;
        g_aux = (float)NE_ * aux;
    }
}

// ---------------- scatter ----------------
__global__ void scatter_kernel() {
    int slot = blockIdx.x * blockDim.x + threadIdx.x;
    if (slot >= NS_) return;
#pragma unroll
    for (int k = 0; k < KTOP_; k++) {
        int en = 2 * slot + k;
        int e = g_top_idx[en];
        int p = atomicAdd(&g_cursor[e], 1);
        g_perm[p] = en;
    }
}

// ---------------- combine ----------------
__global__ void combine_kernel(float* __restrict__ out, int out_size) {
    int idx = blockIdx.x * 256 + threadIdx.x;
    int c = idx & (SD_ - 1);
    int slot = idx >> 7;
    int token = slot >> 3, s = slot & 7;
    float add = g_Yent[(2 * slot) * SD_ + c] + g_Yent[(2 * slot + 1) * SD_ + c];
    out[token * DIM_ + s * SD_ + c] += add;
    if (idx == 0 && out_size > TOK_ * DIM_) out[TOK_ * DIM_] = g_aux;
}

// ---------------- launch ----------------
extern "C" void kernel_launch(void* const* d_in, const int* in_sizes, int n_in,
                              void* d_out, int out_size) {
    const float* X   = (const float*)d_in[0];
    const float* Ws1 = (const float*)d_in[1];
    const float* bs1 = (const float*)d_in[2];
    const float* Ws2 = (const float*)d_in[3];
    const float* bs2 = (const float*)d_in[4];
    const float* Wr  = (const float*)d_in[5];
    const float* We1 = (const float*)d_in[6];
    const float* be1 = (const float*)d_in[7];
    const float* We2 = (const float*)d_in[8];
    const float* be2 = (const float*)d_in[9];
    float* out = (float*)d_out;

    static cudaStream_t s2 = nullptr;
    static cudaEvent_t evStart = nullptr, evScatter = nullptr, evX = nullptr, evJoin = nullptr;
    if (s2 == nullptr) {
        cudaStreamCreateWithFlags(&s2, cudaStreamNonBlocking);
        cudaEventCreateWithFlags(&evStart,   cudaEventDisableTiming);
        cudaEventCreateWithFlags(&evScatter, cudaEventDisableTiming);
        cudaEventCreateWithFlags(&evX,       cudaEventDisableTiming);
        cudaEventCreateWithFlags(&evJoin,    cudaEventDisableTiming);
    }

    cudaFuncSetAttribute(gemm_hmma<0>, cudaFuncAttributeMaxDynamicSharedMemorySize, GSM_BYTES);
    cudaFuncSetAttribute(gemm_hmma<1>, cudaFuncAttributeMaxDynamicSharedMemorySize, GSM_BYTES);
    cudaFuncSetAttribute(routed_hmma, cudaFuncAttributeMaxDynamicSharedMemorySize, RT2_SMEM);

    __half *Xc, *W1c, *W2c, *H1c, *E1c, *E2c;
    cudaGetSymbolAddress((void**)&Xc,  g_Xc);
    cudaGetSymbolAddress((void**)&W1c, g_W1c);
    cudaGetSymbolAddress((void**)&W2c, g_W2c);
    cudaGetSymbolAddress((void**)&H1c, g_H1c);
    cudaGetSymbolAddress((void**)&E1c, g_E1c);
    cudaGetSymbolAddress((void**)&E2c, g_E2c);

    // ---- fork immediately: converts on s2 concurrent with router chain on main ----
    cudaEventRecord(evStart, 0);
    cudaStreamWaitEvent(s2, evStart, 0);

    // s2: routed prerequisites
    cvt_kernel<<<(TOK_ * DIM_ / 4 + 255) / 256, 256, 0, s2>>>(X, Xc, TOK_ * DIM_ / 4);
    cudaEventRecord(evX, s2);
    cvt_kernel<<<(NE_ * SD_ * HR_ / 4 + 255) / 256, 256, 0, s2>>>(We1, E1c, NE_ * SD_ * HR_ / 4);
    cvt_kernel<<<(NE_ * HR_ * SD_ / 4 + 255) / 256, 256, 0, s2>>>(We2, E2c, NE_ * HR_ * SD_ / 4);

    // main: router chain
    init_kernel<<<1, 64>>>();
    router_kernel<<<NS_ / 128, 128>>>(X, Wr);
    offsets_kernel<<<1, 32>>>();
    scatter_kernel<<<NS_ / 128, 128>>>();
    cudaEventRecord(evScatter, 0);

    // s2: routed experts
    cudaStreamWaitEvent(s2, evScatter, 0);
    routed_hmma<<<dim3(NENT_ / 128, NE_), 512, RT2_SMEM, s2>>>(
        Xc, E1c, be1, E2c, be2);
    cudaEventRecord(evJoin, s2);

    // main: shared expert
    cvt_kernel<<<(DIM_ * HSH_ / 4 + 255) / 256, 256>>>(Ws1, W1c, DIM_ * HSH_ / 4);
    cvt_kernel<<<(HSH_ * DIM_ / 4 + 255) / 256, 256>>>(Ws2, W2c, HSH_ * DIM_ / 4);
    cudaStreamWaitEvent(0, evX, 0);
    gemm_hmma<0><<<dim3(HSH_ / BN_, TOK_ / BM_), 256, GSM_BYTES>>>(
        Xc, W1c, bs1, nullptr, H1c, TOK_, HSH_, DIM_);
    gemm_hmma<1><<<dim3(DIM_ / BN_, TOK_ / BM_), 256, GSM_BYTES>>>(
        H1c, W2c, bs2, out, nullptr, TOK_, DIM_, HSH_);

    // ---- join + combine ----
    cudaStreamWaitEvent(0, evJoin, 0);
    combine_kernel<<<(NS_ * SD_) / 256, 256>>>(out, out_size);
}

// round 10
// speedup vs baseline: 12.4617x; 1.0050x over previous
#include <cuda_runtime.h>
#include <cuda_fp16.h>
#include <cstdint>

// ---------------- problem constants ----------------
#define B_ 2
#define T_ 2048
#define DIM_ 1024
#define SEG_ 8
#define SD_ 128
#define NE_ 16
#define KTOP_ 2
#define HSH_ 4096
#define HR_ 512
#define TOK_ (B_ * T_)            // 4096 tokens
#define NS_ (TOK_ * SEG_)         // 32768 token-segments
#define NENT_ (NS_ * KTOP_)       // 65536 routed entries

// ---------------- device scratch ----------------
__device__ __half g_Xc[TOK_ * DIM_];
__device__ __half g_W1c[DIM_ * HSH_];
__device__ __half g_W2c[HSH_ * DIM_];
__device__ __half g_H1c[TOK_ * HSH_];
__device__ __half g_E1c[NE_ * SD_ * HR_];
__device__ __half g_E2c[NE_ * HR_ * SD_];
__device__ float g_Yent[NENT_ * SD_];
__device__ int   g_top_idx[NENT_];
__device__ float g_top_w[NENT_];
__device__ int   g_cnt[NE_];
__device__ float g_wsum[NE_];
__device__ int   g_off[NE_ + 1];
__device__ int   g_cursor[NE_];
__device__ int   g_perm[NENT_];
__device__ float g_aux;

__device__ __forceinline__ float gelu_t(float x) {
    float x3 = x * x * x;
    return 0.5f * x * (1.0f + tanhf(0.7978845608028654f * (x + 0.044715f * x3)));
}

__device__ __forceinline__ uint32_t smem_u32(const void* p) {
    uint32_t a;
    asm("{ .reg .u64 t; cvta.to.shared.u64 t, %1; cvt.u32.u64 %0, t; }" : "=r"(a) : "l"(p));
    return a;
}

__device__ __forceinline__ void ldsm_x4(uint32_t r[4], uint32_t addr) {
    asm volatile("ldmatrix.sync.aligned.m8n8.x4.shared.b16 {%0,%1,%2,%3}, [%4];"
        : "=r"(r[0]), "=r"(r[1]), "=r"(r[2]), "=r"(r[3]) : "r"(addr));
}
__device__ __forceinline__ void ldsm_x4_t(uint32_t r[4], uint32_t addr) {
    asm volatile("ldmatrix.sync.aligned.m8n8.x4.trans.shared.b16 {%0,%1,%2,%3}, [%4];"
        : "=r"(r[0]), "=r"(r[1]), "=r"(r[2]), "=r"(r[3]) : "r"(addr));
}
__device__ __forceinline__ void mma_f16(float d[4], const uint32_t a[4], const uint32_t b[2]) {
    asm volatile("mma.sync.aligned.m16n8k16.row.col.f32.f16.f16.f32 "
        "{%0,%1,%2,%3}, {%4,%5,%6,%7}, {%8,%9}, {%0,%1,%2,%3};"
        : "+f"(d[0]), "+f"(d[1]), "+f"(d[2]), "+f"(d[3])
        : "r"(a[0]), "r"(a[1]), "r"(a[2]), "r"(a[3]), "r"(b[0]), "r"(b[1]));
}
__device__ __forceinline__ void cp16(uint32_t s, const void* g, int szbytes) {
    asm volatile("cp.async.cg.shared.global [%0], [%1], 16, %2;"
        :: "r"(s), "l"(g), "r"(szbytes));
}
__device__ __forceinline__ void cp_commit() { asm volatile("cp.async.commit_group;" ::: "memory"); }
__device__ __forceinline__ void cp_wait0()  { asm volatile("cp.async.wait_group 0;" ::: "memory"); }
__device__ __forceinline__ void cp_wait1()  { asm volatile("cp.async.wait_group 1;" ::: "memory"); }

// ---------------- fp32 -> fp16 conversion (single + pair) ----------------
__global__ void cvt_kernel(const float* __restrict__ src, __half* __restrict__ dst, int n4) {
    int i = blockIdx.x * 256 + threadIdx.x;
    if (i >= n4) return;
    float4 v = ((const float4*)src)[i];
    ((__half2*)dst)[2 * i]     = __floats2half2_rn(v.x, v.y);
    ((__half2*)dst)[2 * i + 1] = __floats2half2_rn(v.z, v.w);
}

__global__ void cvt2_kernel(const float* __restrict__ s1, __half* __restrict__ d1, int n1,
                            const float* __restrict__ s2, __half* __restrict__ d2, int n2) {
    int i = blockIdx.x * 256 + threadIdx.x;
    const float* s; __half* d; int j;
    if (i < n1) { s = s1; d = d1; j = i; }
    else if (i < n1 + n2) { s = s2; d = d2; j = i - n1; }
    else return;
    float4 v = ((const float4*)s)[j];
    ((__half2*)d)[2 * j]     = __floats2half2_rn(v.x, v.y);
    ((__half2*)d)[2 * j + 1] = __floats2half2_rn(v.z, v.w);
}

// ---------------- HMMA fp16 GEMM, 3-stage cp.async pipeline, 1 sync/chunk ----------------
#define BM_ 128
#define BN_ 128
#define BK_ 64
#define ASTR_ 72
#define BSTR_ 136
#define STG_BYTES 35840
#define GSM_BYTES (3 * STG_BYTES)

template <int MODE>
__global__ void __launch_bounds__(256, 2)
gemm_hmma(const __half* __restrict__ A, const __half* __restrict__ Bm,
          const float* __restrict__ bias,
          float* __restrict__ Cf, __half* __restrict__ Ch,
          int M, int N, int K) {
    extern __shared__ char smraw[];

    int tid = threadIdx.x;
    int wid = tid >> 5, lane = tid & 31;
    int wm = wid & 1, wn = wid >> 1;
    int bn = blockIdx.x * BN_, bm = blockIdx.y * BM_;

    uint32_t uS = smem_u32(smraw);

    float acc[4][4][4];
#pragma unroll
    for (int i = 0; i < 4; i++)
#pragma unroll
        for (int j = 0; j < 4; j++)
#pragma unroll
            for (int q = 0; q < 4; q++) acc[i][j][q] = 0.0f;

    int lo16 = lane & 15, hi16 = lane >> 4;

    auto load_chunk = [&](int kc, int st) {
        uint32_t bA = uS + st * STG_BYTES;
        uint32_t bB = bA + 18432;
#pragma unroll 2
        for (int i = tid; i < 1024; i += 256) {
            int r = i >> 3, u = i & 7;
            int g = (bm + r) * K + kc + u * 8;
            cp16(bA + (uint32_t)(r * ASTR_ + u * 8) * 2, A + g, 16);
        }
#pragma unroll 2
        for (int i = tid; i < 1024; i += 256) {
            int r = i >> 4, u = i & 15;
            int g = (kc + r) * N + bn + u * 8;
            cp16(bB + (uint32_t)(r * BSTR_ + u * 8) * 2, Bm + g, 16);
        }
    };

    int nch = K / BK_;
    load_chunk(0, 0);
    cp_commit();
    load_chunk(BK_, 1);
    cp_commit();

    for (int c = 0; c < nch; c++) {
        int st = c % 3;
        cp_wait1();            // load(c) complete
        __syncthreads();       // all warps done computing chunk c-1 -> stage (c-1)%3 free
        if (c + 2 < nch) load_chunk((c + 2) * BK_, (c + 2) % 3);
        cp_commit();

        uint32_t uA = uS + st * STG_BYTES;
        uint32_t uB = uA + 18432;

#pragma unroll
        for (int ks = 0; ks < 4; ks++) {
            int k0 = ks * 16;
            uint32_t Bf[4][2];
#pragma unroll
            for (int p = 0; p < 2; p++) {
                uint32_t boff = (uint32_t)(((k0 + lo16) * BSTR_ + wn * 32 + p * 16 + 8 * hi16) * 2);
                uint32_t r4[4];
                ldsm_x4_t(r4, uB + boff);
                Bf[p * 2][0] = r4[0]; Bf[p * 2][1] = r4[1];
                Bf[p * 2 + 1][0] = r4[2]; Bf[p * 2 + 1][1] = r4[3];
            }
            uint32_t Af[4][4];
#pragma unroll
            for (int mt = 0; mt < 4; mt++) {
                uint32_t aoff = (uint32_t)(((wm * 64 + mt * 16 + lo16) * ASTR_ + k0 + 8 * hi16) * 2);
                ldsm_x4(Af[mt], uA + aoff);
            }
#pragma unroll
            for (int mt = 0; mt < 4; mt++)
#pragma unroll
                for (int nt = 0; nt < 4; nt++) mma_f16(acc[mt][nt], Af[mt], Bf[nt]);
        }
    }

    int row_in = lane >> 2, colq = (lane & 3) * 2;
#pragma unroll
    for (int mt = 0; mt < 4; mt++) {
#pragma unroll
        for (int nt = 0; nt < 4; nt++) {
            int m0 = bm + wm * 64 + mt * 16 + row_in;
            int n0 = bn + wn * 32 + nt * 8 + colq;
            float b0 = bias[n0], b1 = bias[n0 + 1];
            float v00 = acc[mt][nt][0] + b0, v01 = acc[mt][nt][1] + b1;
            float v10 = acc[mt][nt][2] + b0, v11 = acc[mt][nt][3] + b1;
            if (MODE == 0) {
                *(__half2*)(Ch + m0 * N + n0)       = __floats2half2_rn(gelu_t(v00), gelu_t(v01));
                *(__half2*)(Ch + (m0 + 8) * N + n0) = __floats2half2_rn(gelu_t(v10), gelu_t(v11));
            } else {
                *(float2*)(Cf + m0 * N + n0)       = make_float2(v00, v01);
                *(float2*)(Cf + (m0 + 8) * N + n0) = make_float2(v10, v11);
            }
        }
    }
}

// ---------------- routed experts: fp16 single-pass, 512 threads ----------------
// smem layout (half elems):
//  sX [128][136] @ 0, sH [128][72] @ 17408, W1 [128][72] @ 26624, W2 [64][136] @ 35840
#define RT2_SMEM (44544 * 2)

__global__ void __launch_bounds__(512)
routed_hmma(const __half* __restrict__ Xc,
            const __half* __restrict__ E1c, const float* __restrict__ be1,
            const __half* __restrict__ E2c, const float* __restrict__ be2) {
    extern __shared__ __half sm2[];
    __shared__ int   s_entry[128];
    __shared__ float s_w[128];

    int tid = threadIdx.x, wid = tid >> 5, lane = tid & 31;
    int e = blockIdx.y;
    int base = g_off[e] + blockIdx.x * 128;
    int end  = g_off[e + 1];
    if (base >= end) return;

    __half* sH = sm2 + 17408;

    uint32_t uS  = smem_u32(sm2);
    uint32_t uX  = uS;
    uint32_t uH  = uS + 17408 * 2;
    uint32_t uW1 = uS + 26624 * 2;
    uint32_t uW2 = uS + 35840 * 2;

    for (int i = tid; i < 128; i += 512) {
        int p = base + i;
        if (p < end) {
            int en = g_perm[p];
            s_entry[i] = en;
            s_w[i] = g_top_w[en];
        } else {
            s_entry[i] = -1;
            s_w[i] = 0.0f;
        }
    }
    __syncthreads();

    const __half* W1 = E1c + e * (SD_ * HR_);
    const __half* W2 = E2c + e * (HR_ * SD_);
    const float* b1 = be1 + e * HR_;
    const float* b2 = be2 + e * SD_;

    // X gather via cp.async (zero-fill masked rows)
    for (int i = tid; i < 2048; i += 512) {
        int row = i >> 4, u = i & 15;
        int en = s_entry[row];
        int sz = (en >= 0) ? 16 : 0;
        int slot = en >> 1;
        long goff = (en >= 0) ? ((long)(slot >> 3) * DIM_ + (slot & 7) * SD_ + u * 8) : 0;
        cp16(uX + (uint32_t)(row * 136 + u * 8) * 2, Xc + goff, sz);
    }
    // W1 chunk 0
    for (int i = tid; i < 1024; i += 512) {
        int k = i >> 3, u = i & 7;
        cp16(uW1 + (uint32_t)(k * 72 + u * 8) * 2, W1 + k * HR_ + u * 8, 16);
    }
    cp_commit();
    cp_wait0();
    __syncthreads();

    int wm = wid & 3, wn = wid >> 2;
    int lo16 = lane & 15, hi16 = lane >> 4;
    int row_in = lane >> 2, colq = (lane & 3) * 2;

    float yacc[2][4][4];
#pragma unroll
    for (int i = 0; i < 2; i++)
#pragma unroll
        for (int j = 0; j < 4; j++)
#pragma unroll
            for (int q = 0; q < 4; q++) yacc[i][j][q] = 0.0f;

    for (int ch = 0; ch < 8; ch++) {
        int h0 = ch * 64;

        // prefetch W2[ch] during GEMM1
        for (int i = tid; i < 1024; i += 512) {
            int k = i >> 4, u = i & 15;
            cp16(uW2 + (uint32_t)(k * 136 + u * 8) * 2, W2 + (h0 + k) * SD_ + u * 8, 16);
        }
        cp_commit();

        // GEMM1: H = X @ W1[ch]  (M=128, N=64, K=128)
        float hacc[2][2][4];
#pragma unroll
        for (int i = 0; i < 2; i++)
#pragma unroll
            for (int j = 0; j < 2; j++)
#pragma unroll
                for (int q = 0; q < 4; q++) hacc[i][j][q] = 0.0f;

#pragma unroll
        for (int ks = 0; ks < 8; ks++) {
            int k0 = ks * 16;
            uint32_t boff = (uint32_t)(((k0 + lo16) * 72 + wn * 16 + 8 * hi16) * 2);
            uint32_t Bf[2][2], r4[4];
            ldsm_x4_t(r4, uW1 + boff);
            Bf[0][0] = r4[0]; Bf[0][1] = r4[1]; Bf[1][0] = r4[2]; Bf[1][1] = r4[3];
            uint32_t Af[2][4];
#pragma unroll
            for (int mt = 0; mt < 2; mt++) {
                uint32_t aoff = (uint32_t)(((wm * 32 + mt * 16 + lo16) * 136 + k0 + 8 * hi16) * 2);
                ldsm_x4(Af[mt], uX + aoff);
            }
#pragma unroll
            for (int mt = 0; mt < 2; mt++)
#pragma unroll
                for (int nt = 0; nt < 2; nt++) mma_f16(hacc[mt][nt], Af[mt], Bf[nt]);
        }

        // H epilogue: gelu(bias+acc) -> fp16 into sH
#pragma unroll
        for (int mt = 0; mt < 2; mt++) {
#pragma unroll
            for (int nt = 0; nt < 2; nt++) {
                int n0 = wn * 16 + nt * 8 + colq;
                float bb0 = b1[h0 + n0], bb1 = b1[h0 + n0 + 1];
                int r0 = wm * 32 + mt * 16 + row_in;
                *(__half2*)(sH + r0 * 72 + n0) =
                    __floats2half2_rn(gelu_t(hacc[mt][nt][0] + bb0), gelu_t(hacc[mt][nt][1] + bb1));
                *(__half2*)(sH + (r0 + 8) * 72 + n0) =
                    __floats2half2_rn(gelu_t(hacc[mt][nt][2] + bb0), gelu_t(hacc[mt][nt][3] + bb1));
            }
        }
        cp_wait0();
        __syncthreads();

        // prefetch W1[ch+1] during GEMM2
        if (ch < 7) {
            int h1 = h0 + 64;
            for (int i = tid; i < 1024; i += 512) {
                int k = i >> 3, u = i & 7;
                cp16(uW1 + (uint32_t)(k * 72 + u * 8) * 2, W1 + k * HR_ + h1 + u * 8, 16);
            }
        }
        cp_commit();

        // GEMM2: Y += H @ W2[ch]  (M=128, N=128, K=64)
#pragma unroll
        for (int ks = 0; ks < 4; ks++) {
            int k0 = ks * 16;
            uint32_t Bf[4][2];
#pragma unroll
            for (int p = 0; p < 2; p++) {
                uint32_t boff = (uint32_t)(((k0 + lo16) * 136 + wn * 32 + p * 16 + 8 * hi16) * 2);
                uint32_t r4[4];
                ldsm_x4_t(r4, uW2 + boff);
                Bf[p * 2][0] = r4[0]; Bf[p * 2][1] = r4[1];
                Bf[p * 2 + 1][0] = r4[2]; Bf[p * 2 + 1][1] = r4[3];
            }
            uint32_t Af[2][4];
#pragma unroll
            for (int mt = 0; mt < 2; mt++) {
                uint32_t aoff = (uint32_t)(((wm * 32 + mt * 16 + lo16) * 72 + k0 + 8 * hi16) * 2);
                ldsm_x4(Af[mt], uH + aoff);
            }
#pragma unroll
            for (int mt = 0; mt < 2; mt++)
#pragma unroll
                for (int nt = 0; nt < 4; nt++) mma_f16(yacc[mt][nt], Af[mt], Bf[nt]);
        }
        cp_wait0();
        __syncthreads();
    }

    // epilogue: g_Yent[entry] = w * (y + b2)
#pragma unroll
    for (int mt = 0; mt < 2; mt++) {
#pragma unroll
        for (int nt = 0; nt < 4; nt++) {
            int n0 = wn * 32 + nt * 8 + colq;
            float bb0 = b2[n0], bb1 = b2[n0 + 1];
            int r0 = wm * 32 + mt * 16 + row_in;
            int en0 = s_entry[r0];
            if (en0 >= 0) {
                float w = s_w[r0];
                *(float2*)(g_Yent + en0 * SD_ + n0) =
                    make_float2(w * (yacc[mt][nt][0] + bb0), w * (yacc[mt][nt][1] + bb1));
            }
            int en1 = s_entry[r0 + 8];
            if (en1 >= 0) {
                float w = s_w[r0 + 8];
                *(float2*)(g_Yent + en1 * SD_ + n0) =
                    make_float2(w * (yacc[mt][nt][2] + bb0), w * (yacc[mt][nt][3] + bb1));
            }
        }
    }
}

// ---------------- init ----------------
__global__ void init_kernel() {
    int t = threadIdx.x;
    if (t < NE_) { g_cnt[t] = 0; g_wsum[t] = 0.0f; }
}

// ---------------- router ----------------
__global__ void router_kernel(const float* __restrict__ X, const float* __restrict__ Wr) {
    __shared__ float Wrs[SD_ * NE_];
    __shared__ int   scnt[NE_];
    __shared__ float sws[NE_];
    int tid = threadIdx.x;
    for (int i = tid; i < SD_ * NE_; i += 128) Wrs[i] = Wr[i];
    if (tid < NE_) { scnt[tid] = 0; sws[tid] = 0.0f; }
    __syncthreads();

    int slot = blockIdx.x * 128 + tid;
    const float* x = X + (slot >> 3) * DIM_ + (slot & 7) * SD_;
    float lg[NE_];
#pragma unroll
    for (int e = 0; e < NE_; e++) lg[e] = 0.0f;
    for (int k = 0; k < SD_; k++) {
        float xv = x[k];
        const float* wr = &Wrs[k * NE_];
#pragma unroll
        for (int e = 0; e < NE_; e++) lg[e] += xv * wr[e];
    }
    float mx = lg[0];
#pragma unroll
    for (int e = 1; e < NE_; e++) mx = fmaxf(mx, lg[e]);
    float p[NE_]; float sum = 0.0f;
#pragma unroll
    for (int e = 0; e < NE_; e++) { p[e] = expf(lg[e] - mx); sum += p[e]; }
    float inv = 1.0f / sum;
    int i0 = 0; float m0 = -1.0f;
#pragma unroll
    for (int e = 0; e < NE_; e++) if (p[e] > m0) { m0 = p[e]; i0 = e; }
    int i1 = 0; float m1 = -1.0f;
#pragma unroll
    for (int e = 0; e < NE_; e++) if (e != i0 && p[e] > m1) { m1 = p[e]; i1 = e; }
    float w0 = m0 * inv, w1 = m1 * inv;

    g_top_idx[2 * slot]     = i0;
    g_top_idx[2 * slot + 1] = i1;
    g_top_w[2 * slot]       = w0;
    g_top_w[2 * slot + 1]   = w1;

    atomicAdd(&scnt[i0], 1); atomicAdd(&scnt[i1], 1);
    atomicAdd(&sws[i0], w0); atomicAdd(&sws[i1], w1);
    __syncthreads();
    if (tid < NE_) {
        atomicAdd(&g_cnt[tid], scnt[tid]);
        atomicAdd(&g_wsum[tid], sws[tid]);
    }
}

// ---------------- offsets + aux ----------------
__global__ void offsets_kernel() {
    if (threadIdx.x == 0) {
        int acc = 0; float aux = 0.0f;
        for (int e = 0; e < NE_; e++) {
            g_off[e] = acc; g_cursor[e] = acc;
            acc += g_cnt[e];
            float f = (float)g_cnt[e] / ((float)NS_ * (float)KTOP_);
            float P = g_wsum[e] / (float)NS_;
            aux += f * P;
        }
        g_off[NE_] = acc;
        g_aux = (float)NE_ * aux;
    }
}

// ---------------- scatter ----------------
__global__ void scatter_kernel() {
    int slot = blockIdx.x * blockDim.x + threadIdx.x;
    if (slot >= NS_) return;
#pragma unroll
    for (int k = 0; k < KTOP_; k++) {
        int en = 2 * slot + k;
        int e = g_top_idx[en];
        int p = atomicAdd(&g_cursor[e], 1);
        g_perm[p] = en;
    }
}

// ---------------- combine ----------------
__global__ void combine_kernel(float* __restrict__ out, int out_size) {
    int idx = blockIdx.x * 256 + threadIdx.x;
    int c = idx & (SD_ - 1);
    int slot = idx >> 7;
    int token = slot >> 3, s = slot & 7;
    float add = g_Yent[(2 * slot) * SD_ + c] + g_Yent[(2 * slot + 1) * SD_ + c];
    out[token * DIM_ + s * SD_ + c] += add;
    if (idx == 0 && out_size > TOK_ * DIM_) out[TOK_ * DIM_] = g_aux;
}

// ---------------- launch ----------------
extern "C" void kernel_launch(void* const* d_in, const int* in_sizes, int n_in,
                              void* d_out, int out_size) {
    const float* X   = (const float*)d_in[0];
    const float* Ws1 = (const float*)d_in[1];
    const float* bs1 = (const float*)d_in[2];
    const float* Ws2 = (const float*)d_in[3];
    const float* bs2 = (const float*)d_in[4];
    const float* Wr  = (const float*)d_in[5];
    const float* We1 = (const float*)d_in[6];
    const float* be1 = (const float*)d_in[7];
    const float* We2 = (const float*)d_in[8];
    const float* be2 = (const float*)d_in[9];
    float* out = (float*)d_out;

    static cudaStream_t s2 = nullptr, s3 = nullptr;
    static cudaEvent_t evStart = nullptr, evScatter = nullptr, evX = nullptr, evJoin = nullptr;
    if (s2 == nullptr) {
        cudaStreamCreateWithFlags(&s2, cudaStreamNonBlocking);
        cudaStreamCreateWithFlags(&s3, cudaStreamNonBlocking);
        cudaEventCreateWithFlags(&evStart,   cudaEventDisableTiming);
        cudaEventCreateWithFlags(&evScatter, cudaEventDisableTiming);
        cudaEventCreateWithFlags(&evX,       cudaEventDisableTiming);
        cudaEventCreateWithFlags(&evJoin,    cudaEventDisableTiming);
    }

    cudaFuncSetAttribute(gemm_hmma<0>, cudaFuncAttributeMaxDynamicSharedMemorySize, GSM_BYTES);
    cudaFuncSetAttribute(gemm_hmma<1>, cudaFuncAttributeMaxDynamicSharedMemorySize, GSM_BYTES);
    cudaFuncSetAttribute(routed_hmma, cudaFuncAttributeMaxDynamicSharedMemorySize, RT2_SMEM);

    __half *Xc, *W1c, *W2c, *H1c, *E1c, *E2c;
    cudaGetSymbolAddress((void**)&Xc,  g_Xc);
    cudaGetSymbolAddress((void**)&W1c, g_W1c);
    cudaGetSymbolAddress((void**)&W2c, g_W2c);
    cudaGetSymbolAddress((void**)&H1c, g_H1c);
    cudaGetSymbolAddress((void**)&E1c, g_E1c);
    cudaGetSymbolAddress((void**)&E2c, g_E2c);

    // ---- fork: three streams ----
    cudaEventRecord(evStart, 0);
    cudaStreamWaitEvent(s2, evStart, 0);
    cudaStreamWaitEvent(s3, evStart, 0);

    // s3: router chain (off the critical path)
    init_kernel<<<1, 64, 0, s3>>>();
    router_kernel<<<NS_ / 128, 128, 0, s3>>>(X, Wr);
    offsets_kernel<<<1, 32, 0, s3>>>();
    scatter_kernel<<<NS_ / 128, 128, 0, s3>>>();
    cudaEventRecord(evScatter, s3);

    // s2: routed prerequisites + routed
    cvt_kernel<<<(TOK_ * DIM_ / 4 + 255) / 256, 256, 0, s2>>>(X, Xc, TOK_ * DIM_ / 4);
    cudaEventRecord(evX, s2);
    cvt2_kernel<<<(NE_ * SD_ * HR_ / 4 + NE_ * HR_ * SD_ / 4 + 255) / 256, 256, 0, s2>>>(
        We1, E1c, NE_ * SD_ * HR_ / 4, We2, E2c, NE_ * HR_ * SD_ / 4);
    cudaStreamWaitEvent(s2, evScatter, 0);
    routed_hmma<<<dim3(NENT_ / 128, NE_), 512, RT2_SMEM, s2>>>(
        Xc, E1c, be1, E2c, be2);
    cudaEventRecord(evJoin, s2);

    // main: shared expert (critical path)
    cvt2_kernel<<<(DIM_ * HSH_ / 4 + HSH_ * DIM_ / 4 + 255) / 256, 256>>>(
        Ws1, W1c, DIM_ * HSH_ / 4, Ws2, W2c, HSH_ * DIM_ / 4);
    cudaStreamWaitEvent(0, evX, 0);
    gemm_hmma<0><<<dim3(HSH_ / BN_, TOK_ / BM_), 256, GSM_BYTES>>>(
        Xc, W1c, bs1, nullptr, H1c, TOK_, HSH_, DIM_);
    gemm_hmma<1><<<dim3(DIM_ / BN_, TOK_ / BM_), 256, GSM_BYTES>>>(
        H1c, W2c, bs2, out, nullptr, TOK_, DIM_, HSH_);

    // ---- join + combine ----
    cudaStreamWaitEvent(0, evJoin, 0);
    combine_kernel<<<(NS_ * SD_) / 256, 256>>>(out, out_size);
}